// round 6
// baseline (speedup 1.0000x reference)
#include <cuda_runtime.h>
#include <math.h>

#define NH   12
#define NN   4096
#define ND   128
#define NIN  256

typedef unsigned long long u64t;

// ---- packed f32x2 helpers ----
__device__ __forceinline__ u64t pk2(float lo, float hi) {
    u64t r;
    asm("mov.b64 %0, {%1, %2};" : "=l"(r) : "f"(lo), "f"(hi));
    return r;
}
__device__ __forceinline__ void upk2(u64t v, float& lo, float& hi) {
    asm("mov.b64 {%0, %1}, %2;" : "=f"(lo), "=f"(hi) : "l"(v));
}
__device__ __forceinline__ void fma2(u64t& d, u64t a, u64t b) {
    asm("fma.rn.f32x2 %0, %1, %2, %0;" : "+l"(d) : "l"(a), "l"(b));
}
__device__ __forceinline__ void mul2(u64t& d, u64t a) {
    asm("mul.rn.f32x2 %0, %0, %1;" : "+l"(d) : "l"(a));
}

// ---- cp.async helpers ----
__device__ __forceinline__ void cpa16(void* dst, const void* src) {
    unsigned d = (unsigned)__cvta_generic_to_shared(dst);
    asm volatile("cp.async.cg.shared.global [%0], [%1], 16;" :: "r"(d), "l"(src));
}
__device__ __forceinline__ void cpa_commit() {
    asm volatile("cp.async.commit_group;" ::: "memory");
}
template<int N>
__device__ __forceinline__ void cpa_wait() {
    asm volatile("cp.async.wait_group %0;" :: "n"(N) : "memory");
}

// ---------------- scratch ----------------
__device__ float g_QTr[NH * 129 * NN];   // d-major, row0 = -alpha*t_q, rest alpha*s
__device__ float g_KTr[NH * 129 * NN];   // d-major, row0 = +t_k
__device__ float g_VS [NH * NN * ND];
__device__ float g_VT [NH * NN];
__device__ float g_OS [NH * NN * ND];
__device__ float g_OT [NH * NN];

// =====================================================================
// Kernel 1: projections. Q/K written d-major transposed (t in row 0,
// alpha + Minkowski sign folded into Q). V row-major as before.
// =====================================================================
__global__ __launch_bounds__(256) void proj_kernel(
    const float* __restrict__ x,
    const float* __restrict__ Wq, const float* __restrict__ bq,
    const float* __restrict__ Wk, const float* __restrict__ bk,
    const float* __restrict__ Wv, const float* __restrict__ bv,
    const float* __restrict__ scale_ptr)
{
    const int by  = blockIdx.y;
    const int h   = by % NH;
    const int sel = by / NH;

    const float* W = (sel == 0) ? Wq : (sel == 1) ? Wk : Wv;
    const float* B = (sel == 0) ? bq : (sel == 1) ? bk : bv;

    const int n0  = blockIdx.x * 64;
    const int tid = threadIdx.x;
    const int tx  = tid & 15;
    const int ty  = tid >> 4;

    __shared__ float Xt[32][68];
    __shared__ float Wt[32][132];

    u64t ac1[2][4], ac2[2][4];
#pragma unroll
    for (int i = 0; i < 2; i++)
#pragma unroll
        for (int j = 0; j < 4; j++) { ac1[i][j] = 0ull; ac2[i][j] = 0ull; }

    const float* Wh = W + (size_t)h * ND * NIN;

    for (int kb = 0; kb < NIN; kb += 32) {
        __syncthreads();
#pragma unroll
        for (int r = 0; r < 8; r++) {
            int idx = tid + r * 256;
            int k = idx & 31, m = idx >> 5;
            Xt[k][m] = x[(size_t)(n0 + m) * 257 + 1 + kb + k];
        }
#pragma unroll
        for (int r = 0; r < 16; r++) {
            int idx = tid + r * 256;
            int k = idx & 31, o = idx >> 5;
            Wt[k][o] = Wh[(size_t)o * NIN + kb + k];
        }
        __syncthreads();

#pragma unroll
        for (int k = 0; k < 32; k++) {
            float4 a  = *(const float4*)&Xt[k][ty * 4];
            float4 b0 = *(const float4*)&Wt[k][tx * 8];
            float4 b1 = *(const float4*)&Wt[k][tx * 8 + 4];
            u64t ap[2] = {pk2(a.x, a.y), pk2(a.z, a.w)};
            u64t bp[4] = {pk2(b0.x, b0.y), pk2(b0.z, b0.w),
                          pk2(b1.x, b1.y), pk2(b1.z, b1.w)};
            u64t bs[4] = {pk2(b0.y, b0.x), pk2(b0.w, b0.z),
                          pk2(b1.y, b1.x), pk2(b1.w, b1.z)};
#pragma unroll
            for (int i = 0; i < 2; i++)
#pragma unroll
                for (int j = 0; j < 4; j++) {
                    fma2(ac1[i][j], ap[i], bp[j]);
                    fma2(ac2[i][j], ap[i], bs[j]);
                }
        }
    }

    float acc[4][8];
#pragma unroll
    for (int i = 0; i < 2; i++)
#pragma unroll
        for (int j = 0; j < 4; j++) {
            upk2(ac1[i][j], acc[2 * i][2 * j],     acc[2 * i + 1][2 * j + 1]);
            upk2(ac2[i][j], acc[2 * i][2 * j + 1], acc[2 * i + 1][2 * j]);
        }

    float bb[8];
#pragma unroll
    for (int j = 0; j < 8; j++) bb[j] = B[h * ND + tx * 8 + j];

    float ss[4] = {0.f, 0.f, 0.f, 0.f};
#pragma unroll
    for (int i = 0; i < 4; i++)
#pragma unroll
        for (int j = 0; j < 8; j++) {
            acc[i][j] += bb[j];
            ss[i] = fmaf(acc[i][j], acc[i][j], ss[i]);
        }

#pragma unroll
    for (int off = 8; off; off >>= 1)
#pragma unroll
        for (int i = 0; i < 4; i++)
            ss[i] += __shfl_xor_sync(0xffffffffu, ss[i], off);

    const float alpha = 2.0f / scale_ptr[0];

    if (sel < 2) {
        // transposed d-major output with t in row 0
        const float smul = (sel == 0) ? alpha : 1.0f;
        const float tmul = (sel == 0) ? -alpha : 1.0f;
        float* T = ((sel == 0) ? g_QTr : g_KTr) + (size_t)h * 129 * NN;
#pragma unroll
        for (int j = 0; j < 8; j++) {
            int d = tx * 8 + j + 1;
            float4 w = {acc[0][j] * smul, acc[1][j] * smul,
                        acc[2][j] * smul, acc[3][j] * smul};
            *(float4*)&T[(size_t)d * NN + n0 + ty * 4] = w;
        }
        if (tx == 0) {
#pragma unroll
            for (int i = 0; i < 4; i++)
                T[n0 + ty * 4 + i] = tmul * sqrtf(ss[i] + 1.0f);
        }
    } else {
        // V: row-major
#pragma unroll
        for (int i = 0; i < 4; i++) {
            int n = n0 + ty * 4 + i;
            float* dst = g_VS + ((size_t)(h * NN + n)) * ND + tx * 8;
            float4 w0 = {acc[i][0], acc[i][1], acc[i][2], acc[i][3]};
            float4 w1 = {acc[i][4], acc[i][5], acc[i][6], acc[i][7]};
            *(float4*)(dst)     = w0;
            *(float4*)(dst + 4) = w1;
            if (tx == 0) g_VT[h * NN + n] = sqrtf(ss[i] + 1.0f);
        }
    }
}

// =====================================================================
// Kernel 2: flash attention + midpoint_norm.
// 512 threads, Q-tile 128 rows, cp.async double-buffered K, pipelined V.
// =====================================================================
#define QT_STR 132
#define KT_STR 68
#define PM_STR 132
#define VS_STR 128

#define OFF_QT  0
#define SZ_QT   (129 * QT_STR)            // 17028
#define OFF_KT0 (SZ_QT)
#define SZ_KT   (129 * KT_STR)            // 8772
#define OFF_KT1 (OFF_KT0 + SZ_KT)
#define OFF_VS  (OFF_KT1 + SZ_KT)         // 34572
#define OFF_PM  (OFF_VS + 64 * VS_STR)    // 42764
#define OFF_VT  (OFF_PM + 64 * PM_STR)    // 51212
#define ATTN_SMEM_FLOATS (OFF_VT + 64)    // 51276
#define ATTN_SMEM_BYTES  (ATTN_SMEM_FLOATS * 4)

__device__ __forceinline__ void load_k_tile(const float* __restrict__ src,
                                            float* __restrict__ dst, int tid)
{
    // 129 rows x 64 floats = 2064 float4
    for (int idx = tid; idx < 129 * 16; idx += 512) {
        int d = idx >> 4, c = idx & 15;
        cpa16(dst + d * KT_STR + c * 4, src + (size_t)d * NN + c * 4);
    }
}

__global__ __launch_bounds__(512, 1) void attn_kernel()
{
    extern __shared__ float sm[];
    float* Qt  = sm + OFF_QT;    // [129][132]
    float* Kt0 = sm + OFF_KT0;   // [129][68] x2
    float* Kt1 = sm + OFF_KT1;
    float* Vs  = sm + OFF_VS;    // [64][128]
    float* Pm  = sm + OFF_PM;    // [64][132]  (k-major)
    float* vt  = sm + OFF_VT;    // [64]

    const int h   = blockIdx.y;
    const int m0  = blockIdx.x * 128;
    const int tid = threadIdx.x;
    const int tx  = tid & 15;    // score cols tx*4.. / PV cols tx*8..
    const int ty  = tid >> 4;    // rows ty*4..ty*4+3

    const float* qsrc = g_QTr + (size_t)h * 129 * NN + m0;
    const float* kbase = g_KTr + (size_t)h * 129 * NN;

    // prologue: Qt + K(0)  (one commit group)
    for (int idx = tid; idx < 129 * 32; idx += 512) {
        int d = idx >> 5, c = idx & 31;
        cpa16(Qt + d * QT_STR + c * 4, qsrc + (size_t)d * NN + c * 4);
    }
    load_k_tile(kbase, Kt0, tid);
    cpa_commit();

    float m_i[4], l_i[4], acc_t[4];
    u64t ac1[2][4], ac2[2][4];
#pragma unroll
    for (int i = 0; i < 4; i++) { m_i[i] = -INFINITY; l_i[i] = 0.f; acc_t[i] = 0.f; }
#pragma unroll
    for (int i = 0; i < 2; i++)
#pragma unroll
        for (int j = 0; j < 4; j++) { ac1[i][j] = 0ull; ac2[i][j] = 0ull; }

    for (int c64 = 0; c64 < 64; c64++) {
        const int k0 = c64 * 64;
        float* Ktc = (c64 & 1) ? Kt1 : Kt0;
        float* Ktn = (c64 & 1) ? Kt0 : Kt1;

        __syncthreads();   // A: PV(c-1)/Pm reads done; Vs reusable

        // V(c) + vt(c)
        {
            const float* vsrc = g_VS + ((size_t)(h * NN + k0)) * ND;
            for (int idx = tid; idx < 2048; idx += 512) {
                int n = idx >> 5, c = idx & 31;
                cpa16(Vs + n * VS_STR + c * 4, vsrc + (size_t)n * ND + c * 4);
            }
            if (tid < 16) cpa16(vt + tid * 4, g_VT + h * NN + k0 + tid * 4);
        }
        cpa_commit();                       // group V(c)

        if (c64 < 63) {
            load_k_tile(kbase + k0 + 64, Ktn, tid);
            cpa_commit();                   // group K(c+1)
            cpa_wait<2>();                  // K(c) [and Qt] complete
        } else {
            cpa_wait<1>();
        }
        __syncthreads();   // B: Kt(c) visible to all threads

        // ---- scores: 4x4 diag-packed over 129 dims ----
        u64t sd1[4], sd2[4];
#pragma unroll
        for (int i = 0; i < 4; i++) { sd1[i] = 0ull; sd2[i] = 0ull; }

        const float* qp = Qt + ty * 4;
        const float* kp = Ktc + tx * 4;
#pragma unroll 3
        for (int d = 0; d < 129; d++) {
            float4 q  = *(const float4*)qp; qp += QT_STR;
            float4 kk = *(const float4*)kp; kp += KT_STR;
            u64t a0 = pk2(q.x, q.y),  a1 = pk2(q.z, q.w);
            u64t b0 = pk2(kk.x, kk.y), b1 = pk2(kk.z, kk.w);
            u64t b0s = pk2(kk.y, kk.x), b1s = pk2(kk.w, kk.z);
            fma2(sd1[0], a0, b0);  fma2(sd2[0], a0, b0s);
            fma2(sd1[1], a0, b1);  fma2(sd2[1], a0, b1s);
            fma2(sd1[2], a1, b0);  fma2(sd2[2], a1, b0s);
            fma2(sd1[3], a1, b1);  fma2(sd2[3], a1, b1s);
        }

        float s[4][4];
#pragma unroll
        for (int i2 = 0; i2 < 2; i2++)
#pragma unroll
            for (int j2 = 0; j2 < 2; j2++) {
                upk2(sd1[i2 * 2 + j2], s[2 * i2][2 * j2],     s[2 * i2 + 1][2 * j2 + 1]);
                upk2(sd2[i2 * 2 + j2], s[2 * i2][2 * j2 + 1], s[2 * i2 + 1][2 * j2]);
            }

        // ---- online softmax ----
        float tmax[4];
#pragma unroll
        for (int i = 0; i < 4; i++)
            tmax[i] = fmaxf(fmaxf(s[i][0], s[i][1]), fmaxf(s[i][2], s[i][3]));
#pragma unroll
        for (int off = 8; off; off >>= 1)
#pragma unroll
            for (int i = 0; i < 4; i++)
                tmax[i] = fmaxf(tmax[i], __shfl_xor_sync(0xffffffffu, tmax[i], off));

        float fac[4], tsum[4];
#pragma unroll
        for (int i = 0; i < 4; i++) {
            float newm = fmaxf(m_i[i], tmax[i]);
            fac[i] = __expf(m_i[i] - newm);
            m_i[i] = newm;
            tsum[i] = 0.f;
#pragma unroll
            for (int j = 0; j < 4; j++) {
                s[i][j] = __expf(s[i][j] - newm);
                tsum[i] += s[i][j];
            }
        }
#pragma unroll
        for (int off = 8; off; off >>= 1)
#pragma unroll
            for (int i = 0; i < 4; i++)
                tsum[i] += __shfl_xor_sync(0xffffffffu, tsum[i], off);

#pragma unroll
        for (int i = 0; i < 4; i++) {
            l_i[i] = l_i[i] * fac[i] + tsum[i];
            acc_t[i] *= fac[i];
        }
#pragma unroll
        for (int i2 = 0; i2 < 2; i2++) {
            u64t fp = pk2(fac[2 * i2], fac[2 * i2 + 1]);
#pragma unroll
            for (int j = 0; j < 4; j++) { mul2(ac1[i2][j], fp); mul2(ac2[i2][j], fp); }
        }

        // stage P tile (k-major)
#pragma unroll
        for (int j = 0; j < 4; j++) {
            float4 w = {s[0][j], s[1][j], s[2][j], s[3][j]};
            *(float4*)(Pm + (tx * 4 + j) * PM_STR + ty * 4) = w;
        }

        if (c64 < 63) cpa_wait<1>(); else cpa_wait<0>();   // V(c) complete
        __syncthreads();   // C: Pm + Vs visible

        // ---- PV: 4 rows x 8 cols diag-packed ----
#pragma unroll 4
        for (int k = 0; k < 64; k++) {
            float4 p  = *(const float4*)(Pm + k * PM_STR + ty * 4);
            const float* vrow = Vs + k * VS_STR + tx * 8;
            float4 v0 = *(const float4*)(vrow);
            float4 v1 = *(const float4*)(vrow + 4);
            u64t pp0 = pk2(p.x, p.y), pp1 = pk2(p.z, p.w);
            u64t vp0 = pk2(v0.x, v0.y), vp1 = pk2(v0.z, v0.w);
            u64t vp2 = pk2(v1.x, v1.y), vp3 = pk2(v1.z, v1.w);
            u64t vq0 = pk2(v0.y, v0.x), vq1 = pk2(v0.w, v0.z);
            u64t vq2 = pk2(v1.y, v1.x), vq3 = pk2(v1.w, v1.z);
            fma2(ac1[0][0], pp0, vp0);  fma2(ac2[0][0], pp0, vq0);
            fma2(ac1[0][1], pp0, vp1);  fma2(ac2[0][1], pp0, vq1);
            fma2(ac1[0][2], pp0, vp2);  fma2(ac2[0][2], pp0, vq2);
            fma2(ac1[0][3], pp0, vp3);  fma2(ac2[0][3], pp0, vq3);
            fma2(ac1[1][0], pp1, vp0);  fma2(ac2[1][0], pp1, vq0);
            fma2(ac1[1][1], pp1, vp1);  fma2(ac2[1][1], pp1, vq1);
            fma2(ac1[1][2], pp1, vp2);  fma2(ac2[1][2], pp1, vq2);
            fma2(ac1[1][3], pp1, vp3);  fma2(ac2[1][3], pp1, vq3);
        }

        // distributed t-accumulation: lane handles k = tx*4..tx*4+3
#pragma unroll
        for (int j = 0; j < 4; j++) {
            int k = tx * 4 + j;
            float vv = vt[k];
            float4 p = *(const float4*)(Pm + k * PM_STR + ty * 4);
            acc_t[0] = fmaf(p.x, vv, acc_t[0]);
            acc_t[1] = fmaf(p.y, vv, acc_t[1]);
            acc_t[2] = fmaf(p.z, vv, acc_t[2]);
            acc_t[3] = fmaf(p.w, vv, acc_t[3]);
        }
    }

    // ---- epilogue ----
    float o[4][8];
#pragma unroll
    for (int i2 = 0; i2 < 2; i2++)
#pragma unroll
        for (int j = 0; j < 4; j++) {
            upk2(ac1[i2][j], o[2 * i2][2 * j],     o[2 * i2 + 1][2 * j + 1]);
            upk2(ac2[i2][j], o[2 * i2][2 * j + 1], o[2 * i2 + 1][2 * j]);
        }

    float ssum[4];
#pragma unroll
    for (int i = 0; i < 4; i++) {
        float rl = 1.0f / l_i[i];
        ssum[i] = 0.f;
#pragma unroll
        for (int j = 0; j < 8; j++) {
            o[i][j] *= rl;
            ssum[i] = fmaf(o[i][j], o[i][j], ssum[i]);
        }
        acc_t[i] *= rl;   // per-lane partial
    }
#pragma unroll
    for (int off = 8; off; off >>= 1)
#pragma unroll
        for (int i = 0; i < 4; i++) {
            ssum[i]  += __shfl_xor_sync(0xffffffffu, ssum[i], off);
            acc_t[i] += __shfl_xor_sync(0xffffffffu, acc_t[i], off);
        }

#pragma unroll
    for (int i = 0; i < 4; i++) {
        float inner = ssum[i] - acc_t[i] * acc_t[i];
        float f = 1.0f / sqrtf(fmaxf(fabsf(inner), 1e-8f));
        int n = m0 + ty * 4 + i;
        float* dst = g_OS + ((size_t)(h * NN + n)) * ND + tx * 8;
        float4 w0 = {o[i][0] * f, o[i][1] * f, o[i][2] * f, o[i][3] * f};
        float4 w1 = {o[i][4] * f, o[i][5] * f, o[i][6] * f, o[i][7] * f};
        *(float4*)(dst)     = w0;
        *(float4*)(dst + 4) = w1;
        if (tx == 0) g_OT[h * NN + n] = acc_t[i] * f;
    }
}

// =====================================================================
// Kernel 3: head mean + final midpoint_norm -> out[n][129]
// =====================================================================
__global__ __launch_bounds__(256) void final_kernel(float* __restrict__ out)
{
    const int warp = threadIdx.x >> 5;
    const int lane = threadIdx.x & 31;
    const int n = blockIdx.x * 8 + warp;

    float s0 = 0.f, s1 = 0.f, s2 = 0.f, s3 = 0.f, t = 0.f;
#pragma unroll
    for (int h = 0; h < NH; h++) {
        float4 v = *(const float4*)&g_OS[((size_t)(h * NN + n)) * ND + lane * 4];
        s0 += v.x; s1 += v.y; s2 += v.z; s3 += v.w;
        t += g_OT[h * NN + n];
    }
    const float inv = 1.0f / (float)NH;
    s0 *= inv; s1 *= inv; s2 *= inv; s3 *= inv; t *= inv;

    float q = s0 * s0 + s1 * s1 + s2 * s2 + s3 * s3;
#pragma unroll
    for (int off = 16; off; off >>= 1) q += __shfl_xor_sync(0xffffffffu, q, off);

    float inner = q - t * t;
    float f = 1.0f / sqrtf(fmaxf(fabsf(inner), 1e-8f));

    float* o = out + (size_t)n * 129;
    if (lane == 0) o[0] = t * f;
    o[1 + lane * 4 + 0] = s0 * f;
    o[1 + lane * 4 + 1] = s1 * f;
    o[1 + lane * 4 + 2] = s2 * f;
    o[1 + lane * 4 + 3] = s3 * f;
}

// =====================================================================
extern "C" void kernel_launch(void* const* d_in, const int* in_sizes, int n_in,
                              void* d_out, int out_size)
{
    const float* x     = (const float*)d_in[0];
    const float* Wq    = (const float*)d_in[1];
    const float* bq    = (const float*)d_in[2];
    const float* Wk    = (const float*)d_in[3];
    const float* bk    = (const float*)d_in[4];
    const float* Wv    = (const float*)d_in[5];
    const float* bv    = (const float*)d_in[6];
    const float* scale = (const float*)d_in[7];
    float* out = (float*)d_out;

    cudaFuncSetAttribute(attn_kernel,
                         cudaFuncAttributeMaxDynamicSharedMemorySize,
                         ATTN_SMEM_BYTES);

    proj_kernel<<<dim3(NN / 64, NH * 3), 256>>>(x, Wq, bq, Wk, bk, Wv, bv, scale);
    attn_kernel<<<dim3(NN / 128, NH), 512, ATTN_SMEM_BYTES>>>();
    final_kernel<<<NN / 8, 256>>>(out);
}

// round 7
// speedup vs baseline: 2.0687x; 2.0687x over previous
#include <cuda_runtime.h>
#include <math.h>

#define NH   12
#define NN   4096
#define ND   128
#define NIN  256

typedef unsigned long long u64t;

// ---- packed f32x2 helpers (proj GEMM) ----
__device__ __forceinline__ u64t pk2(float lo, float hi) {
    u64t r; asm("mov.b64 %0, {%1, %2};" : "=l"(r) : "f"(lo), "f"(hi)); return r;
}
__device__ __forceinline__ void upk2(u64t v, float& lo, float& hi) {
    asm("mov.b64 {%0, %1}, %2;" : "=f"(lo), "=f"(hi) : "l"(v));
}
__device__ __forceinline__ void fma2(u64t& d, u64t a, u64t b) {
    asm("fma.rn.f32x2 %0, %1, %2, %0;" : "+l"(d) : "l"(a), "l"(b));
}

// ---- tf32 ----
__device__ __forceinline__ float tf32r(float x) {
    unsigned u; asm("cvt.rna.tf32.f32 %0, %1;" : "=r"(u) : "f"(x));
    return __uint_as_float(u);
}
__device__ __forceinline__ void mma8(float* c,
    unsigned a0, unsigned a1, unsigned a2, unsigned a3,
    unsigned b0, unsigned b1)
{
    asm volatile("mma.sync.aligned.m16n8k8.row.col.f32.tf32.tf32.f32 "
        "{%0,%1,%2,%3}, {%4,%5,%6,%7}, {%8,%9}, {%0,%1,%2,%3};"
        : "+f"(c[0]), "+f"(c[1]), "+f"(c[2]), "+f"(c[3])
        : "r"(a0), "r"(a1), "r"(a2), "r"(a3), "r"(b0), "r"(b1));
}

// ---- cp.async ----
__device__ __forceinline__ void cpa16(void* dst, const void* src) {
    unsigned d = (unsigned)__cvta_generic_to_shared(dst);
    asm volatile("cp.async.cg.shared.global [%0], [%1], 16;" :: "r"(d), "l"(src));
}
__device__ __forceinline__ void cpa4(void* dst, const void* src) {
    unsigned d = (unsigned)__cvta_generic_to_shared(dst);
    asm volatile("cp.async.ca.shared.global [%0], [%1], 4;" :: "r"(d), "l"(src));
}
__device__ __forceinline__ void cpa_commit() {
    asm volatile("cp.async.commit_group;" ::: "memory");
}
template<int N>
__device__ __forceinline__ void cpa_wait() {
    asm volatile("cp.async.wait_group %0;" :: "n"(N) : "memory");
}

// ---------------- scratch ----------------
__device__ float g_Qd[NH * 128 * NN];   // d-major, tf32(alpha*s_q)
__device__ float g_Kd[NH * 128 * NN];   // d-major, tf32(s_k)
__device__ float g_VS[NH * NN * ND];    // row-major, tf32(v_s)
__device__ float g_tq[NH * NN];         // alpha * t_q  (fp32)
__device__ float g_tk[NH * NN];         // t_k          (fp32)
__device__ float g_VT[NH * NN];         // tf32(v_t)
__device__ float g_OS[NH * NN * ND];    // ave (space), unnormalized midpoint
__device__ float g_OT[NH * NN];         // ave (time)

// =====================================================================
// Kernel 1: projections (FFMA2 GEMM core unchanged; new epilogue)
// =====================================================================
__global__ __launch_bounds__(256) void proj_kernel(
    const float* __restrict__ x,
    const float* __restrict__ Wq, const float* __restrict__ bq,
    const float* __restrict__ Wk, const float* __restrict__ bk,
    const float* __restrict__ Wv, const float* __restrict__ bv,
    const float* __restrict__ scale_ptr)
{
    const int by  = blockIdx.y;
    const int h   = by % NH;
    const int sel = by / NH;

    const float* W = (sel == 0) ? Wq : (sel == 1) ? Wk : Wv;
    const float* B = (sel == 0) ? bq : (sel == 1) ? bk : bv;

    const int n0  = blockIdx.x * 64;
    const int tid = threadIdx.x;
    const int tx  = tid & 15;
    const int ty  = tid >> 4;

    __shared__ float Xt[32][68];
    __shared__ float Wt[32][132];

    u64t ac1[2][4], ac2[2][4];
#pragma unroll
    for (int i = 0; i < 2; i++)
#pragma unroll
        for (int j = 0; j < 4; j++) { ac1[i][j] = 0ull; ac2[i][j] = 0ull; }

    const float* Wh = W + (size_t)h * ND * NIN;

    for (int kb = 0; kb < NIN; kb += 32) {
        __syncthreads();
#pragma unroll
        for (int r = 0; r < 8; r++) {
            int idx = tid + r * 256;
            int k = idx & 31, m = idx >> 5;
            Xt[k][m] = x[(size_t)(n0 + m) * 257 + 1 + kb + k];
        }
#pragma unroll
        for (int r = 0; r < 16; r++) {
            int idx = tid + r * 256;
            int k = idx & 31, o = idx >> 5;
            Wt[k][o] = Wh[(size_t)o * NIN + kb + k];
        }
        __syncthreads();

#pragma unroll
        for (int k = 0; k < 32; k++) {
            float4 a  = *(const float4*)&Xt[k][ty * 4];
            float4 b0 = *(const float4*)&Wt[k][tx * 8];
            float4 b1 = *(const float4*)&Wt[k][tx * 8 + 4];
            u64t ap[2] = {pk2(a.x, a.y), pk2(a.z, a.w)};
            u64t bp[4] = {pk2(b0.x, b0.y), pk2(b0.z, b0.w),
                          pk2(b1.x, b1.y), pk2(b1.z, b1.w)};
            u64t bs[4] = {pk2(b0.y, b0.x), pk2(b0.w, b0.z),
                          pk2(b1.y, b1.x), pk2(b1.w, b1.z)};
#pragma unroll
            for (int i = 0; i < 2; i++)
#pragma unroll
                for (int j = 0; j < 4; j++) {
                    fma2(ac1[i][j], ap[i], bp[j]);
                    fma2(ac2[i][j], ap[i], bs[j]);
                }
        }
    }

    float acc[4][8];
#pragma unroll
    for (int i = 0; i < 2; i++)
#pragma unroll
        for (int j = 0; j < 4; j++) {
            upk2(ac1[i][j], acc[2 * i][2 * j],     acc[2 * i + 1][2 * j + 1]);
            upk2(ac2[i][j], acc[2 * i][2 * j + 1], acc[2 * i + 1][2 * j]);
        }

    float bb[8];
#pragma unroll
    for (int j = 0; j < 8; j++) bb[j] = B[h * ND + tx * 8 + j];

    float ss[4] = {0.f, 0.f, 0.f, 0.f};
#pragma unroll
    for (int i = 0; i < 4; i++)
#pragma unroll
        for (int j = 0; j < 8; j++) {
            acc[i][j] += bb[j];
            ss[i] = fmaf(acc[i][j], acc[i][j], ss[i]);
        }
#pragma unroll
    for (int off = 8; off; off >>= 1)
#pragma unroll
        for (int i = 0; i < 4; i++)
            ss[i] += __shfl_xor_sync(0xffffffffu, ss[i], off);

    const float alpha = 2.0f / scale_ptr[0];

    if (sel == 0) {
        float* T = g_Qd + (size_t)h * 128 * NN;
#pragma unroll
        for (int j = 0; j < 8; j++) {
            int d = tx * 8 + j;
            float4 w = {tf32r(alpha * acc[0][j]), tf32r(alpha * acc[1][j]),
                        tf32r(alpha * acc[2][j]), tf32r(alpha * acc[3][j])};
            *(float4*)&T[(size_t)d * NN + n0 + ty * 4] = w;
        }
        if (tx == 0)
#pragma unroll
            for (int i = 0; i < 4; i++)
                g_tq[h * NN + n0 + ty * 4 + i] = alpha * sqrtf(ss[i] + 1.0f);
    } else if (sel == 1) {
        float* T = g_Kd + (size_t)h * 128 * NN;
#pragma unroll
        for (int j = 0; j < 8; j++) {
            int d = tx * 8 + j;
            float4 w = {tf32r(acc[0][j]), tf32r(acc[1][j]),
                        tf32r(acc[2][j]), tf32r(acc[3][j])};
            *(float4*)&T[(size_t)d * NN + n0 + ty * 4] = w;
        }
        if (tx == 0)
#pragma unroll
            for (int i = 0; i < 4; i++)
                g_tk[h * NN + n0 + ty * 4 + i] = sqrtf(ss[i] + 1.0f);
    } else {
#pragma unroll
        for (int i = 0; i < 4; i++) {
            int n = n0 + ty * 4 + i;
            float* dst = g_VS + ((size_t)(h * NN + n)) * ND + tx * 8;
            float4 w0 = {tf32r(acc[i][0]), tf32r(acc[i][1]),
                         tf32r(acc[i][2]), tf32r(acc[i][3])};
            float4 w1 = {tf32r(acc[i][4]), tf32r(acc[i][5]),
                         tf32r(acc[i][6]), tf32r(acc[i][7])};
            *(float4*)(dst)     = w0;
            *(float4*)(dst + 4) = w1;
            if (tx == 0) g_VT[h * NN + n] = tf32r(sqrtf(ss[i] + 1.0f));
        }
    }
}

// =====================================================================
// Kernel 2: flash attention via tf32 mma.sync (m16n8k8), 512 threads.
// No online softmax (logits <= 0 by Lorentz Cauchy-Schwarz).
// fp32 rank-1 fixup for the -alpha*t_q*t_k term.
// =====================================================================
#define QSTR 128
#define KSTR 72
#define VSTR 136
#define PSTR 68

#define OFF_QD   0
#define OFF_K0   16384
#define OFF_K1   (OFF_K0 + 9216)     // 25600
#define OFF_VS   (OFF_K1 + 9216)     // 34816
#define OFF_P    (OFF_VS + 8704)     // 43520
#define OFF_TK0  (OFF_P + 8704)      // 52224
#define OFF_TK1  (OFF_TK0 + 64)      // 52288
#define OFF_LRED (OFF_TK1 + 64)      // 52352  [128][4]
#define OFF_LTOT (OFF_LRED + 512)    // 52864
#define ATTN_SMEM_FLOATS (OFF_LTOT + 128)   // 52992
#define ATTN_SMEM_BYTES  (ATTN_SMEM_FLOATS * 4)

__global__ __launch_bounds__(512, 1) void attn_kernel()
{
    extern __shared__ float sm[];
    float* Qd   = sm + OFF_QD;    // [128 d][128 m]
    float* Vs   = sm + OFF_VS;    // [64 k][136]  (col 128 = v_t, 129..135 = 0)
    float* Pm   = sm + OFF_P;     // [128 m][68]
    float* Lred = sm + OFF_LRED;
    float* Ltot = sm + OFF_LTOT;

    const int h    = blockIdx.y;
    const int m0   = blockIdx.x * 128;
    const int tid  = threadIdx.x;
    const int lane = tid & 31;
    const int wid  = tid >> 5;
    const int qp   = lane & 3;    // quad position
    const int qr   = lane >> 2;   // quad row
    const int mg   = wid & 3;     // m-group: rows mg*32..+32
    const int ng   = wid >> 2;    // n-group

    const float* qsrc = g_Qd + (size_t)h * 128 * NN + m0;
    const float* ksrc = g_Kd + (size_t)h * 128 * NN;

    // tq rows for the fp32 fixup (constant across chunks)
    float tqr[4];
#pragma unroll
    for (int i = 0; i < 4; i++)
        tqr[i] = g_tq[h * NN + m0 + mg * 32 + qr + 8 * i];

    // zero V pad cols (128..135; col 128 overwritten per chunk)
    for (int i = tid; i < 64 * 8; i += 512)
        Vs[(i >> 3) * VSTR + 128 + (i & 7)] = 0.0f;

    // prologue: Q tile + K(0) + tk(0), one commit group
    for (int idx = tid; idx < 128 * 32; idx += 512) {
        int d = idx >> 5, c = idx & 31;
        cpa16(Qd + d * QSTR + c * 4, qsrc + (size_t)d * NN + c * 4);
    }
    for (int idx = tid; idx < 128 * 16; idx += 512) {
        int d = idx >> 4, c = idx & 15;
        cpa16(sm + OFF_K0 + d * KSTR + c * 4, ksrc + (size_t)d * NN + c * 4);
    }
    if (tid < 16) cpa16(sm + OFF_TK0 + tid * 4, g_tk + h * NN + tid * 4);
    cpa_commit();

    float oc[2][4][4], ot[2][4], lacc[4];
#pragma unroll
    for (int mt = 0; mt < 2; mt++) {
#pragma unroll
        for (int j = 0; j < 4; j++)
#pragma unroll
            for (int r = 0; r < 4; r++) oc[mt][j][r] = 0.0f;
#pragma unroll
        for (int r = 0; r < 4; r++) ot[mt][r] = 0.0f;
    }
#pragma unroll
    for (int i = 0; i < 4; i++) lacc[i] = 0.0f;

    for (int c64 = 0; c64 < 64; c64++) {
        const int k0 = c64 * 64;
        float* Kc  = sm + ((c64 & 1) ? OFF_K1 : OFF_K0);
        float* Kn  = sm + ((c64 & 1) ? OFF_K0 : OFF_K1);
        float* tkc = sm + ((c64 & 1) ? OFF_TK1 : OFF_TK0);
        float* tkn = sm + ((c64 & 1) ? OFF_TK0 : OFF_TK1);

        __syncthreads();   // A: PV(c-1) finished; Vs / Kn / P writable

        // V(c) (+ v_t into col 128)
        {
            const float* vsrc = g_VS + ((size_t)(h * NN + k0)) * ND;
            for (int idx = tid; idx < 2048; idx += 512) {
                int n = idx >> 5, c = idx & 31;
                cpa16(Vs + n * VSTR + c * 4, vsrc + (size_t)n * ND + c * 4);
            }
            if (tid < 64) cpa4(Vs + tid * VSTR + 128, g_VT + h * NN + k0 + tid);
        }
        cpa_commit();

        if (c64 < 63) {
            const float* kn = ksrc + k0 + 64;
            for (int idx = tid; idx < 2048; idx += 512) {
                int d = idx >> 4, c = idx & 15;
                cpa16(Kn + d * KSTR + c * 4, kn + (size_t)d * NN + c * 4);
            }
            if (tid < 16) cpa16(tkn + tid * 4, g_tk + h * NN + k0 + 64 + tid * 4);
            cpa_commit();
            cpa_wait<2>();   // K(c), tk(c) [and prologue] done
        } else {
            cpa_wait<1>();
        }
        __syncthreads();   // B: K(c)/tk(c) visible

        // ---- scores: warp = rows mg*32..+32 (2 mtiles), cols ng*16..+16 ----
        float sc[2][2][4];
#pragma unroll
        for (int mt = 0; mt < 2; mt++)
#pragma unroll
            for (int nt = 0; nt < 2; nt++)
#pragma unroll
                for (int r = 0; r < 4; r++) sc[mt][nt][r] = 0.0f;

#pragma unroll
        for (int ks = 0; ks < 16; ks++) {
            const float* qa = Qd + (ks * 8 + qp) * QSTR + mg * 32 + qr;
            unsigned a[2][4];
#pragma unroll
            for (int mt = 0; mt < 2; mt++) {
                const float* q2 = qa + mt * 16;
                a[mt][0] = __float_as_uint(q2[0]);
                a[mt][1] = __float_as_uint(q2[8]);
                a[mt][2] = __float_as_uint(q2[4 * QSTR]);
                a[mt][3] = __float_as_uint(q2[4 * QSTR + 8]);
            }
            const float* kb = Kc + (ks * 8 + qp) * KSTR + ng * 16 + qr;
#pragma unroll
            for (int nt = 0; nt < 2; nt++) {
                unsigned b0 = __float_as_uint(kb[nt * 8]);
                unsigned b1 = __float_as_uint(kb[nt * 8 + 4 * KSTR]);
                mma8(sc[0][nt], a[0][0], a[0][1], a[0][2], a[0][3], b0, b1);
                mma8(sc[1][nt], a[1][0], a[1][1], a[1][2], a[1][3], b0, b1);
            }
        }

        // ---- fixup + exp + stage P + l partials ----
#pragma unroll
        for (int mt = 0; mt < 2; mt++) {
            int prow = mg * 32 + mt * 16 + qr;
#pragma unroll
            for (int nt = 0; nt < 2; nt++) {
                int col = ng * 16 + nt * 8 + qp * 2;
                float t0 = tkc[col], t1 = tkc[col + 1];
                float p0 = tf32r(__expf(sc[mt][nt][0] - tqr[mt * 2]     * t0));
                float p1 = tf32r(__expf(sc[mt][nt][1] - tqr[mt * 2]     * t1));
                float p2 = tf32r(__expf(sc[mt][nt][2] - tqr[mt * 2 + 1] * t0));
                float p3 = tf32r(__expf(sc[mt][nt][3] - tqr[mt * 2 + 1] * t1));
                lacc[mt * 2]     += p0 + p1;
                lacc[mt * 2 + 1] += p2 + p3;
                *(float2*)&Pm[prow * PSTR + col]       = make_float2(p0, p1);
                *(float2*)&Pm[(prow + 8) * PSTR + col] = make_float2(p2, p3);
            }
        }

        if (c64 < 63) cpa_wait<1>(); else cpa_wait<0>();   // V(c) done
        __syncthreads();   // C: P + V visible

        // ---- PV: warp = rows mg*32..+32, d-ntiles {ng,ng+4,ng+8,ng+12} ----
#pragma unroll
        for (int ks = 0; ks < 8; ks++) {
            unsigned a[2][4];
#pragma unroll
            for (int mt = 0; mt < 2; mt++) {
                const float* pa = Pm + (mg * 32 + mt * 16 + qr) * PSTR + ks * 8 + qp;
                a[mt][0] = __float_as_uint(pa[0]);
                a[mt][1] = __float_as_uint(pa[8 * PSTR]);
                a[mt][2] = __float_as_uint(pa[4]);
                a[mt][3] = __float_as_uint(pa[8 * PSTR + 4]);
            }
            const float* vb = Vs + (ks * 8 + qp) * VSTR + qr;
#pragma unroll
            for (int j = 0; j < 4; j++) {
                int nb = (ng + 4 * j) * 8;
                unsigned b0 = __float_as_uint(vb[nb]);
                unsigned b1 = __float_as_uint(vb[nb + 4 * VSTR]);
                mma8(oc[0][j], a[0][0], a[0][1], a[0][2], a[0][3], b0, b1);
                mma8(oc[1][j], a[1][0], a[1][1], a[1][2], a[1][3], b0, b1);
            }
            if (ng == 0) {
                unsigned b0 = __float_as_uint(vb[128]);
                unsigned b1 = __float_as_uint(vb[128 + 4 * VSTR]);
                mma8(ot[0], a[0][0], a[0][1], a[0][2], a[0][3], b0, b1);
                mma8(ot[1], a[1][0], a[1][1], a[1][2], a[1][3], b0, b1);
            }
        }
    }

    // ---- epilogue: l reduction, ave = acc/l, store ----
#pragma unroll
    for (int i = 0; i < 4; i++) {
        lacc[i] += __shfl_xor_sync(0xffffffffu, lacc[i], 1);
        lacc[i] += __shfl_xor_sync(0xffffffffu, lacc[i], 2);
    }
    if (qp == 0) {
#pragma unroll
        for (int i = 0; i < 4; i++)
            Lred[(mg * 32 + qr + 8 * i) * 4 + ng] = lacc[i];
    }
    __syncthreads();
    if (tid < 128) {
        const float* lr = Lred + tid * 4;
        Ltot[tid] = lr[0] + lr[1] + lr[2] + lr[3];
    }
    __syncthreads();

    float rl[4];
#pragma unroll
    for (int i = 0; i < 4; i++) rl[i] = 1.0f / Ltot[mg * 32 + qr + 8 * i];

#pragma unroll
    for (int mt = 0; mt < 2; mt++) {
#pragma unroll
        for (int rr = 0; rr < 2; rr++) {
            int row = m0 + mg * 32 + mt * 16 + qr + rr * 8;
            float rlv = rl[mt * 2 + rr];
            float* orow = g_OS + ((size_t)(h * NN + row)) * ND;
#pragma unroll
            for (int j = 0; j < 4; j++) {
                int d0 = (ng + 4 * j) * 8 + qp * 2;
                *(float2*)&orow[d0] =
                    make_float2(oc[mt][j][rr * 2] * rlv, oc[mt][j][rr * 2 + 1] * rlv);
            }
            if (ng == 0 && qp == 0)
                g_OT[h * NN + row] = ot[mt][rr * 2] * rlv;
        }
    }
}

// =====================================================================
// Kernel 3: per-head midpoint_norm + head mean + final norm
// =====================================================================
__global__ __launch_bounds__(256) void final_kernel(float* __restrict__ out)
{
    const int warp = threadIdx.x >> 5;
    const int lane = threadIdx.x & 31;
    const int n = blockIdx.x * 8 + warp;

    float as0 = 0.f, as1 = 0.f, as2 = 0.f, as3 = 0.f, at = 0.f;
#pragma unroll
    for (int h = 0; h < NH; h++) {
        float4 v = *(const float4*)&g_OS[((size_t)(h * NN + n)) * ND + lane * 4];
        float t = g_OT[h * NN + n];
        float ssn = v.x * v.x + v.y * v.y + v.z * v.z + v.w * v.w;
#pragma unroll
        for (int off = 16; off; off >>= 1)
            ssn += __shfl_xor_sync(0xffffffffu, ssn, off);
        float inner = ssn - t * t;
        float f = 1.0f / sqrtf(fmaxf(fabsf(inner), 1e-8f));
        as0 += v.x * f; as1 += v.y * f; as2 += v.z * f; as3 += v.w * f;
        at  += t * f;
    }
    const float inv = 1.0f / (float)NH;
    as0 *= inv; as1 *= inv; as2 *= inv; as3 *= inv; at *= inv;

    float q = as0 * as0 + as1 * as1 + as2 * as2 + as3 * as3;
#pragma unroll
    for (int off = 16; off; off >>= 1)
        q += __shfl_xor_sync(0xffffffffu, q, off);

    float inner = q - at * at;
    float f = 1.0f / sqrtf(fmaxf(fabsf(inner), 1e-8f));

    float* o = out + (size_t)n * 129;
    if (lane == 0) o[0] = at * f;
    o[1 + lane * 4 + 0] = as0 * f;
    o[1 + lane * 4 + 1] = as1 * f;
    o[1 + lane * 4 + 2] = as2 * f;
    o[1 + lane * 4 + 3] = as3 * f;
}

// =====================================================================
extern "C" void kernel_launch(void* const* d_in, const int* in_sizes, int n_in,
                              void* d_out, int out_size)
{
    const float* x     = (const float*)d_in[0];
    const float* Wq    = (const float*)d_in[1];
    const float* bq    = (const float*)d_in[2];
    const float* Wk    = (const float*)d_in[3];
    const float* bk    = (const float*)d_in[4];
    const float* Wv    = (const float*)d_in[5];
    const float* bv    = (const float*)d_in[6];
    const float* scale = (const float*)d_in[7];
    float* out = (float*)d_out;

    cudaFuncSetAttribute(attn_kernel,
                         cudaFuncAttributeMaxDynamicSharedMemorySize,
                         ATTN_SMEM_BYTES);

    proj_kernel<<<dim3(NN / 64, NH * 3), 256>>>(x, Wq, bq, Wk, bk, Wv, bv, scale);
    attn_kernel<<<dim3(NN / 128, NH), 512, ATTN_SMEM_BYTES>>>();
    final_kernel<<<NN / 8, 256>>>(out);
}

// round 8
// speedup vs baseline: 4.0500x; 1.9577x over previous
#include <cuda_runtime.h>
#include <math.h>

#define NH   12
#define NN   4096
#define ND   128
#define NIN  256

// ---- tf32 ----
__device__ __forceinline__ float tf32r(float x) {
    unsigned u; asm("cvt.rna.tf32.f32 %0, %1;" : "=r"(u) : "f"(x));
    return __uint_as_float(u);
}
__device__ __forceinline__ void mma8(float* c,
    unsigned a0, unsigned a1, unsigned a2, unsigned a3,
    unsigned b0, unsigned b1)
{
    asm volatile("mma.sync.aligned.m16n8k8.row.col.f32.tf32.tf32.f32 "
        "{%0,%1,%2,%3}, {%4,%5,%6,%7}, {%8,%9}, {%0,%1,%2,%3};"
        : "+f"(c[0]), "+f"(c[1]), "+f"(c[2]), "+f"(c[3])
        : "r"(a0), "r"(a1), "r"(a2), "r"(a3), "r"(b0), "r"(b1));
}

// ---- cp.async ----
__device__ __forceinline__ void cpa16(void* dst, const void* src) {
    unsigned d = (unsigned)__cvta_generic_to_shared(dst);
    asm volatile("cp.async.cg.shared.global [%0], [%1], 16;" :: "r"(d), "l"(src));
}
__device__ __forceinline__ void cpa4(void* dst, const void* src) {
    unsigned d = (unsigned)__cvta_generic_to_shared(dst);
    asm volatile("cp.async.ca.shared.global [%0], [%1], 4;" :: "r"(d), "l"(src));
}
__device__ __forceinline__ void cpa_commit() {
    asm volatile("cp.async.commit_group;" ::: "memory");
}
template<int N>
__device__ __forceinline__ void cpa_wait() {
    asm volatile("cp.async.wait_group %0;" :: "n"(N) : "memory");
}

// ---------------- scratch ----------------
__device__ float g_Qd[NH * 128 * NN];   // d-major, tf32(alpha*s_q)
__device__ float g_Kd[NH * 128 * NN];   // d-major, tf32(s_k)
__device__ float g_VS[NH * NN * ND];    // row-major, tf32(v_s)
__device__ float g_tq[NH * NN];         // alpha * t_q  (fp32)
__device__ float g_tk[NH * NN];         // t_k          (fp32)
__device__ float g_VT[NH * NN];         // tf32(v_t)
__device__ float g_OS[NH * NN * ND];    // ave (space), unnormalized midpoint
__device__ float g_OT[NH * NN];         // ave (time)

// =====================================================================
// Kernel 1: projections via tf32 mma.sync. Block = 128 rows x 128 cols,
// K=256 in 8 chunks of 32, double-buffered cp.async.
// 8 warps: mg = wid&3 (rows mg*32), ngg = wid>>2 (cols ngg*64).
// =====================================================================
#define PSTRX 36
#define PROJ_TILE (128 * PSTRX)              // 4608 floats per tile
#define PROJ_SMEM_FLOATS (4 * PROJ_TILE)     // X0 W0 X1 W1
#define PROJ_SMEM_BYTES  (PROJ_SMEM_FLOATS * 4)

__global__ __launch_bounds__(256, 1) void proj_kernel(
    const float* __restrict__ x,
    const float* __restrict__ Wq, const float* __restrict__ bq,
    const float* __restrict__ Wk, const float* __restrict__ bk,
    const float* __restrict__ Wv, const float* __restrict__ bv,
    const float* __restrict__ scale_ptr)
{
    extern __shared__ float psm[];
    __shared__ float Sred[128][2];

    const int by  = blockIdx.y;
    const int h   = by % NH;
    const int sel = by / NH;

    const float* W = (sel == 0) ? Wq : (sel == 1) ? Wk : Wv;
    const float* B = (sel == 0) ? bq : (sel == 1) ? bk : bv;
    const float* Wh = W + (size_t)h * ND * NIN;

    const int n0   = blockIdx.x * 128;
    const int tid  = threadIdx.x;
    const int lane = tid & 31;
    const int wid  = tid >> 5;
    const int qp   = lane & 3;
    const int qr   = lane >> 2;
    const int mg   = wid & 3;
    const int ngg  = wid >> 2;

    // chunk loader: X[128 m][32 k] (cpa4, x rows are odd-length) + W[128 o][32 k]
    auto load_chunk = [&](int kb, int buf) {
        float* Xs = psm + buf * (2 * PROJ_TILE);
        float* Ws = Xs + PROJ_TILE;
        for (int idx = tid; idx < 128 * 32; idx += 256) {
            int m = idx >> 5, k = idx & 31;
            cpa4(Xs + m * PSTRX + k, x + (size_t)(n0 + m) * 257 + 1 + kb + k);
        }
        for (int idx = tid; idx < 128 * 8; idx += 256) {
            int o = idx >> 3, kq = idx & 7;
            cpa16(Ws + o * PSTRX + kq * 4, Wh + (size_t)o * NIN + kb + kq * 4);
        }
    };

    float cacc[2][8][4];
#pragma unroll
    for (int mt = 0; mt < 2; mt++)
#pragma unroll
        for (int nt = 0; nt < 8; nt++)
#pragma unroll
            for (int r = 0; r < 4; r++) cacc[mt][nt][r] = 0.0f;

    load_chunk(0, 0);
    cpa_commit();

    for (int c = 0; c < 8; c++) {
        if (c < 7) {
            load_chunk((c + 1) * 32, (c + 1) & 1);
            cpa_commit();
            cpa_wait<1>();
        } else {
            cpa_wait<0>();
        }
        __syncthreads();

        const float* Xc = psm + (c & 1) * (2 * PROJ_TILE);
        const float* Wc = Xc + PROJ_TILE;

#pragma unroll
        for (int ks = 0; ks < 4; ks++) {
            unsigned a[2][4];
            const float* qa = Xc + (mg * 32 + qr) * PSTRX + ks * 8 + qp;
#pragma unroll
            for (int mt = 0; mt < 2; mt++) {
                const float* q2 = qa + mt * 16 * PSTRX;
                a[mt][0] = __float_as_uint(q2[0]);
                a[mt][1] = __float_as_uint(q2[8 * PSTRX]);
                a[mt][2] = __float_as_uint(q2[4]);
                a[mt][3] = __float_as_uint(q2[8 * PSTRX + 4]);
            }
#pragma unroll
            for (int nt = 0; nt < 8; nt++) {
                const float* kb = Wc + (ngg * 64 + nt * 8 + qr) * PSTRX + ks * 8 + qp;
                unsigned b0 = __float_as_uint(kb[0]);
                unsigned b1 = __float_as_uint(kb[4]);
                mma8(cacc[0][nt], a[0][0], a[0][1], a[0][2], a[0][3], b0, b1);
                mma8(cacc[1][nt], a[1][0], a[1][1], a[1][2], a[1][3], b0, b1);
            }
        }
        __syncthreads();
    }

    // ---- epilogue: bias, row |s|^2, t, stores ----
    float bb[8][2];
#pragma unroll
    for (int nt = 0; nt < 8; nt++) {
        int col = ngg * 64 + nt * 8 + qp * 2;
        bb[nt][0] = B[h * ND + col];
        bb[nt][1] = B[h * ND + col + 1];
    }

    float ssq[2][2] = {{0.f, 0.f}, {0.f, 0.f}};
#pragma unroll
    for (int mt = 0; mt < 2; mt++)
#pragma unroll
        for (int nt = 0; nt < 8; nt++) {
#pragma unroll
            for (int rr = 0; rr < 2; rr++) {
                cacc[mt][nt][rr * 2]     += bb[nt][0];
                cacc[mt][nt][rr * 2 + 1] += bb[nt][1];
                ssq[mt][rr] = fmaf(cacc[mt][nt][rr * 2], cacc[mt][nt][rr * 2], ssq[mt][rr]);
                ssq[mt][rr] = fmaf(cacc[mt][nt][rr * 2 + 1], cacc[mt][nt][rr * 2 + 1], ssq[mt][rr]);
            }
        }
#pragma unroll
    for (int mt = 0; mt < 2; mt++)
#pragma unroll
        for (int rr = 0; rr < 2; rr++) {
            ssq[mt][rr] += __shfl_xor_sync(0xffffffffu, ssq[mt][rr], 1);
            ssq[mt][rr] += __shfl_xor_sync(0xffffffffu, ssq[mt][rr], 2);
        }
    if (qp == 0) {
#pragma unroll
        for (int mt = 0; mt < 2; mt++)
#pragma unroll
            for (int rr = 0; rr < 2; rr++)
                Sred[mg * 32 + mt * 16 + rr * 8 + qr][ngg] = ssq[mt][rr];
    }
    __syncthreads();

    const float alpha = 2.0f / scale_ptr[0];

    if (sel < 2) {
        const float smul = (sel == 0) ? alpha : 1.0f;
        float* T = ((sel == 0) ? g_Qd : g_Kd) + (size_t)h * 128 * NN;
#pragma unroll
        for (int mt = 0; mt < 2; mt++)
#pragma unroll
            for (int rr = 0; rr < 2; rr++) {
                int n = n0 + mg * 32 + mt * 16 + rr * 8 + qr;
#pragma unroll
                for (int nt = 0; nt < 8; nt++) {
                    int d = ngg * 64 + nt * 8 + qp * 2;
                    T[(size_t)d * NN + n]       = tf32r(smul * cacc[mt][nt][rr * 2]);
                    T[(size_t)(d + 1) * NN + n] = tf32r(smul * cacc[mt][nt][rr * 2 + 1]);
                }
                if (qp == 0 && ngg == 0) {
                    int row = mg * 32 + mt * 16 + rr * 8 + qr;
                    float sfull = Sred[row][0] + Sred[row][1];
                    float t = sqrtf(sfull + 1.0f);
                    if (sel == 0) g_tq[h * NN + n] = alpha * t;
                    else          g_tk[h * NN + n] = t;
                }
            }
    } else {
#pragma unroll
        for (int mt = 0; mt < 2; mt++)
#pragma unroll
            for (int rr = 0; rr < 2; rr++) {
                int n = n0 + mg * 32 + mt * 16 + rr * 8 + qr;
                float* dst = g_VS + ((size_t)(h * NN + n)) * ND;
#pragma unroll
                for (int nt = 0; nt < 8; nt++) {
                    int col = ngg * 64 + nt * 8 + qp * 2;
                    *(float2*)&dst[col] = make_float2(tf32r(cacc[mt][nt][rr * 2]),
                                                      tf32r(cacc[mt][nt][rr * 2 + 1]));
                }
                if (qp == 0 && ngg == 0) {
                    int row = mg * 32 + mt * 16 + rr * 8 + qr;
                    float sfull = Sred[row][0] + Sred[row][1];
                    g_VT[h * NN + n] = tf32r(sqrtf(sfull + 1.0f));
                }
            }
    }
}

// =====================================================================
// Kernel 2: flash attention via tf32 mma.sync (m16n8k8), 512 threads.
// No online softmax (logits <= 0 by Lorentz Cauchy-Schwarz).
// fp32 rank-1 fixup for the -alpha*t_q*t_k term.
// QSTR = 136 -> conflict-free score A-loads (banks qr + 8*qp).
// =====================================================================
#define QSTR 136
#define KSTR 72
#define VSTR 136
#define PSTR 68

#define OFF_QD   0
#define OFF_K0   17408
#define OFF_K1   (OFF_K0 + 9216)     // 26624
#define OFF_VS   (OFF_K1 + 9216)     // 35840
#define OFF_P    (OFF_VS + 8704)     // 44544
#define OFF_TK0  (OFF_P + 8704)      // 53248
#define OFF_TK1  (OFF_TK0 + 64)      // 53312
#define OFF_LRED (OFF_TK1 + 64)      // 53376  [128][4]
#define OFF_LTOT (OFF_LRED + 512)    // 53888
#define ATTN_SMEM_FLOATS (OFF_LTOT + 128)   // 54016
#define ATTN_SMEM_BYTES  (ATTN_SMEM_FLOATS * 4)

__global__ __launch_bounds__(512, 1) void attn_kernel()
{
    extern __shared__ float sm[];
    float* Qd   = sm + OFF_QD;    // [128 d][136]
    float* Vs   = sm + OFF_VS;    // [64 k][136]  (col 128 = v_t, 129..135 = 0)
    float* Pm   = sm + OFF_P;     // [128 m][68]
    float* Lred = sm + OFF_LRED;
    float* Ltot = sm + OFF_LTOT;

    const int h    = blockIdx.y;
    const int m0   = blockIdx.x * 128;
    const int tid  = threadIdx.x;
    const int lane = tid & 31;
    const int wid  = tid >> 5;
    const int qp   = lane & 3;
    const int qr   = lane >> 2;
    const int mg   = wid & 3;
    const int ng   = wid >> 2;

    const float* qsrc = g_Qd + (size_t)h * 128 * NN + m0;
    const float* ksrc = g_Kd + (size_t)h * 128 * NN;

    float tqr[4];
#pragma unroll
    for (int i = 0; i < 4; i++)
        tqr[i] = g_tq[h * NN + m0 + mg * 32 + qr + 8 * i];

    for (int i = tid; i < 64 * 8; i += 512)
        Vs[(i >> 3) * VSTR + 128 + (i & 7)] = 0.0f;

    for (int idx = tid; idx < 128 * 32; idx += 512) {
        int d = idx >> 5, c = idx & 31;
        cpa16(Qd + d * QSTR + c * 4, qsrc + (size_t)d * NN + c * 4);
    }
    for (int idx = tid; idx < 128 * 16; idx += 512) {
        int d = idx >> 4, c = idx & 15;
        cpa16(sm + OFF_K0 + d * KSTR + c * 4, ksrc + (size_t)d * NN + c * 4);
    }
    if (tid < 16) cpa16(sm + OFF_TK0 + tid * 4, g_tk + h * NN + tid * 4);
    cpa_commit();

    float oc[2][4][4], ot[2][4], lacc[4];
#pragma unroll
    for (int mt = 0; mt < 2; mt++) {
#pragma unroll
        for (int j = 0; j < 4; j++)
#pragma unroll
            for (int r = 0; r < 4; r++) oc[mt][j][r] = 0.0f;
#pragma unroll
        for (int r = 0; r < 4; r++) ot[mt][r] = 0.0f;
    }
#pragma unroll
    for (int i = 0; i < 4; i++) lacc[i] = 0.0f;

    for (int c64 = 0; c64 < 64; c64++) {
        const int k0 = c64 * 64;
        float* Kc  = sm + ((c64 & 1) ? OFF_K1 : OFF_K0);
        float* Kn  = sm + ((c64 & 1) ? OFF_K0 : OFF_K1);
        float* tkc = sm + ((c64 & 1) ? OFF_TK1 : OFF_TK0);
        float* tkn = sm + ((c64 & 1) ? OFF_TK0 : OFF_TK1);

        __syncthreads();

        {
            const float* vsrc = g_VS + ((size_t)(h * NN + k0)) * ND;
            for (int idx = tid; idx < 2048; idx += 512) {
                int n = idx >> 5, c = idx & 31;
                cpa16(Vs + n * VSTR + c * 4, vsrc + (size_t)n * ND + c * 4);
            }
            if (tid < 64) cpa4(Vs + tid * VSTR + 128, g_VT + h * NN + k0 + tid);
        }
        cpa_commit();

        if (c64 < 63) {
            const float* kn = ksrc + k0 + 64;
            for (int idx = tid; idx < 2048; idx += 512) {
                int d = idx >> 4, c = idx & 15;
                cpa16(Kn + d * KSTR + c * 4, kn + (size_t)d * NN + c * 4);
            }
            if (tid < 16) cpa16(tkn + tid * 4, g_tk + h * NN + k0 + 64 + tid * 4);
            cpa_commit();
            cpa_wait<2>();
        } else {
            cpa_wait<1>();
        }
        __syncthreads();

        // ---- scores ----
        float sc[2][2][4];
#pragma unroll
        for (int mt = 0; mt < 2; mt++)
#pragma unroll
            for (int nt = 0; nt < 2; nt++)
#pragma unroll
                for (int r = 0; r < 4; r++) sc[mt][nt][r] = 0.0f;

#pragma unroll
        for (int ks = 0; ks < 16; ks++) {
            const float* qa = Qd + (ks * 8 + qp) * QSTR + mg * 32 + qr;
            unsigned a[2][4];
#pragma unroll
            for (int mt = 0; mt < 2; mt++) {
                const float* q2 = qa + mt * 16;
                a[mt][0] = __float_as_uint(q2[0]);
                a[mt][1] = __float_as_uint(q2[8]);
                a[mt][2] = __float_as_uint(q2[4 * QSTR]);
                a[mt][3] = __float_as_uint(q2[4 * QSTR + 8]);
            }
            const float* kb = Kc + (ks * 8 + qp) * KSTR + ng * 16 + qr;
#pragma unroll
            for (int nt = 0; nt < 2; nt++) {
                unsigned b0 = __float_as_uint(kb[nt * 8]);
                unsigned b1 = __float_as_uint(kb[nt * 8 + 4 * KSTR]);
                mma8(sc[0][nt], a[0][0], a[0][1], a[0][2], a[0][3], b0, b1);
                mma8(sc[1][nt], a[1][0], a[1][1], a[1][2], a[1][3], b0, b1);
            }
        }

        // ---- fixup + exp + stage P + l partials ----
#pragma unroll
        for (int mt = 0; mt < 2; mt++) {
            int prow = mg * 32 + mt * 16 + qr;
#pragma unroll
            for (int nt = 0; nt < 2; nt++) {
                int col = ng * 16 + nt * 8 + qp * 2;
                float t0 = tkc[col], t1 = tkc[col + 1];
                float p0 = tf32r(__expf(sc[mt][nt][0] - tqr[mt * 2]     * t0));
                float p1 = tf32r(__expf(sc[mt][nt][1] - tqr[mt * 2]     * t1));
                float p2 = tf32r(__expf(sc[mt][nt][2] - tqr[mt * 2 + 1] * t0));
                float p3 = tf32r(__expf(sc[mt][nt][3] - tqr[mt * 2 + 1] * t1));
                lacc[mt * 2]     += p0 + p1;
                lacc[mt * 2 + 1] += p2 + p3;
                *(float2*)&Pm[prow * PSTR + col]       = make_float2(p0, p1);
                *(float2*)&Pm[(prow + 8) * PSTR + col] = make_float2(p2, p3);
            }
        }

        if (c64 < 63) cpa_wait<1>(); else cpa_wait<0>();
        __syncthreads();

        // ---- PV ----
#pragma unroll
        for (int ks = 0; ks < 8; ks++) {
            unsigned a[2][4];
#pragma unroll
            for (int mt = 0; mt < 2; mt++) {
                const float* pa = Pm + (mg * 32 + mt * 16 + qr) * PSTR + ks * 8 + qp;
                a[mt][0] = __float_as_uint(pa[0]);
                a[mt][1] = __float_as_uint(pa[8 * PSTR]);
                a[mt][2] = __float_as_uint(pa[4]);
                a[mt][3] = __float_as_uint(pa[8 * PSTR + 4]);
            }
            const float* vb = Vs + (ks * 8 + qp) * VSTR + qr;
#pragma unroll
            for (int j = 0; j < 4; j++) {
                int nb = (ng + 4 * j) * 8;
                unsigned b0 = __float_as_uint(vb[nb]);
                unsigned b1 = __float_as_uint(vb[nb + 4 * VSTR]);
                mma8(oc[0][j], a[0][0], a[0][1], a[0][2], a[0][3], b0, b1);
                mma8(oc[1][j], a[1][0], a[1][1], a[1][2], a[1][3], b0, b1);
            }
            if (ng == 0) {
                unsigned b0 = __float_as_uint(vb[128]);
                unsigned b1 = __float_as_uint(vb[128 + 4 * VSTR]);
                mma8(ot[0], a[0][0], a[0][1], a[0][2], a[0][3], b0, b1);
                mma8(ot[1], a[1][0], a[1][1], a[1][2], a[1][3], b0, b1);
            }
        }
    }

    // ---- epilogue ----
#pragma unroll
    for (int i = 0; i < 4; i++) {
        lacc[i] += __shfl_xor_sync(0xffffffffu, lacc[i], 1);
        lacc[i] += __shfl_xor_sync(0xffffffffu, lacc[i], 2);
    }
    if (qp == 0) {
#pragma unroll
        for (int i = 0; i < 4; i++)
            Lred[(mg * 32 + qr + 8 * i) * 4 + ng] = lacc[i];
    }
    __syncthreads();
    if (tid < 128) {
        const float* lr = Lred + tid * 4;
        Ltot[tid] = lr[0] + lr[1] + lr[2] + lr[3];
    }
    __syncthreads();

    float rl[4];
#pragma unroll
    for (int i = 0; i < 4; i++) rl[i] = 1.0f / Ltot[mg * 32 + qr + 8 * i];

#pragma unroll
    for (int mt = 0; mt < 2; mt++) {
#pragma unroll
        for (int rr = 0; rr < 2; rr++) {
            int row = m0 + mg * 32 + mt * 16 + qr + rr * 8;
            float rlv = rl[mt * 2 + rr];
            float* orow = g_OS + ((size_t)(h * NN + row)) * ND;
#pragma unroll
            for (int j = 0; j < 4; j++) {
                int d0 = (ng + 4 * j) * 8 + qp * 2;
                *(float2*)&orow[d0] =
                    make_float2(oc[mt][j][rr * 2] * rlv, oc[mt][j][rr * 2 + 1] * rlv);
            }
            if (ng == 0 && qp == 0)
                g_OT[h * NN + row] = ot[mt][rr * 2] * rlv;
        }
    }
}

// =====================================================================
// Kernel 3: per-head midpoint_norm + head mean + final norm
// =====================================================================
__global__ __launch_bounds__(256) void final_kernel(float* __restrict__ out)
{
    const int warp = threadIdx.x >> 5;
    const int lane = threadIdx.x & 31;
    const int n = blockIdx.x * 8 + warp;

    float as0 = 0.f, as1 = 0.f, as2 = 0.f, as3 = 0.f, at = 0.f;
#pragma unroll
    for (int h = 0; h < NH; h++) {
        float4 v = *(const float4*)&g_OS[((size_t)(h * NN + n)) * ND + lane * 4];
        float t = g_OT[h * NN + n];
        float ssn = v.x * v.x + v.y * v.y + v.z * v.z + v.w * v.w;
#pragma unroll
        for (int off = 16; off; off >>= 1)
            ssn += __shfl_xor_sync(0xffffffffu, ssn, off);
        float inner = ssn - t * t;
        float f = 1.0f / sqrtf(fmaxf(fabsf(inner), 1e-8f));
        as0 += v.x * f; as1 += v.y * f; as2 += v.z * f; as3 += v.w * f;
        at  += t * f;
    }
    const float inv = 1.0f / (float)NH;
    as0 *= inv; as1 *= inv; as2 *= inv; as3 *= inv; at *= inv;

    float q = as0 * as0 + as1 * as1 + as2 * as2 + as3 * as3;
#pragma unroll
    for (int off = 16; off; off >>= 1)
        q += __shfl_xor_sync(0xffffffffu, q, off);

    float inner = q - at * at;
    float f = 1.0f / sqrtf(fmaxf(fabsf(inner), 1e-8f));

    float* o = out + (size_t)n * 129;
    if (lane == 0) o[0] = at * f;
    o[1 + lane * 4 + 0] = as0 * f;
    o[1 + lane * 4 + 1] = as1 * f;
    o[1 + lane * 4 + 2] = as2 * f;
    o[1 + lane * 4 + 3] = as3 * f;
}

// =====================================================================
extern "C" void kernel_launch(void* const* d_in, const int* in_sizes, int n_in,
                              void* d_out, int out_size)
{
    const float* x     = (const float*)d_in[0];
    const float* Wq    = (const float*)d_in[1];
    const float* bq    = (const float*)d_in[2];
    const float* Wk    = (const float*)d_in[3];
    const float* bk    = (const float*)d_in[4];
    const float* Wv    = (const float*)d_in[5];
    const float* bv    = (const float*)d_in[6];
    const float* scale = (const float*)d_in[7];
    float* out = (float*)d_out;

    cudaFuncSetAttribute(proj_kernel,
                         cudaFuncAttributeMaxDynamicSharedMemorySize,
                         PROJ_SMEM_BYTES);
    cudaFuncSetAttribute(attn_kernel,
                         cudaFuncAttributeMaxDynamicSharedMemorySize,
                         ATTN_SMEM_BYTES);

    proj_kernel<<<dim3(NN / 128, NH * 3), 256, PROJ_SMEM_BYTES>>>(
        x, Wq, bq, Wk, bk, Wv, bv, scale);
    attn_kernel<<<dim3(NN / 128, NH), 512, ATTN_SMEM_BYTES>>>();
    final_kernel<<<NN / 8, 256>>>(out);
}

// round 9
// speedup vs baseline: 6.6137x; 1.6330x over previous
#include <cuda_runtime.h>
#include <math.h>

#define NH   12
#define NN   4096
#define ND   128
#define NIN  256

// ---- tf32 (proj) ----
__device__ __forceinline__ void mma8(float* c,
    unsigned a0, unsigned a1, unsigned a2, unsigned a3,
    unsigned b0, unsigned b1)
{
    asm volatile("mma.sync.aligned.m16n8k8.row.col.f32.tf32.tf32.f32 "
        "{%0,%1,%2,%3}, {%4,%5,%6,%7}, {%8,%9}, {%0,%1,%2,%3};"
        : "+f"(c[0]), "+f"(c[1]), "+f"(c[2]), "+f"(c[3])
        : "r"(a0), "r"(a1), "r"(a2), "r"(a3), "r"(b0), "r"(b1));
}
// ---- bf16 (attn) ----
__device__ __forceinline__ void mma16(float* c,
    unsigned a0, unsigned a1, unsigned a2, unsigned a3,
    unsigned b0, unsigned b1)
{
    asm volatile("mma.sync.aligned.m16n8k16.row.col.f32.bf16.bf16.f32 "
        "{%0,%1,%2,%3}, {%4,%5,%6,%7}, {%8,%9}, {%0,%1,%2,%3};"
        : "+f"(c[0]), "+f"(c[1]), "+f"(c[2]), "+f"(c[3])
        : "r"(a0), "r"(a1), "r"(a2), "r"(a3), "r"(b0), "r"(b1));
}
__device__ __forceinline__ unsigned pkbf2(float lo, float hi) {
    unsigned r;
    asm("{.reg .b16 l, h;\n\t"
        "cvt.rn.bf16.f32 l, %1;\n\t"
        "cvt.rn.bf16.f32 h, %2;\n\t"
        "mov.b32 %0, {l, h};}"
        : "=r"(r) : "f"(lo), "f"(hi));
    return r;
}

// ---- cp.async ----
__device__ __forceinline__ void cpa16(void* dst, const void* src) {
    unsigned d = (unsigned)__cvta_generic_to_shared(dst);
    asm volatile("cp.async.cg.shared.global [%0], [%1], 16;" :: "r"(d), "l"(src));
}
__device__ __forceinline__ void cpa4(void* dst, const void* src) {
    unsigned d = (unsigned)__cvta_generic_to_shared(dst);
    asm volatile("cp.async.ca.shared.global [%0], [%1], 4;" :: "r"(d), "l"(src));
}
__device__ __forceinline__ void cpa_commit() {
    asm volatile("cp.async.commit_group;" ::: "memory");
}
template<int N>
__device__ __forceinline__ void cpa_wait() {
    asm volatile("cp.async.wait_group %0;" :: "n"(N) : "memory");
}

// ---------------- scratch ----------------
// Q/K: bf16x2 d-pair-packed, d-major: [h][dp 64][n 4096]
__device__ unsigned g_Qp[NH * 64 * NN];     // alpha * s_q
__device__ unsigned g_Kp[NH * 64 * NN];     // s_k
// V: bf16x2 key-pair-packed: [h][np 2048][d 128]
__device__ unsigned g_Vp[NH * (NN / 2) * ND];
__device__ unsigned g_VTp[NH * (NN / 2)];   // (v_t[2i], v_t[2i+1])
__device__ float g_tq[NH * NN];             // alpha * t_q (fp32)
__device__ float g_tk[NH * NN];             // t_k (fp32)
__device__ float g_OS[NH * NN * ND];
__device__ float g_OT[NH * NN];

// =====================================================================
// Kernel 1: projections via tf32 mma.sync; epilogue emits packed bf16.
// =====================================================================
#define PSTRX 36
#define PROJ_TILE (128 * PSTRX)
#define PROJ_SMEM_FLOATS (4 * PROJ_TILE)
#define PROJ_SMEM_BYTES  (PROJ_SMEM_FLOATS * 4)

__global__ __launch_bounds__(256, 1) void proj_kernel(
    const float* __restrict__ x,
    const float* __restrict__ Wq, const float* __restrict__ bq,
    const float* __restrict__ Wk, const float* __restrict__ bk,
    const float* __restrict__ Wv, const float* __restrict__ bv,
    const float* __restrict__ scale_ptr)
{
    extern __shared__ float psm[];
    __shared__ float Sred[128][2];

    const int by  = blockIdx.y;
    const int h   = by % NH;
    const int sel = by / NH;

    const float* W = (sel == 0) ? Wq : (sel == 1) ? Wk : Wv;
    const float* B = (sel == 0) ? bq : (sel == 1) ? bk : bv;
    const float* Wh = W + (size_t)h * ND * NIN;

    const int n0   = blockIdx.x * 128;
    const int tid  = threadIdx.x;
    const int lane = tid & 31;
    const int wid  = tid >> 5;
    const int qp   = lane & 3;
    const int qr   = lane >> 2;
    const int mg   = wid & 3;
    const int ngg  = wid >> 2;

    auto load_chunk = [&](int kb, int buf) {
        float* Xs = psm + buf * (2 * PROJ_TILE);
        float* Ws = Xs + PROJ_TILE;
        for (int idx = tid; idx < 128 * 32; idx += 256) {
            int m = idx >> 5, k = idx & 31;
            cpa4(Xs + m * PSTRX + k, x + (size_t)(n0 + m) * 257 + 1 + kb + k);
        }
        for (int idx = tid; idx < 128 * 8; idx += 256) {
            int o = idx >> 3, kq = idx & 7;
            cpa16(Ws + o * PSTRX + kq * 4, Wh + (size_t)o * NIN + kb + kq * 4);
        }
    };

    float cacc[2][8][4];
#pragma unroll
    for (int mt = 0; mt < 2; mt++)
#pragma unroll
        for (int nt = 0; nt < 8; nt++)
#pragma unroll
            for (int r = 0; r < 4; r++) cacc[mt][nt][r] = 0.0f;

    load_chunk(0, 0);
    cpa_commit();

    for (int c = 0; c < 8; c++) {
        if (c < 7) {
            load_chunk((c + 1) * 32, (c + 1) & 1);
            cpa_commit();
            cpa_wait<1>();
        } else {
            cpa_wait<0>();
        }
        __syncthreads();

        const float* Xc = psm + (c & 1) * (2 * PROJ_TILE);
        const float* Wc = Xc + PROJ_TILE;

#pragma unroll
        for (int ks = 0; ks < 4; ks++) {
            unsigned a[2][4];
            const float* qa = Xc + (mg * 32 + qr) * PSTRX + ks * 8 + qp;
#pragma unroll
            for (int mt = 0; mt < 2; mt++) {
                const float* q2 = qa + mt * 16 * PSTRX;
                a[mt][0] = __float_as_uint(q2[0]);
                a[mt][1] = __float_as_uint(q2[8 * PSTRX]);
                a[mt][2] = __float_as_uint(q2[4]);
                a[mt][3] = __float_as_uint(q2[8 * PSTRX + 4]);
            }
#pragma unroll
            for (int nt = 0; nt < 8; nt++) {
                const float* kb = Wc + (ngg * 64 + nt * 8 + qr) * PSTRX + ks * 8 + qp;
                unsigned b0 = __float_as_uint(kb[0]);
                unsigned b1 = __float_as_uint(kb[4]);
                mma8(cacc[0][nt], a[0][0], a[0][1], a[0][2], a[0][3], b0, b1);
                mma8(cacc[1][nt], a[1][0], a[1][1], a[1][2], a[1][3], b0, b1);
            }
        }
        __syncthreads();
    }

    // ---- epilogue: bias, |s|^2, t, packed stores ----
    float bb[8][2];
#pragma unroll
    for (int nt = 0; nt < 8; nt++) {
        int col = ngg * 64 + nt * 8 + qp * 2;
        bb[nt][0] = B[h * ND + col];
        bb[nt][1] = B[h * ND + col + 1];
    }

    float ssq[2][2] = {{0.f, 0.f}, {0.f, 0.f}};
#pragma unroll
    for (int mt = 0; mt < 2; mt++)
#pragma unroll
        for (int nt = 0; nt < 8; nt++)
#pragma unroll
            for (int rr = 0; rr < 2; rr++) {
                cacc[mt][nt][rr * 2]     += bb[nt][0];
                cacc[mt][nt][rr * 2 + 1] += bb[nt][1];
                ssq[mt][rr] = fmaf(cacc[mt][nt][rr * 2], cacc[mt][nt][rr * 2], ssq[mt][rr]);
                ssq[mt][rr] = fmaf(cacc[mt][nt][rr * 2 + 1], cacc[mt][nt][rr * 2 + 1], ssq[mt][rr]);
            }
#pragma unroll
    for (int mt = 0; mt < 2; mt++)
#pragma unroll
        for (int rr = 0; rr < 2; rr++) {
            ssq[mt][rr] += __shfl_xor_sync(0xffffffffu, ssq[mt][rr], 1);
            ssq[mt][rr] += __shfl_xor_sync(0xffffffffu, ssq[mt][rr], 2);
        }
    if (qp == 0) {
#pragma unroll
        for (int mt = 0; mt < 2; mt++)
#pragma unroll
            for (int rr = 0; rr < 2; rr++)
                Sred[mg * 32 + mt * 16 + rr * 8 + qr][ngg] = ssq[mt][rr];
    }
    __syncthreads();

    const float alpha = 2.0f / scale_ptr[0];

    if (sel < 2) {
        const float smul = (sel == 0) ? alpha : 1.0f;
        unsigned* T = ((sel == 0) ? g_Qp : g_Kp) + (size_t)h * 64 * NN;
#pragma unroll
        for (int mt = 0; mt < 2; mt++)
#pragma unroll
            for (int rr = 0; rr < 2; rr++) {
                int n = n0 + mg * 32 + mt * 16 + rr * 8 + qr;
#pragma unroll
                for (int nt = 0; nt < 8; nt++) {
                    int dp = ngg * 32 + nt * 4 + qp;
                    T[(size_t)dp * NN + n] =
                        pkbf2(smul * cacc[mt][nt][rr * 2], smul * cacc[mt][nt][rr * 2 + 1]);
                }
                if (qp == 0 && ngg == 0) {
                    int row = mg * 32 + mt * 16 + rr * 8 + qr;
                    float t = sqrtf(Sred[row][0] + Sred[row][1] + 1.0f);
                    if (sel == 0) g_tq[h * NN + n] = alpha * t;
                    else          g_tk[h * NN + n] = t;
                }
            }
    } else {
        // V: key-pair packing via shfl_down(4)  (row qr even pairs with qr+1)
#pragma unroll
        for (int mt = 0; mt < 2; mt++)
#pragma unroll
            for (int rr = 0; rr < 2; rr++) {
                int n = n0 + mg * 32 + mt * 16 + rr * 8 + qr;
                int row = mg * 32 + mt * 16 + rr * 8 + qr;
                float t = sqrtf(Sred[row][0] + Sred[row][1] + 1.0f);
                float tp = __shfl_down_sync(0xffffffffu, t, 4);
                unsigned* vdst = g_Vp + ((size_t)h * 2048 + (n >> 1)) * ND;
#pragma unroll
                for (int nt = 0; nt < 8; nt++) {
                    int col = ngg * 64 + nt * 8 + qp * 2;
                    float v0 = cacc[mt][nt][rr * 2];
                    float v1 = cacc[mt][nt][rr * 2 + 1];
                    float v0p = __shfl_down_sync(0xffffffffu, v0, 4);
                    float v1p = __shfl_down_sync(0xffffffffu, v1, 4);
                    if ((qr & 1) == 0) {
                        vdst[col]     = pkbf2(v0, v0p);
                        vdst[col + 1] = pkbf2(v1, v1p);
                    }
                }
                if (qp == 0 && ngg == 0 && (qr & 1) == 0)
                    g_VTp[h * 2048 + (n >> 1)] = pkbf2(t, tp);
            }
    }
}

// =====================================================================
// Kernel 2: flash attention via bf16 mma.sync (m16n8k16), 512 threads.
// Packed operands; fp32 rank-1 fixup; no online softmax.
// =====================================================================
#define MSTR 136
#define KSTR 72
#define VSTR 136
#define PSTR 36

#define OFF_QP   0                       // [64 dp][136]  u32
#define OFF_K0   8704
#define OFF_K1   (OFF_K0 + 4608)         // 13312
#define OFF_VP   (OFF_K1 + 4608)         // 17920  [32 np][136] u32
#define OFF_PP   (OFF_VP + 4352)         // 22272  [128 m][36] u32
#define OFF_TK0  (OFF_PP + 4608)         // 26880  (f32)
#define OFF_TK1  (OFF_TK0 + 64)          // 26944
#define OFF_LRED (OFF_TK1 + 64)          // 27008
#define OFF_LTOT (OFF_LRED + 512)        // 27520
#define ATTN_SMEM_WORDS (OFF_LTOT + 128) // 27648
#define ATTN_SMEM_BYTES (ATTN_SMEM_WORDS * 4)

__global__ __launch_bounds__(512, 1) void attn_kernel()
{
    extern __shared__ unsigned smu[];
    unsigned* Qp   = smu + OFF_QP;
    unsigned* Vp   = smu + OFF_VP;
    unsigned* Pp   = smu + OFF_PP;
    float*    Lred = (float*)(smu + OFF_LRED);
    float*    Ltot = (float*)(smu + OFF_LTOT);

    const int h    = blockIdx.y;
    const int m0   = blockIdx.x * 128;
    const int tid  = threadIdx.x;
    const int lane = tid & 31;
    const int wid  = tid >> 5;
    const int qp   = lane & 3;
    const int qr   = lane >> 2;
    const int mg   = wid & 3;
    const int ng   = wid >> 2;

    const unsigned* qsrc = g_Qp + (size_t)h * 64 * NN + m0;
    const unsigned* ksrc = g_Kp + (size_t)h * 64 * NN;

    float tqr[4];
#pragma unroll
    for (int i = 0; i < 4; i++)
        tqr[i] = g_tq[h * NN + m0 + mg * 32 + qr + 8 * i];

    // zero V pad cols 129..135 (written once; V loads never touch them)
    for (int i = tid; i < 32 * 7; i += 512)
        Vp[(i / 7) * VSTR + 129 + (i % 7)] = 0u;

    // prologue: Q tile + K(0) + tk(0)
    for (int idx = tid; idx < 64 * 32; idx += 512) {
        int dp = idx >> 5, c = idx & 31;
        cpa16(Qp + dp * MSTR + c * 4, qsrc + (size_t)dp * NN + c * 4);
    }
    for (int idx = tid; idx < 64 * 16; idx += 512) {
        int dp = idx >> 4, c = idx & 15;
        cpa16(smu + OFF_K0 + dp * KSTR + c * 4, ksrc + (size_t)dp * NN + c * 4);
    }
    if (tid < 16) cpa16(smu + OFF_TK0 + tid * 4, g_tk + h * NN + tid * 4);
    cpa_commit();

    float oc[2][4][4], ot[2][4], lacc[4];
#pragma unroll
    for (int mt = 0; mt < 2; mt++) {
#pragma unroll
        for (int j = 0; j < 4; j++)
#pragma unroll
            for (int r = 0; r < 4; r++) oc[mt][j][r] = 0.0f;
#pragma unroll
        for (int r = 0; r < 4; r++) ot[mt][r] = 0.0f;
    }
#pragma unroll
    for (int i = 0; i < 4; i++) lacc[i] = 0.0f;

    for (int c64 = 0; c64 < 64; c64++) {
        const int k0 = c64 * 64;
        unsigned* Kc  = smu + ((c64 & 1) ? OFF_K1 : OFF_K0);
        unsigned* Kn  = smu + ((c64 & 1) ? OFF_K0 : OFF_K1);
        float*    tkc = (float*)(smu + ((c64 & 1) ? OFF_TK1 : OFF_TK0));
        float*    tkn = (float*)(smu + ((c64 & 1) ? OFF_TK0 : OFF_TK1));

        __syncthreads();   // A: PV(c-1) done; Vp/Pp/Kn writable

        // V(c): 32 key-pairs x 128 d + v_t col
        {
            const unsigned* vsrc = g_Vp + ((size_t)h * 2048 + (k0 >> 1)) * ND;
            for (int idx = tid; idx < 1024; idx += 512) {
                int np = idx >> 5, c = idx & 31;
                cpa16(Vp + np * VSTR + c * 4, vsrc + (size_t)np * ND + c * 4);
            }
            if (tid < 32) cpa4(Vp + tid * VSTR + 128, g_VTp + h * 2048 + (k0 >> 1) + tid);
        }
        cpa_commit();

        if (c64 < 63) {
            const unsigned* kn = ksrc + k0 + 64;
            for (int idx = tid; idx < 64 * 16; idx += 512) {
                int dp = idx >> 4, c = idx & 15;
                cpa16(Kn + dp * KSTR + c * 4, kn + (size_t)dp * NN + c * 4);
            }
            if (tid < 16) cpa16(tkn + tid * 4, g_tk + h * NN + k0 + 64 + tid * 4);
            cpa_commit();
            cpa_wait<2>();
        } else {
            cpa_wait<1>();
        }
        __syncthreads();   // B: K(c)/tk(c) visible

        // ---- scores: 8 k16-steps ----
        float sc[2][2][4];
#pragma unroll
        for (int mt = 0; mt < 2; mt++)
#pragma unroll
            for (int nt = 0; nt < 2; nt++)
#pragma unroll
                for (int r = 0; r < 4; r++) sc[mt][nt][r] = 0.0f;

#pragma unroll
        for (int ks = 0; ks < 8; ks++) {
            const unsigned* qa = Qp + (ks * 8 + qp) * MSTR + mg * 32 + qr;
            unsigned a[2][4];
#pragma unroll
            for (int mt = 0; mt < 2; mt++) {
                a[mt][0] = qa[mt * 16];
                a[mt][1] = qa[mt * 16 + 8];
                a[mt][2] = qa[4 * MSTR + mt * 16];
                a[mt][3] = qa[4 * MSTR + mt * 16 + 8];
            }
            const unsigned* kb = Kc + (ks * 8 + qp) * KSTR + ng * 16 + qr;
#pragma unroll
            for (int nt = 0; nt < 2; nt++) {
                unsigned b0 = kb[nt * 8];
                unsigned b1 = kb[4 * KSTR + nt * 8];
                mma16(sc[0][nt], a[0][0], a[0][1], a[0][2], a[0][3], b0, b1);
                mma16(sc[1][nt], a[1][0], a[1][1], a[1][2], a[1][3], b0, b1);
            }
        }

        // ---- fixup + exp + stage packed P + l partials ----
#pragma unroll
        for (int mt = 0; mt < 2; mt++) {
            int prow = mg * 32 + mt * 16 + qr;
            int npcol = ng * 8 + qp;   // + nt*4
#pragma unroll
            for (int nt = 0; nt < 2; nt++) {
                int col = ng * 16 + nt * 8 + qp * 2;
                float t0 = tkc[col], t1 = tkc[col + 1];
                float p0 = __expf(sc[mt][nt][0] - tqr[mt * 2]     * t0);
                float p1 = __expf(sc[mt][nt][1] - tqr[mt * 2]     * t1);
                float p2 = __expf(sc[mt][nt][2] - tqr[mt * 2 + 1] * t0);
                float p3 = __expf(sc[mt][nt][3] - tqr[mt * 2 + 1] * t1);
                unsigned pk01 = pkbf2(p0, p1);
                unsigned pk23 = pkbf2(p2, p3);
                // l sums the ROUNDED values (keeps ave a convex combination)
                lacc[mt * 2] += __uint_as_float(pk01 << 16)
                              + __uint_as_float(pk01 & 0xffff0000u);
                lacc[mt * 2 + 1] += __uint_as_float(pk23 << 16)
                                  + __uint_as_float(pk23 & 0xffff0000u);
                Pp[prow * PSTR + npcol + nt * 4]       = pk01;
                Pp[(prow + 8) * PSTR + npcol + nt * 4] = pk23;
            }
        }

        if (c64 < 63) cpa_wait<1>(); else cpa_wait<0>();   // V(c) done
        __syncthreads();   // C: Pp + Vp visible

        // ---- PV: 4 k16-steps over 64 keys ----
#pragma unroll
        for (int ks = 0; ks < 4; ks++) {
            const unsigned* pa = Pp + (mg * 32 + qr) * PSTR + ks * 8 + qp;
            unsigned a[2][4];
#pragma unroll
            for (int mt = 0; mt < 2; mt++) {
                a[mt][0] = pa[mt * 16 * PSTR];
                a[mt][1] = pa[(mt * 16 + 8) * PSTR];
                a[mt][2] = pa[mt * 16 * PSTR + 4];
                a[mt][3] = pa[(mt * 16 + 8) * PSTR + 4];
            }
            const unsigned* vb = Vp + (ks * 8 + qp) * VSTR + qr;
#pragma unroll
            for (int j = 0; j < 4; j++) {
                int nb = (ng + 4 * j) * 8;
                unsigned b0 = vb[nb];
                unsigned b1 = vb[4 * VSTR + nb];
                mma16(oc[0][j], a[0][0], a[0][1], a[0][2], a[0][3], b0, b1);
                mma16(oc[1][j], a[1][0], a[1][1], a[1][2], a[1][3], b0, b1);
            }
            if (ng == 0) {
                unsigned b0 = vb[128];
                unsigned b1 = vb[4 * VSTR + 128];
                mma16(ot[0], a[0][0], a[0][1], a[0][2], a[0][3], b0, b1);
                mma16(ot[1], a[1][0], a[1][1], a[1][2], a[1][3], b0, b1);
            }
        }
    }

    // ---- epilogue ----
#pragma unroll
    for (int i = 0; i < 4; i++) {
        lacc[i] += __shfl_xor_sync(0xffffffffu, lacc[i], 1);
        lacc[i] += __shfl_xor_sync(0xffffffffu, lacc[i], 2);
    }
    if (qp == 0) {
#pragma unroll
        for (int i = 0; i < 4; i++)
            Lred[(mg * 32 + qr + 8 * i) * 4 + ng] = lacc[i];
    }
    __syncthreads();
    if (tid < 128) {
        const float* lr = Lred + tid * 4;
        Ltot[tid] = lr[0] + lr[1] + lr[2] + lr[3];
    }
    __syncthreads();

    float rl[4];
#pragma unroll
    for (int i = 0; i < 4; i++) rl[i] = 1.0f / Ltot[mg * 32 + qr + 8 * i];

#pragma unroll
    for (int mt = 0; mt < 2; mt++) {
#pragma unroll
        for (int rr = 0; rr < 2; rr++) {
            int row = m0 + mg * 32 + mt * 16 + qr + rr * 8;
            float rlv = rl[mt * 2 + rr];
            float* orow = g_OS + ((size_t)(h * NN + row)) * ND;
#pragma unroll
            for (int j = 0; j < 4; j++) {
                int d0 = (ng + 4 * j) * 8 + qp * 2;
                *(float2*)&orow[d0] =
                    make_float2(oc[mt][j][rr * 2] * rlv, oc[mt][j][rr * 2 + 1] * rlv);
            }
            if (ng == 0 && qp == 0)
                g_OT[h * NN + row] = ot[mt][rr * 2] * rlv;
        }
    }
}

// =====================================================================
// Kernel 3: per-head midpoint_norm + head mean + final norm
// =====================================================================
__global__ __launch_bounds__(256) void final_kernel(float* __restrict__ out)
{
    const int warp = threadIdx.x >> 5;
    const int lane = threadIdx.x & 31;
    const int n = blockIdx.x * 8 + warp;

    float as0 = 0.f, as1 = 0.f, as2 = 0.f, as3 = 0.f, at = 0.f;
#pragma unroll
    for (int h = 0; h < NH; h++) {
        float4 v = *(const float4*)&g_OS[((size_t)(h * NN + n)) * ND + lane * 4];
        float t = g_OT[h * NN + n];
        float ssn = v.x * v.x + v.y * v.y + v.z * v.z + v.w * v.w;
#pragma unroll
        for (int off = 16; off; off >>= 1)
            ssn += __shfl_xor_sync(0xffffffffu, ssn, off);
        float inner = ssn - t * t;
        float f = 1.0f / sqrtf(fmaxf(fabsf(inner), 1e-8f));
        as0 += v.x * f; as1 += v.y * f; as2 += v.z * f; as3 += v.w * f;
        at  += t * f;
    }
    const float inv = 1.0f / (float)NH;
    as0 *= inv; as1 *= inv; as2 *= inv; as3 *= inv; at *= inv;

    float q = as0 * as0 + as1 * as1 + as2 * as2 + as3 * as3;
#pragma unroll
    for (int off = 16; off; off >>= 1)
        q += __shfl_xor_sync(0xffffffffu, q, off);

    float inner = q - at * at;
    float f = 1.0f / sqrtf(fmaxf(fabsf(inner), 1e-8f));

    float* o = out + (size_t)n * 129;
    if (lane == 0) o[0] = at * f;
    o[1 + lane * 4 + 0] = as0 * f;
    o[1 + lane * 4 + 1] = as1 * f;
    o[1 + lane * 4 + 2] = as2 * f;
    o[1 + lane * 4 + 3] = as3 * f;
}

// =====================================================================
extern "C" void kernel_launch(void* const* d_in, const int* in_sizes, int n_in,
                              void* d_out, int out_size)
{
    const float* x     = (const float*)d_in[0];
    const float* Wq    = (const float*)d_in[1];
    const float* bq    = (const float*)d_in[2];
    const float* Wk    = (const float*)d_in[3];
    const float* bk    = (const float*)d_in[4];
    const float* Wv    = (const float*)d_in[5];
    const float* bv    = (const float*)d_in[6];
    const float* scale = (const float*)d_in[7];
    float* out = (float*)d_out;

    cudaFuncSetAttribute(proj_kernel,
                         cudaFuncAttributeMaxDynamicSharedMemorySize,
                         PROJ_SMEM_BYTES);
    cudaFuncSetAttribute(attn_kernel,
                         cudaFuncAttributeMaxDynamicSharedMemorySize,
                         ATTN_SMEM_BYTES);

    proj_kernel<<<dim3(NN / 128, NH * 3), 256, PROJ_SMEM_BYTES>>>(
        x, Wq, bq, Wk, bk, Wv, bv, scale);
    attn_kernel<<<dim3(NN / 128, NH), 512, ATTN_SMEM_BYTES>>>();
    final_kernel<<<NN / 8, 256>>>(out);
}

// round 10
// speedup vs baseline: 6.6261x; 1.0019x over previous
#include <cuda_runtime.h>
#include <math.h>

#define NH   12
#define NN   4096
#define ND   128
#define NIN  256

// ---- tf32 (proj) ----
__device__ __forceinline__ void mma8(float* c,
    unsigned a0, unsigned a1, unsigned a2, unsigned a3,
    unsigned b0, unsigned b1)
{
    asm volatile("mma.sync.aligned.m16n8k8.row.col.f32.tf32.tf32.f32 "
        "{%0,%1,%2,%3}, {%4,%5,%6,%7}, {%8,%9}, {%0,%1,%2,%3};"
        : "+f"(c[0]), "+f"(c[1]), "+f"(c[2]), "+f"(c[3])
        : "r"(a0), "r"(a1), "r"(a2), "r"(a3), "r"(b0), "r"(b1));
}
// ---- bf16 (attn) ----
__device__ __forceinline__ void mma16(float* c,
    unsigned a0, unsigned a1, unsigned a2, unsigned a3,
    unsigned b0, unsigned b1)
{
    asm volatile("mma.sync.aligned.m16n8k16.row.col.f32.bf16.bf16.f32 "
        "{%0,%1,%2,%3}, {%4,%5,%6,%7}, {%8,%9}, {%0,%1,%2,%3};"
        : "+f"(c[0]), "+f"(c[1]), "+f"(c[2]), "+f"(c[3])
        : "r"(a0), "r"(a1), "r"(a2), "r"(a3), "r"(b0), "r"(b1));
}
__device__ __forceinline__ unsigned pkbf2(float lo, float hi) {
    unsigned r;
    asm("{.reg .b16 l, h;\n\t"
        "cvt.rn.bf16.f32 l, %1;\n\t"
        "cvt.rn.bf16.f32 h, %2;\n\t"
        "mov.b32 %0, {l, h};}"
        : "=r"(r) : "f"(lo), "f"(hi));
    return r;
}

// ---- cp.async ----
__device__ __forceinline__ void cpa16(void* dst, const void* src) {
    unsigned d = (unsigned)__cvta_generic_to_shared(dst);
    asm volatile("cp.async.cg.shared.global [%0], [%1], 16;" :: "r"(d), "l"(src));
}
__device__ __forceinline__ void cpa4(void* dst, const void* src) {
    unsigned d = (unsigned)__cvta_generic_to_shared(dst);
    asm volatile("cp.async.ca.shared.global [%0], [%1], 4;" :: "r"(d), "l"(src));
}
__device__ __forceinline__ void cpa_commit() {
    asm volatile("cp.async.commit_group;" ::: "memory");
}
template<int N>
__device__ __forceinline__ void cpa_wait() {
    asm volatile("cp.async.wait_group %0;" :: "n"(N) : "memory");
}

// ---------------- scratch ----------------
// Q/K: bf16x2 d-pair-packed, d-major: [h][dp 64][n 4096]
__device__ unsigned g_Qp[NH * 64 * NN];     // alpha * s_q
__device__ unsigned g_Kp[NH * 64 * NN];     // s_k
// V: bf16x2 key-pair-packed: [h][np 2048][d 128]
__device__ unsigned g_Vp[NH * (NN / 2) * ND];
__device__ unsigned g_VTp[NH * (NN / 2)];   // (v_t[2i], v_t[2i+1])
__device__ float g_tq[NH * NN];             // alpha * t_q (fp32)
__device__ float g_tk[NH * NN];             // t_k (fp32)
__device__ float g_OS[NH * NN * ND];
__device__ float g_OT[NH * NN];

// =====================================================================
// Kernel 1: projections via tf32 mma.sync; epilogue emits packed bf16.
// =====================================================================
#define PSTRX 36
#define PROJ_TILE (128 * PSTRX)
#define PROJ_SMEM_FLOATS (4 * PROJ_TILE)
#define PROJ_SMEM_BYTES  (PROJ_SMEM_FLOATS * 4)

__global__ __launch_bounds__(256, 1) void proj_kernel(
    const float* __restrict__ x,
    const float* __restrict__ Wq, const float* __restrict__ bq,
    const float* __restrict__ Wk, const float* __restrict__ bk,
    const float* __restrict__ Wv, const float* __restrict__ bv,
    const float* __restrict__ scale_ptr)
{
    extern __shared__ float psm[];
    __shared__ float Sred[128][2];

    const int by  = blockIdx.y;
    const int h   = by % NH;
    const int sel = by / NH;

    const float* W = (sel == 0) ? Wq : (sel == 1) ? Wk : Wv;
    const float* B = (sel == 0) ? bq : (sel == 1) ? bk : bv;
    const float* Wh = W + (size_t)h * ND * NIN;

    const int n0   = blockIdx.x * 128;
    const int tid  = threadIdx.x;
    const int lane = tid & 31;
    const int wid  = tid >> 5;
    const int qp   = lane & 3;
    const int qr   = lane >> 2;
    const int mg   = wid & 3;
    const int ngg  = wid >> 2;

    auto load_chunk = [&](int kb, int buf) {
        float* Xs = psm + buf * (2 * PROJ_TILE);
        float* Ws = Xs + PROJ_TILE;
        for (int idx = tid; idx < 128 * 32; idx += 256) {
            int m = idx >> 5, k = idx & 31;
            cpa4(Xs + m * PSTRX + k, x + (size_t)(n0 + m) * 257 + 1 + kb + k);
        }
        for (int idx = tid; idx < 128 * 8; idx += 256) {
            int o = idx >> 3, kq = idx & 7;
            cpa16(Ws + o * PSTRX + kq * 4, Wh + (size_t)o * NIN + kb + kq * 4);
        }
    };

    float cacc[2][8][4];
#pragma unroll
    for (int mt = 0; mt < 2; mt++)
#pragma unroll
        for (int nt = 0; nt < 8; nt++)
#pragma unroll
            for (int r = 0; r < 4; r++) cacc[mt][nt][r] = 0.0f;

    load_chunk(0, 0);
    cpa_commit();

    for (int c = 0; c < 8; c++) {
        if (c < 7) {
            load_chunk((c + 1) * 32, (c + 1) & 1);
            cpa_commit();
            cpa_wait<1>();
        } else {
            cpa_wait<0>();
        }
        __syncthreads();

        const float* Xc = psm + (c & 1) * (2 * PROJ_TILE);
        const float* Wc = Xc + PROJ_TILE;

#pragma unroll
        for (int ks = 0; ks < 4; ks++) {
            unsigned a[2][4];
            const float* qa = Xc + (mg * 32 + qr) * PSTRX + ks * 8 + qp;
#pragma unroll
            for (int mt = 0; mt < 2; mt++) {
                const float* q2 = qa + mt * 16 * PSTRX;
                a[mt][0] = __float_as_uint(q2[0]);
                a[mt][1] = __float_as_uint(q2[8 * PSTRX]);
                a[mt][2] = __float_as_uint(q2[4]);
                a[mt][3] = __float_as_uint(q2[8 * PSTRX + 4]);
            }
#pragma unroll
            for (int nt = 0; nt < 8; nt++) {
                const float* kb = Wc + (ngg * 64 + nt * 8 + qr) * PSTRX + ks * 8 + qp;
                unsigned b0 = __float_as_uint(kb[0]);
                unsigned b1 = __float_as_uint(kb[4]);
                mma8(cacc[0][nt], a[0][0], a[0][1], a[0][2], a[0][3], b0, b1);
                mma8(cacc[1][nt], a[1][0], a[1][1], a[1][2], a[1][3], b0, b1);
            }
        }
        __syncthreads();
    }

    // ---- epilogue: bias, |s|^2, t, packed stores ----
    float bb[8][2];
#pragma unroll
    for (int nt = 0; nt < 8; nt++) {
        int col = ngg * 64 + nt * 8 + qp * 2;
        bb[nt][0] = B[h * ND + col];
        bb[nt][1] = B[h * ND + col + 1];
    }

    float ssq[2][2] = {{0.f, 0.f}, {0.f, 0.f}};
#pragma unroll
    for (int mt = 0; mt < 2; mt++)
#pragma unroll
        for (int nt = 0; nt < 8; nt++)
#pragma unroll
            for (int rr = 0; rr < 2; rr++) {
                cacc[mt][nt][rr * 2]     += bb[nt][0];
                cacc[mt][nt][rr * 2 + 1] += bb[nt][1];
                ssq[mt][rr] = fmaf(cacc[mt][nt][rr * 2], cacc[mt][nt][rr * 2], ssq[mt][rr]);
                ssq[mt][rr] = fmaf(cacc[mt][nt][rr * 2 + 1], cacc[mt][nt][rr * 2 + 1], ssq[mt][rr]);
            }
#pragma unroll
    for (int mt = 0; mt < 2; mt++)
#pragma unroll
        for (int rr = 0; rr < 2; rr++) {
            ssq[mt][rr] += __shfl_xor_sync(0xffffffffu, ssq[mt][rr], 1);
            ssq[mt][rr] += __shfl_xor_sync(0xffffffffu, ssq[mt][rr], 2);
        }
    if (qp == 0) {
#pragma unroll
        for (int mt = 0; mt < 2; mt++)
#pragma unroll
            for (int rr = 0; rr < 2; rr++)
                Sred[mg * 32 + mt * 16 + rr * 8 + qr][ngg] = ssq[mt][rr];
    }
    __syncthreads();

    const float alpha = 2.0f / scale_ptr[0];

    if (sel < 2) {
        const float smul = (sel == 0) ? alpha : 1.0f;
        unsigned* T = ((sel == 0) ? g_Qp : g_Kp) + (size_t)h * 64 * NN;
#pragma unroll
        for (int mt = 0; mt < 2; mt++)
#pragma unroll
            for (int rr = 0; rr < 2; rr++) {
                int n = n0 + mg * 32 + mt * 16 + rr * 8 + qr;
#pragma unroll
                for (int nt = 0; nt < 8; nt++) {
                    int dp = ngg * 32 + nt * 4 + qp;
                    T[(size_t)dp * NN + n] =
                        pkbf2(smul * cacc[mt][nt][rr * 2], smul * cacc[mt][nt][rr * 2 + 1]);
                }
                if (qp == 0 && ngg == 0) {
                    int row = mg * 32 + mt * 16 + rr * 8 + qr;
                    float t = sqrtf(Sred[row][0] + Sred[row][1] + 1.0f);
                    if (sel == 0) g_tq[h * NN + n] = alpha * t;
                    else          g_tk[h * NN + n] = t;
                }
            }
    } else {
        // V: key-pair packing via shfl_down(4)  (row qr even pairs with qr+1)
#pragma unroll
        for (int mt = 0; mt < 2; mt++)
#pragma unroll
            for (int rr = 0; rr < 2; rr++) {
                int n = n0 + mg * 32 + mt * 16 + rr * 8 + qr;
                int row = mg * 32 + mt * 16 + rr * 8 + qr;
                float t = sqrtf(Sred[row][0] + Sred[row][1] + 1.0f);
                float tp = __shfl_down_sync(0xffffffffu, t, 4);
                unsigned* vdst = g_Vp + ((size_t)h * 2048 + (n >> 1)) * ND;
#pragma unroll
                for (int nt = 0; nt < 8; nt++) {
                    int col = ngg * 64 + nt * 8 + qp * 2;
                    float v0 = cacc[mt][nt][rr * 2];
                    float v1 = cacc[mt][nt][rr * 2 + 1];
                    float v0p = __shfl_down_sync(0xffffffffu, v0, 4);
                    float v1p = __shfl_down_sync(0xffffffffu, v1, 4);
                    if ((qr & 1) == 0) {
                        vdst[col]     = pkbf2(v0, v0p);
                        vdst[col + 1] = pkbf2(v1, v1p);
                    }
                }
                if (qp == 0 && ngg == 0 && (qr & 1) == 0)
                    g_VTp[h * 2048 + (n >> 1)] = pkbf2(t, tp);
            }
    }
}

// =====================================================================
// Kernel 2: flash attention via bf16 mma.sync (m16n8k16), 512 threads.
// Packed operands; fp32 rank-1 fixup; no online softmax.
// =====================================================================
#define MSTR 136
#define KSTR 72
#define VSTR 136
#define PSTR 36

#define OFF_QP   0                       // [64 dp][136]  u32
#define OFF_K0   8704
#define OFF_K1   (OFF_K0 + 4608)         // 13312
#define OFF_VP   (OFF_K1 + 4608)         // 17920  [32 np][136] u32
#define OFF_PP   (OFF_VP + 4352)         // 22272  [128 m][36] u32
#define OFF_TK0  (OFF_PP + 4608)         // 26880  (f32)
#define OFF_TK1  (OFF_TK0 + 64)          // 26944
#define OFF_LRED (OFF_TK1 + 64)          // 27008
#define OFF_LTOT (OFF_LRED + 512)        // 27520
#define ATTN_SMEM_WORDS (OFF_LTOT + 128) // 27648
#define ATTN_SMEM_BYTES (ATTN_SMEM_WORDS * 4)

__global__ __launch_bounds__(512, 1) void attn_kernel()
{
    extern __shared__ unsigned smu[];
    unsigned* Qp   = smu + OFF_QP;
    unsigned* Vp   = smu + OFF_VP;
    unsigned* Pp   = smu + OFF_PP;
    float*    Lred = (float*)(smu + OFF_LRED);
    float*    Ltot = (float*)(smu + OFF_LTOT);

    const int h    = blockIdx.y;
    const int m0   = blockIdx.x * 128;
    const int tid  = threadIdx.x;
    const int lane = tid & 31;
    const int wid  = tid >> 5;
    const int qp   = lane & 3;
    const int qr   = lane >> 2;
    const int mg   = wid & 3;
    const int ng   = wid >> 2;

    const unsigned* qsrc = g_Qp + (size_t)h * 64 * NN + m0;
    const unsigned* ksrc = g_Kp + (size_t)h * 64 * NN;

    float tqr[4];
#pragma unroll
    for (int i = 0; i < 4; i++)
        tqr[i] = g_tq[h * NN + m0 + mg * 32 + qr + 8 * i];

    // zero V pad cols 129..135 (written once; V loads never touch them)
    for (int i = tid; i < 32 * 7; i += 512)
        Vp[(i / 7) * VSTR + 129 + (i % 7)] = 0u;

    // prologue: Q tile + K(0) + tk(0)
    for (int idx = tid; idx < 64 * 32; idx += 512) {
        int dp = idx >> 5, c = idx & 31;
        cpa16(Qp + dp * MSTR + c * 4, qsrc + (size_t)dp * NN + c * 4);
    }
    for (int idx = tid; idx < 64 * 16; idx += 512) {
        int dp = idx >> 4, c = idx & 15;
        cpa16(smu + OFF_K0 + dp * KSTR + c * 4, ksrc + (size_t)dp * NN + c * 4);
    }
    if (tid < 16) cpa16(smu + OFF_TK0 + tid * 4, g_tk + h * NN + tid * 4);
    cpa_commit();

    float oc[2][4][4], ot[2][4], lacc[4];
#pragma unroll
    for (int mt = 0; mt < 2; mt++) {
#pragma unroll
        for (int j = 0; j < 4; j++)
#pragma unroll
            for (int r = 0; r < 4; r++) oc[mt][j][r] = 0.0f;
#pragma unroll
        for (int r = 0; r < 4; r++) ot[mt][r] = 0.0f;
    }
#pragma unroll
    for (int i = 0; i < 4; i++) lacc[i] = 0.0f;

    for (int c64 = 0; c64 < 64; c64++) {
        const int k0 = c64 * 64;
        unsigned* Kc  = smu + ((c64 & 1) ? OFF_K1 : OFF_K0);
        unsigned* Kn  = smu + ((c64 & 1) ? OFF_K0 : OFF_K1);
        float*    tkc = (float*)(smu + ((c64 & 1) ? OFF_TK1 : OFF_TK0));
        float*    tkn = (float*)(smu + ((c64 & 1) ? OFF_TK0 : OFF_TK1));

        __syncthreads();   // A: PV(c-1) done; Vp/Pp/Kn writable

        // V(c): 32 key-pairs x 128 d + v_t col
        {
            const unsigned* vsrc = g_Vp + ((size_t)h * 2048 + (k0 >> 1)) * ND;
            for (int idx = tid; idx < 1024; idx += 512) {
                int np = idx >> 5, c = idx & 31;
                cpa16(Vp + np * VSTR + c * 4, vsrc + (size_t)np * ND + c * 4);
            }
            if (tid < 32) cpa4(Vp + tid * VSTR + 128, g_VTp + h * 2048 + (k0 >> 1) + tid);
        }
        cpa_commit();

        if (c64 < 63) {
            const unsigned* kn = ksrc + k0 + 64;
            for (int idx = tid; idx < 64 * 16; idx += 512) {
                int dp = idx >> 4, c = idx & 15;
                cpa16(Kn + dp * KSTR + c * 4, kn + (size_t)dp * NN + c * 4);
            }
            if (tid < 16) cpa16(tkn + tid * 4, g_tk + h * NN + k0 + 64 + tid * 4);
            cpa_commit();
            cpa_wait<2>();
        } else {
            cpa_wait<1>();
        }
        __syncthreads();   // B: K(c)/tk(c) visible

        // ---- scores: 8 k16-steps ----
        float sc[2][2][4];
#pragma unroll
        for (int mt = 0; mt < 2; mt++)
#pragma unroll
            for (int nt = 0; nt < 2; nt++)
#pragma unroll
                for (int r = 0; r < 4; r++) sc[mt][nt][r] = 0.0f;

#pragma unroll
        for (int ks = 0; ks < 8; ks++) {
            const unsigned* qa = Qp + (ks * 8 + qp) * MSTR + mg * 32 + qr;
            unsigned a[2][4];
#pragma unroll
            for (int mt = 0; mt < 2; mt++) {
                a[mt][0] = qa[mt * 16];
                a[mt][1] = qa[mt * 16 + 8];
                a[mt][2] = qa[4 * MSTR + mt * 16];
                a[mt][3] = qa[4 * MSTR + mt * 16 + 8];
            }
            const unsigned* kb = Kc + (ks * 8 + qp) * KSTR + ng * 16 + qr;
#pragma unroll
            for (int nt = 0; nt < 2; nt++) {
                unsigned b0 = kb[nt * 8];
                unsigned b1 = kb[4 * KSTR + nt * 8];
                mma16(sc[0][nt], a[0][0], a[0][1], a[0][2], a[0][3], b0, b1);
                mma16(sc[1][nt], a[1][0], a[1][1], a[1][2], a[1][3], b0, b1);
            }
        }

        // ---- fixup + exp + stage packed P + l partials ----
#pragma unroll
        for (int mt = 0; mt < 2; mt++) {
            int prow = mg * 32 + mt * 16 + qr;
            int npcol = ng * 8 + qp;   // + nt*4
#pragma unroll
            for (int nt = 0; nt < 2; nt++) {
                int col = ng * 16 + nt * 8 + qp * 2;
                float t0 = tkc[col], t1 = tkc[col + 1];
                float p0 = __expf(sc[mt][nt][0] - tqr[mt * 2]     * t0);
                float p1 = __expf(sc[mt][nt][1] - tqr[mt * 2]     * t1);
                float p2 = __expf(sc[mt][nt][2] - tqr[mt * 2 + 1] * t0);
                float p3 = __expf(sc[mt][nt][3] - tqr[mt * 2 + 1] * t1);
                unsigned pk01 = pkbf2(p0, p1);
                unsigned pk23 = pkbf2(p2, p3);
                // l sums the ROUNDED values (keeps ave a convex combination)
                lacc[mt * 2] += __uint_as_float(pk01 << 16)
                              + __uint_as_float(pk01 & 0xffff0000u);
                lacc[mt * 2 + 1] += __uint_as_float(pk23 << 16)
                                  + __uint_as_float(pk23 & 0xffff0000u);
                Pp[prow * PSTR + npcol + nt * 4]       = pk01;
                Pp[(prow + 8) * PSTR + npcol + nt * 4] = pk23;
            }
        }

        if (c64 < 63) cpa_wait<1>(); else cpa_wait<0>();   // V(c) done
        __syncthreads();   // C: Pp + Vp visible

        // ---- PV: 4 k16-steps over 64 keys ----
#pragma unroll
        for (int ks = 0; ks < 4; ks++) {
            const unsigned* pa = Pp + (mg * 32 + qr) * PSTR + ks * 8 + qp;
            unsigned a[2][4];
#pragma unroll
            for (int mt = 0; mt < 2; mt++) {
                a[mt][0] = pa[mt * 16 * PSTR];
                a[mt][1] = pa[(mt * 16 + 8) * PSTR];
                a[mt][2] = pa[mt * 16 * PSTR + 4];
                a[mt][3] = pa[(mt * 16 + 8) * PSTR + 4];
            }
            const unsigned* vb = Vp + (ks * 8 + qp) * VSTR + qr;
#pragma unroll
            for (int j = 0; j < 4; j++) {
                int nb = (ng + 4 * j) * 8;
                unsigned b0 = vb[nb];
                unsigned b1 = vb[4 * VSTR + nb];
                mma16(oc[0][j], a[0][0], a[0][1], a[0][2], a[0][3], b0, b1);
                mma16(oc[1][j], a[1][0], a[1][1], a[1][2], a[1][3], b0, b1);
            }
            if (ng == 0) {
                unsigned b0 = vb[128];
                unsigned b1 = vb[4 * VSTR + 128];
                mma16(ot[0], a[0][0], a[0][1], a[0][2], a[0][3], b0, b1);
                mma16(ot[1], a[1][0], a[1][1], a[1][2], a[1][3], b0, b1);
            }
        }
    }

    // ---- epilogue ----
#pragma unroll
    for (int i = 0; i < 4; i++) {
        lacc[i] += __shfl_xor_sync(0xffffffffu, lacc[i], 1);
        lacc[i] += __shfl_xor_sync(0xffffffffu, lacc[i], 2);
    }
    if (qp == 0) {
#pragma unroll
        for (int i = 0; i < 4; i++)
            Lred[(mg * 32 + qr + 8 * i) * 4 + ng] = lacc[i];
    }
    __syncthreads();
    if (tid < 128) {
        const float* lr = Lred + tid * 4;
        Ltot[tid] = lr[0] + lr[1] + lr[2] + lr[3];
    }
    __syncthreads();

    float rl[4];
#pragma unroll
    for (int i = 0; i < 4; i++) rl[i] = 1.0f / Ltot[mg * 32 + qr + 8 * i];

#pragma unroll
    for (int mt = 0; mt < 2; mt++) {
#pragma unroll
        for (int rr = 0; rr < 2; rr++) {
            int row = m0 + mg * 32 + mt * 16 + qr + rr * 8;
            float rlv = rl[mt * 2 + rr];
            float* orow = g_OS + ((size_t)(h * NN + row)) * ND;
#pragma unroll
            for (int j = 0; j < 4; j++) {
                int d0 = (ng + 4 * j) * 8 + qp * 2;
                *(float2*)&orow[d0] =
                    make_float2(oc[mt][j][rr * 2] * rlv, oc[mt][j][rr * 2 + 1] * rlv);
            }
            if (ng == 0 && qp == 0)
                g_OT[h * NN + row] = ot[mt][rr * 2] * rlv;
        }
    }
}

// =====================================================================
// Kernel 3: per-head midpoint_norm + head mean + final norm
// =====================================================================
__global__ __launch_bounds__(256) void final_kernel(float* __restrict__ out)
{
    const int warp = threadIdx.x >> 5;
    const int lane = threadIdx.x & 31;
    const int n = blockIdx.x * 8 + warp;

    float as0 = 0.f, as1 = 0.f, as2 = 0.f, as3 = 0.f, at = 0.f;
#pragma unroll
    for (int h = 0; h < NH; h++) {
        float4 v = *(const float4*)&g_OS[((size_t)(h * NN + n)) * ND + lane * 4];
        float t = g_OT[h * NN + n];
        float ssn = v.x * v.x + v.y * v.y + v.z * v.z + v.w * v.w;
#pragma unroll
        for (int off = 16; off; off >>= 1)
            ssn += __shfl_xor_sync(0xffffffffu, ssn, off);
        float inner = ssn - t * t;
        float f = 1.0f / sqrtf(fmaxf(fabsf(inner), 1e-8f));
        as0 += v.x * f; as1 += v.y * f; as2 += v.z * f; as3 += v.w * f;
        at  += t * f;
    }
    const float inv = 1.0f / (float)NH;
    as0 *= inv; as1 *= inv; as2 *= inv; as3 *= inv; at *= inv;

    float q = as0 * as0 + as1 * as1 + as2 * as2 + as3 * as3;
#pragma unroll
    for (int off = 16; off; off >>= 1)
        q += __shfl_xor_sync(0xffffffffu, q, off);

    float inner = q - at * at;
    float f = 1.0f / sqrtf(fmaxf(fabsf(inner), 1e-8f));

    float* o = out + (size_t)n * 129;
    if (lane == 0) o[0] = at * f;
    o[1 + lane * 4 + 0] = as0 * f;
    o[1 + lane * 4 + 1] = as1 * f;
    o[1 + lane * 4 + 2] = as2 * f;
    o[1 + lane * 4 + 3] = as3 * f;
}

// =====================================================================
extern "C" void kernel_launch(void* const* d_in, const int* in_sizes, int n_in,
                              void* d_out, int out_size)
{
    const float* x     = (const float*)d_in[0];
    const float* Wq    = (const float*)d_in[1];
    const float* bq    = (const float*)d_in[2];
    const float* Wk    = (const float*)d_in[3];
    const float* bk    = (const float*)d_in[4];
    const float* Wv    = (const float*)d_in[5];
    const float* bv    = (const float*)d_in[6];
    const float* scale = (const float*)d_in[7];
    float* out = (float*)d_out;

    cudaFuncSetAttribute(proj_kernel,
                         cudaFuncAttributeMaxDynamicSharedMemorySize,
                         PROJ_SMEM_BYTES);
    cudaFuncSetAttribute(attn_kernel,
                         cudaFuncAttributeMaxDynamicSharedMemorySize,
                         ATTN_SMEM_BYTES);

    proj_kernel<<<dim3(NN / 128, NH * 3), 256, PROJ_SMEM_BYTES>>>(
        x, Wq, bq, Wk, bk, Wv, bv, scale);
    attn_kernel<<<dim3(NN / 128, NH), 512, ATTN_SMEM_BYTES>>>();
    final_kernel<<<NN / 8, 256>>>(out);
}

// round 12
// speedup vs baseline: 7.6988x; 1.1619x over previous
#include <cuda_runtime.h>
#include <math.h>

#define NH 12
#define NN 4096
#define ND 128
#define NIN 256

// ---- tf32 (proj) ----
__device__ __forceinline__ void mma8(float* c, unsigned a0, unsigned a1,
    unsigned a2, unsigned a3, unsigned b0, unsigned b1) {
    asm volatile("mma.sync.aligned.m16n8k8.row.col.f32.tf32.tf32.f32 "
        "{%0,%1,%2,%3}, {%4,%5,%6,%7}, {%8,%9}, {%0,%1,%2,%3};"
        : "+f"(c[0]), "+f"(c[1]), "+f"(c[2]), "+f"(c[3])
        : "r"(a0), "r"(a1), "r"(a2), "r"(a3), "r"(b0), "r"(b1));
}
// ---- bf16 (attn) ----
__device__ __forceinline__ void mma16(float* c, unsigned a0, unsigned a1,
    unsigned a2, unsigned a3, unsigned b0, unsigned b1) {
    asm volatile("mma.sync.aligned.m16n8k16.row.col.f32.bf16.bf16.f32 "
        "{%0,%1,%2,%3}, {%4,%5,%6,%7}, {%8,%9}, {%0,%1,%2,%3};"
        : "+f"(c[0]), "+f"(c[1]), "+f"(c[2]), "+f"(c[3])
        : "r"(a0), "r"(a1), "r"(a2), "r"(a3), "r"(b0), "r"(b1));
}
__device__ __forceinline__ unsigned pkbf2(float lo, float hi) {
    unsigned r;
    asm("{.reg .b16 l, h;\n\tcvt.rn.bf16.f32 l, %1;\n\tcvt.rn.bf16.f32 h, %2;\n\t"
        "mov.b32 %0, {l, h};}" : "=r"(r) : "f"(lo), "f"(hi));
    return r;
}
// ---- cp.async ----
__device__ __forceinline__ void cpa16(void* dst, const void* src) {
    unsigned d = (unsigned)__cvta_generic_to_shared(dst);
    asm volatile("cp.async.cg.shared.global [%0], [%1], 16;" :: "r"(d), "l"(src));
}
__device__ __forceinline__ void cpa4(void* dst, const void* src) {
    unsigned d = (unsigned)__cvta_generic_to_shared(dst);
    asm volatile("cp.async.ca.shared.global [%0], [%1], 4;" :: "r"(d), "l"(src));
}
__device__ __forceinline__ void cpa_commit() {
    asm volatile("cp.async.commit_group;" ::: "memory");
}
template<int N> __device__ __forceinline__ void cpa_wait() {
    asm volatile("cp.async.wait_group %0;" :: "n"(N) : "memory");
}

// ---------------- scratch (layouts identical to R8) ----------------
__device__ unsigned g_Qp[NH * 64 * NN];     // bf16x2 d-pair-packed, d-major (alpha*s_q)
__device__ unsigned g_Kp[NH * 64 * NN];     // s_k
__device__ unsigned g_Vp[NH * (NN / 2) * ND];  // key-pair-packed v_s
__device__ unsigned g_VTp[NH * (NN / 2)];      // packed (v_t[2i], v_t[2i+1])
__device__ float g_tq[NH * NN];             // alpha * t_q
__device__ float g_tk[NH * NN];             // t_k
__device__ float g_OS[NH * NN * ND];
__device__ float g_OT[NH * NN];

// =====================================================================
// Kernel 1: projections via tf32 mma (unchanged from R8)
// =====================================================================
#define PSTRX 36
#define PROJ_TILE (128 * PSTRX)
#define PROJ_SMEM_BYTES (4 * PROJ_TILE * 4)

__global__ __launch_bounds__(256, 1) void proj_kernel(
    const float* __restrict__ x,
    const float* __restrict__ Wq, const float* __restrict__ bq,
    const float* __restrict__ Wk, const float* __restrict__ bk,
    const float* __restrict__ Wv, const float* __restrict__ bv,
    const float* __restrict__ scale_ptr)
{
    extern __shared__ float psm[];
    __shared__ float Sred[128][2];

    const int by = blockIdx.y, h = by % NH, sel = by / NH;
    const float* W = (sel == 0) ? Wq : (sel == 1) ? Wk : Wv;
    const float* B = (sel == 0) ? bq : (sel == 1) ? bk : bv;
    const float* Wh = W + (size_t)h * ND * NIN;
    const int n0 = blockIdx.x * 128;
    const int tid = threadIdx.x, lane = tid & 31, wid = tid >> 5;
    const int qp = lane & 3, qr = lane >> 2, mg = wid & 3, ngg = wid >> 2;

    auto load_chunk = [&](int kb, int buf) {
        float* Xs = psm + buf * (2 * PROJ_TILE);
        float* Ws = Xs + PROJ_TILE;
        for (int idx = tid; idx < 128 * 32; idx += 256) {
            int m = idx >> 5, k = idx & 31;
            cpa4(Xs + m * PSTRX + k, x + (size_t)(n0 + m) * 257 + 1 + kb + k);
        }
        for (int idx = tid; idx < 128 * 8; idx += 256) {
            int o = idx >> 3, kq = idx & 7;
            cpa16(Ws + o * PSTRX + kq * 4, Wh + (size_t)o * NIN + kb + kq * 4);
        }
    };

    float cacc[2][8][4];
#pragma unroll
    for (int mt = 0; mt < 2; mt++)
#pragma unroll
        for (int nt = 0; nt < 8; nt++)
#pragma unroll
            for (int r = 0; r < 4; r++) cacc[mt][nt][r] = 0.0f;

    load_chunk(0, 0);
    cpa_commit();
    for (int c = 0; c < 8; c++) {
        if (c < 7) { load_chunk((c + 1) * 32, (c + 1) & 1); cpa_commit(); cpa_wait<1>(); }
        else cpa_wait<0>();
        __syncthreads();
        const float* Xc = psm + (c & 1) * (2 * PROJ_TILE);
        const float* Wc = Xc + PROJ_TILE;
#pragma unroll
        for (int ks = 0; ks < 4; ks++) {
            unsigned a[2][4];
            const float* qa = Xc + (mg * 32 + qr) * PSTRX + ks * 8 + qp;
#pragma unroll
            for (int mt = 0; mt < 2; mt++) {
                const float* q2 = qa + mt * 16 * PSTRX;
                a[mt][0] = __float_as_uint(q2[0]);
                a[mt][1] = __float_as_uint(q2[8 * PSTRX]);
                a[mt][2] = __float_as_uint(q2[4]);
                a[mt][3] = __float_as_uint(q2[8 * PSTRX + 4]);
            }
#pragma unroll
            for (int nt = 0; nt < 8; nt++) {
                const float* kb2 = Wc + (ngg * 64 + nt * 8 + qr) * PSTRX + ks * 8 + qp;
                unsigned b0 = __float_as_uint(kb2[0]);
                unsigned b1 = __float_as_uint(kb2[4]);
                mma8(cacc[0][nt], a[0][0], a[0][1], a[0][2], a[0][3], b0, b1);
                mma8(cacc[1][nt], a[1][0], a[1][1], a[1][2], a[1][3], b0, b1);
            }
        }
        __syncthreads();
    }

    float bb[8][2];
#pragma unroll
    for (int nt = 0; nt < 8; nt++) {
        int col = ngg * 64 + nt * 8 + qp * 2;
        bb[nt][0] = B[h * ND + col];
        bb[nt][1] = B[h * ND + col + 1];
    }
    float ssq[2][2] = {{0.f, 0.f}, {0.f, 0.f}};
#pragma unroll
    for (int mt = 0; mt < 2; mt++)
#pragma unroll
        for (int nt = 0; nt < 8; nt++)
#pragma unroll
            for (int rr = 0; rr < 2; rr++) {
                cacc[mt][nt][rr * 2] += bb[nt][0];
                cacc[mt][nt][rr * 2 + 1] += bb[nt][1];
                ssq[mt][rr] = fmaf(cacc[mt][nt][rr * 2], cacc[mt][nt][rr * 2], ssq[mt][rr]);
                ssq[mt][rr] = fmaf(cacc[mt][nt][rr * 2 + 1], cacc[mt][nt][rr * 2 + 1], ssq[mt][rr]);
            }
#pragma unroll
    for (int mt = 0; mt < 2; mt++)
#pragma unroll
        for (int rr = 0; rr < 2; rr++) {
            ssq[mt][rr] += __shfl_xor_sync(0xffffffffu, ssq[mt][rr], 1);
            ssq[mt][rr] += __shfl_xor_sync(0xffffffffu, ssq[mt][rr], 2);
        }
    if (qp == 0) {
#pragma unroll
        for (int mt = 0; mt < 2; mt++)
#pragma unroll
            for (int rr = 0; rr < 2; rr++)
                Sred[mg * 32 + mt * 16 + rr * 8 + qr][ngg] = ssq[mt][rr];
    }
    __syncthreads();

    const float alpha = 2.0f / scale_ptr[0];

    if (sel < 2) {
        const float smul = (sel == 0) ? alpha : 1.0f;
        unsigned* T = ((sel == 0) ? g_Qp : g_Kp) + (size_t)h * 64 * NN;
#pragma unroll
        for (int mt = 0; mt < 2; mt++)
#pragma unroll
            for (int rr = 0; rr < 2; rr++) {
                int n = n0 + mg * 32 + mt * 16 + rr * 8 + qr;
#pragma unroll
                for (int nt = 0; nt < 8; nt++) {
                    int dp = ngg * 32 + nt * 4 + qp;
                    T[(size_t)dp * NN + n] =
                        pkbf2(smul * cacc[mt][nt][rr * 2], smul * cacc[mt][nt][rr * 2 + 1]);
                }
                if (qp == 0 && ngg == 0) {
                    int row = mg * 32 + mt * 16 + rr * 8 + qr;
                    float t = sqrtf(Sred[row][0] + Sred[row][1] + 1.0f);
                    if (sel == 0) g_tq[h * NN + n] = alpha * t;
                    else          g_tk[h * NN + n] = t;
                }
            }
    } else {
#pragma unroll
        for (int mt = 0; mt < 2; mt++)
#pragma unroll
            for (int rr = 0; rr < 2; rr++) {
                int n = n0 + mg * 32 + mt * 16 + rr * 8 + qr;
                int row = mg * 32 + mt * 16 + rr * 8 + qr;
                float t = sqrtf(Sred[row][0] + Sred[row][1] + 1.0f);
                float tp = __shfl_down_sync(0xffffffffu, t, 4);
                unsigned* vdst = g_Vp + ((size_t)h * 2048 + (n >> 1)) * ND;
#pragma unroll
                for (int nt = 0; nt < 8; nt++) {
                    int col = ngg * 64 + nt * 8 + qp * 2;
                    float v0 = cacc[mt][nt][rr * 2];
                    float v1 = cacc[mt][nt][rr * 2 + 1];
                    float v0p = __shfl_down_sync(0xffffffffu, v0, 4);
                    float v1p = __shfl_down_sync(0xffffffffu, v1, 4);
                    if ((qr & 1) == 0) {
                        vdst[col]     = pkbf2(v0, v0p);
                        vdst[col + 1] = pkbf2(v1, v1p);
                    }
                }
                if (qp == 0 && ngg == 0 && (qr & 1) == 0)
                    g_VTp[h * 2048 + (n >> 1)] = pkbf2(t, tp);
            }
    }
}

// =====================================================================
// Kernel 2: flash attention, bf16 mma.sync, 256 threads, Q in registers.
// Warp grids: score mg4 x ng2 (32 rows x 32 keys), PV mg4 x ng2 over d.
// =====================================================================
#define KSTR 72
#define VSTR 136
#define PSTR 36

#define OFF_K0   0
#define OFF_K1   4608
#define OFF_VP   9216
#define OFF_PP   13568
#define OFF_TK0  18176
#define OFF_TK1  18240
#define OFF_LRED 18304                       // [128][2]
#define ATTN_SMEM_WORDS (OFF_LRED + 256)     // 18560
#define ATTN_SMEM_BYTES (ATTN_SMEM_WORDS * 4)

__global__ __launch_bounds__(256, 1) void attn_kernel()
{
    extern __shared__ unsigned smu[];
    unsigned* Vp = smu + OFF_VP;
    unsigned* Pp = smu + OFF_PP;
    float* Lred = (float*)(smu + OFF_LRED);

    const int h = blockIdx.y, m0 = blockIdx.x * 128;
    const int tid = threadIdx.x, lane = tid & 31, wid = tid >> 5;
    const int qp = lane & 3, qr = lane >> 2;
    const int mg = wid & 3, ng = wid >> 2;   // ng in {0,1}

    const unsigned* ksrc = g_Kp + (size_t)h * 64 * NN;

    float tqr[4];
#pragma unroll
    for (int i = 0; i < 4; i++)
        tqr[i] = g_tq[h * NN + m0 + mg * 32 + qr + 8 * i];

    // Q A-fragments: load ONCE into registers (reused for all 64 chunks)
    unsigned qf[2][8][4];
    {
        const unsigned* qg = g_Qp + (size_t)h * 64 * NN + m0 + mg * 32;
#pragma unroll
        for (int ks = 0; ks < 8; ks++)
#pragma unroll
            for (int mt = 0; mt < 2; mt++) {
                qf[mt][ks][0] = qg[(size_t)(ks * 8 + qp) * NN + mt * 16 + qr];
                qf[mt][ks][1] = qg[(size_t)(ks * 8 + qp) * NN + mt * 16 + qr + 8];
                qf[mt][ks][2] = qg[(size_t)(ks * 8 + 4 + qp) * NN + mt * 16 + qr];
                qf[mt][ks][3] = qg[(size_t)(ks * 8 + 4 + qp) * NN + mt * 16 + qr + 8];
            }
    }

    // zero V pad cols 129..135
    for (int i = tid; i < 32 * 7; i += 256)
        Vp[(i / 7) * VSTR + 129 + (i % 7)] = 0u;

    // prologue: K(0) + tk(0)
    for (int idx = tid; idx < 64 * 16; idx += 256) {
        int dp = idx >> 4, c = idx & 15;
        cpa16(smu + OFF_K0 + dp * KSTR + c * 4, ksrc + (size_t)dp * NN + c * 4);
    }
    if (tid < 16) cpa16(smu + OFF_TK0 + tid * 4, g_tk + h * NN + tid * 4);
    cpa_commit();

    float oc[2][8][4], ot[2][4], lacc[4];
#pragma unroll
    for (int mt = 0; mt < 2; mt++) {
#pragma unroll
        for (int j = 0; j < 8; j++)
#pragma unroll
            for (int r = 0; r < 4; r++) oc[mt][j][r] = 0.0f;
#pragma unroll
        for (int r = 0; r < 4; r++) ot[mt][r] = 0.0f;
    }
#pragma unroll
    for (int i = 0; i < 4; i++) lacc[i] = 0.0f;

    for (int c64 = 0; c64 < 64; c64++) {
        const int k0 = c64 * 64;
        unsigned* Kc = smu + ((c64 & 1) ? OFF_K1 : OFF_K0);
        unsigned* Kn = smu + ((c64 & 1) ? OFF_K0 : OFF_K1);
        float* tkc = (float*)(smu + ((c64 & 1) ? OFF_TK1 : OFF_TK0));
        float* tkn = (float*)(smu + ((c64 & 1) ? OFF_TK0 : OFF_TK1));

        __syncthreads();   // A: PV(c-1) done; Vp/Pp/Kn writable

        // V(c)
        {
            const unsigned* vsrc = g_Vp + ((size_t)h * 2048 + (k0 >> 1)) * ND;
            for (int idx = tid; idx < 1024; idx += 256) {
                int np = idx >> 5, c = idx & 31;
                cpa16(Vp + np * VSTR + c * 4, vsrc + (size_t)np * ND + c * 4);
            }
            if (tid < 32) cpa4(Vp + tid * VSTR + 128, g_VTp + h * 2048 + (k0 >> 1) + tid);
        }
        cpa_commit();

        if (c64 < 63) {
            const unsigned* kn = ksrc + k0 + 64;
            for (int idx = tid; idx < 64 * 16; idx += 256) {
                int dp = idx >> 4, c = idx & 15;
                cpa16(Kn + dp * KSTR + c * 4, kn + (size_t)dp * NN + c * 4);
            }
            if (tid < 16) cpa16(tkn + tid * 4, g_tk + h * NN + k0 + 64 + tid * 4);
            cpa_commit();
            cpa_wait<2>();
        } else {
            cpa_wait<1>();
        }
        __syncthreads();   // B: K(c)/tk(c) visible

        // ---- scores: 32 rows x 32 keys, Q from registers ----
        float sc[2][4][4];
#pragma unroll
        for (int mt = 0; mt < 2; mt++)
#pragma unroll
            for (int nt = 0; nt < 4; nt++)
#pragma unroll
                for (int r = 0; r < 4; r++) sc[mt][nt][r] = 0.0f;

#pragma unroll
        for (int ks = 0; ks < 8; ks++) {
            const unsigned* kb = Kc + (ks * 8 + qp) * KSTR + ng * 32 + qr;
#pragma unroll
            for (int nt = 0; nt < 4; nt++) {
                unsigned b0 = kb[nt * 8];
                unsigned b1 = kb[4 * KSTR + nt * 8];
                mma16(sc[0][nt], qf[0][ks][0], qf[0][ks][1], qf[0][ks][2], qf[0][ks][3], b0, b1);
                mma16(sc[1][nt], qf[1][ks][0], qf[1][ks][1], qf[1][ks][2], qf[1][ks][3], b0, b1);
            }
        }

        // ---- fixup + exp + stage packed P + l partials ----
#pragma unroll
        for (int mt = 0; mt < 2; mt++) {
            int prow = mg * 32 + mt * 16 + qr;
#pragma unroll
            for (int nt = 0; nt < 4; nt++) {
                int col = ng * 32 + nt * 8 + qp * 2;
                float t0 = tkc[col], t1 = tkc[col + 1];
                float p0 = __expf(sc[mt][nt][0] - tqr[mt * 2] * t0);
                float p1 = __expf(sc[mt][nt][1] - tqr[mt * 2] * t1);
                float p2 = __expf(sc[mt][nt][2] - tqr[mt * 2 + 1] * t0);
                float p3 = __expf(sc[mt][nt][3] - tqr[mt * 2 + 1] * t1);
                unsigned pk01 = pkbf2(p0, p1);
                unsigned pk23 = pkbf2(p2, p3);
                lacc[mt * 2] += __uint_as_float(pk01 << 16)
                              + __uint_as_float(pk01 & 0xffff0000u);
                lacc[mt * 2 + 1] += __uint_as_float(pk23 << 16)
                                  + __uint_as_float(pk23 & 0xffff0000u);
                int kp = ng * 16 + nt * 4 + qp;
                Pp[prow * PSTR + kp]       = pk01;
                Pp[(prow + 8) * PSTR + kp] = pk23;
            }
        }

        if (c64 < 63) cpa_wait<1>(); else cpa_wait<0>();   // V(c) done
        __syncthreads();   // C: Pp + Vp visible

        // ---- PV: 32 rows x 64 d-cols per warp (ng halves d) ----
#pragma unroll
        for (int ks = 0; ks < 4; ks++) {
            const unsigned* pa = Pp + (mg * 32 + qr) * PSTR + ks * 8 + qp;
            unsigned a[2][4];
#pragma unroll
            for (int mt = 0; mt < 2; mt++) {
                a[mt][0] = pa[mt * 16 * PSTR];
                a[mt][1] = pa[(mt * 16 + 8) * PSTR];
                a[mt][2] = pa[mt * 16 * PSTR + 4];
                a[mt][3] = pa[(mt * 16 + 8) * PSTR + 4];
            }
            const unsigned* vb = Vp + (ks * 8 + qp) * VSTR + qr;
#pragma unroll
            for (int j = 0; j < 8; j++) {
                int nb = (ng * 8 + j) * 8;
                unsigned b0 = vb[nb];
                unsigned b1 = vb[4 * VSTR + nb];
                mma16(oc[0][j], a[0][0], a[0][1], a[0][2], a[0][3], b0, b1);
                mma16(oc[1][j], a[1][0], a[1][1], a[1][2], a[1][3], b0, b1);
            }
            if (ng == 0) {
                unsigned b0 = vb[128];
                unsigned b1 = vb[4 * VSTR + 128];
                mma16(ot[0], a[0][0], a[0][1], a[0][2], a[0][3], b0, b1);
                mma16(ot[1], a[1][0], a[1][1], a[1][2], a[1][3], b0, b1);
            }
        }
    }

    // ---- epilogue: l reduction across qp then across the 2 ng groups ----
#pragma unroll
    for (int i = 0; i < 4; i++) {
        lacc[i] += __shfl_xor_sync(0xffffffffu, lacc[i], 1);
        lacc[i] += __shfl_xor_sync(0xffffffffu, lacc[i], 2);
    }
    if (qp == 0) {
#pragma unroll
        for (int i = 0; i < 4; i++)
            Lred[(mg * 32 + qr + 8 * i) * 2 + ng] = lacc[i];
    }
    __syncthreads();

#pragma unroll
    for (int mt = 0; mt < 2; mt++) {
#pragma unroll
        for (int rr = 0; rr < 2; rr++) {
            int rloc = mg * 32 + mt * 16 + rr * 8 + qr;
            int row = m0 + rloc;
            float rlv = 1.0f / (Lred[rloc * 2] + Lred[rloc * 2 + 1]);
            float* orow = g_OS + ((size_t)(h * NN + row)) * ND + ng * 64;
#pragma unroll
            for (int j = 0; j < 8; j++) {
                int d0 = j * 8 + qp * 2;
                *(float2*)&orow[d0] =
                    make_float2(oc[mt][j][rr * 2] * rlv, oc[mt][j][rr * 2 + 1] * rlv);
            }
            if (ng == 0 && qp == 0)
                g_OT[h * NN + row] = ot[mt][rr * 2] * rlv;
        }
    }
}

// =====================================================================
// Kernel 3: per-head midpoint_norm + head mean + final norm (unchanged)
// =====================================================================
__global__ __launch_bounds__(256) void final_kernel(float* __restrict__ out)
{
    const int warp = threadIdx.x >> 5, lane = threadIdx.x & 31;
    const int n = blockIdx.x * 8 + warp;

    float as0 = 0.f, as1 = 0.f, as2 = 0.f, as3 = 0.f, at = 0.f;
#pragma unroll
    for (int h = 0; h < NH; h++) {
        float4 v = *(const float4*)&g_OS[((size_t)(h * NN + n)) * ND + lane * 4];
        float t = g_OT[h * NN + n];
        float ssn = v.x * v.x + v.y * v.y + v.z * v.z + v.w * v.w;
#pragma unroll
        for (int off = 16; off; off >>= 1)
            ssn += __shfl_xor_sync(0xffffffffu, ssn, off);
        float inner = ssn - t * t;
        float f = 1.0f / sqrtf(fmaxf(fabsf(inner), 1e-8f));
        as0 += v.x * f; as1 += v.y * f; as2 += v.z * f; as3 += v.w * f;
        at += t * f;
    }
    const float inv = 1.0f / (float)NH;
    as0 *= inv; as1 *= inv; as2 *= inv; as3 *= inv; at *= inv;

    float q = as0 * as0 + as1 * as1 + as2 * as2 + as3 * as3;
#pragma unroll
    for (int off = 16; off; off >>= 1)
        q += __shfl_xor_sync(0xffffffffu, q, off);

    float inner = q - at * at;
    float f = 1.0f / sqrtf(fmaxf(fabsf(inner), 1e-8f));

    float* o = out + (size_t)n * 129;
    if (lane == 0) o[0] = at * f;
    o[1 + lane * 4 + 0] = as0 * f;
    o[1 + lane * 4 + 1] = as1 * f;
    o[1 + lane * 4 + 2] = as2 * f;
    o[1 + lane * 4 + 3] = as3 * f;
}

// =====================================================================
extern "C" void kernel_launch(void* const* d_in, const int* in_sizes, int n_in,
                              void* d_out, int out_size)
{
    const float* x     = (const float*)d_in[0];
    const float* Wq    = (const float*)d_in[1];
    const float* bq    = (const float*)d_in[2];
    const float* Wk    = (const float*)d_in[3];
    const float* bk    = (const float*)d_in[4];
    const float* Wv    = (const float*)d_in[5];
    const float* bv    = (const float*)d_in[6];
    const float* scale = (const float*)d_in[7];
    float* out = (float*)d_out;

    cudaFuncSetAttribute(proj_kernel,
                         cudaFuncAttributeMaxDynamicSharedMemorySize, PROJ_SMEM_BYTES);
    cudaFuncSetAttribute(attn_kernel,
                         cudaFuncAttributeMaxDynamicSharedMemorySize, ATTN_SMEM_BYTES);

    proj_kernel<<<dim3(NN / 128, NH * 3), 256, PROJ_SMEM_BYTES>>>(
        x, Wq, bq, Wk, bk, Wv, bv, scale);
    attn_kernel<<<dim3(NN / 128, NH), 256, ATTN_SMEM_BYTES>>>();
    final_kernel<<<NN / 8, 256>>>(out);
}

// round 13
// speedup vs baseline: 7.8350x; 1.0177x over previous
#include <cuda_runtime.h>
#include <math.h>

#define NH 12
#define NN 4096
#define ND 128
#define NIN 256

// ---- tf32 (proj) ----
__device__ __forceinline__ void mma8(float* c, unsigned a0, unsigned a1,
    unsigned a2, unsigned a3, unsigned b0, unsigned b1) {
    asm volatile("mma.sync.aligned.m16n8k8.row.col.f32.tf32.tf32.f32 "
        "{%0,%1,%2,%3}, {%4,%5,%6,%7}, {%8,%9}, {%0,%1,%2,%3};"
        : "+f"(c[0]), "+f"(c[1]), "+f"(c[2]), "+f"(c[3])
        : "r"(a0), "r"(a1), "r"(a2), "r"(a3), "r"(b0), "r"(b1));
}
// ---- bf16 (attn) ----
__device__ __forceinline__ void mma16(float* c, unsigned a0, unsigned a1,
    unsigned a2, unsigned a3, unsigned b0, unsigned b1) {
    asm volatile("mma.sync.aligned.m16n8k16.row.col.f32.bf16.bf16.f32 "
        "{%0,%1,%2,%3}, {%4,%5,%6,%7}, {%8,%9}, {%0,%1,%2,%3};"
        : "+f"(c[0]), "+f"(c[1]), "+f"(c[2]), "+f"(c[3])
        : "r"(a0), "r"(a1), "r"(a2), "r"(a3), "r"(b0), "r"(b1));
}
__device__ __forceinline__ unsigned pkbf2(float lo, float hi) {
    unsigned r;
    asm("{.reg .b16 l, h;\n\tcvt.rn.bf16.f32 l, %1;\n\tcvt.rn.bf16.f32 h, %2;\n\t"
        "mov.b32 %0, {l, h};}" : "=r"(r) : "f"(lo), "f"(hi));
    return r;
}
// ---- cp.async ----
__device__ __forceinline__ void cpa16(void* dst, const void* src) {
    unsigned d = (unsigned)__cvta_generic_to_shared(dst);
    asm volatile("cp.async.cg.shared.global [%0], [%1], 16;" :: "r"(d), "l"(src));
}
__device__ __forceinline__ void cpa4(void* dst, const void* src) {
    unsigned d = (unsigned)__cvta_generic_to_shared(dst);
    asm volatile("cp.async.ca.shared.global [%0], [%1], 4;" :: "r"(d), "l"(src));
}
__device__ __forceinline__ void cpa_commit() {
    asm volatile("cp.async.commit_group;" ::: "memory");
}
template<int N> __device__ __forceinline__ void cpa_wait() {
    asm volatile("cp.async.wait_group %0;" :: "n"(N) : "memory");
}

#define LOG2E 1.4426950408889634f

// ---------------- scratch ----------------
__device__ unsigned g_Qp[NH * 64 * NN];     // bf16x2 d-pair-packed, d-major (alpha*log2e*s_q)
__device__ unsigned g_Kp[NH * 64 * NN];     // s_k
__device__ unsigned g_Vp[NH * (NN / 2) * ND];  // key-pair-packed v_s
__device__ unsigned g_VTp[NH * (NN / 2)];      // packed (v_t[2i], v_t[2i+1])
__device__ float g_tq[NH * NN];             // alpha*log2e * t_q
__device__ float g_tk[NH * NN];             // t_k
__device__ float g_OS[NH * NN * ND];        // per-head NORMALIZED midpoint (s)
__device__ float g_OT[NH * NN];             // per-head NORMALIZED midpoint (t)

// =====================================================================
// Kernel 1: projections via tf32 mma (R8 core; log2e folded into Q/tq)
// =====================================================================
#define PSTRX 36
#define PROJ_TILE (128 * PSTRX)
#define PROJ_SMEM_BYTES (4 * PROJ_TILE * 4)

__global__ __launch_bounds__(256, 1) void proj_kernel(
    const float* __restrict__ x,
    const float* __restrict__ Wq, const float* __restrict__ bq,
    const float* __restrict__ Wk, const float* __restrict__ bk,
    const float* __restrict__ Wv, const float* __restrict__ bv,
    const float* __restrict__ scale_ptr)
{
    extern __shared__ float psm[];
    __shared__ float Sred[128][2];

    const int by = blockIdx.y, h = by % NH, sel = by / NH;
    const float* W = (sel == 0) ? Wq : (sel == 1) ? Wk : Wv;
    const float* B = (sel == 0) ? bq : (sel == 1) ? bk : bv;
    const float* Wh = W + (size_t)h * ND * NIN;
    const int n0 = blockIdx.x * 128;
    const int tid = threadIdx.x, lane = tid & 31, wid = tid >> 5;
    const int qp = lane & 3, qr = lane >> 2, mg = wid & 3, ngg = wid >> 2;

    auto load_chunk = [&](int kb, int buf) {
        float* Xs = psm + buf * (2 * PROJ_TILE);
        float* Ws = Xs + PROJ_TILE;
        for (int idx = tid; idx < 128 * 32; idx += 256) {
            int m = idx >> 5, k = idx & 31;
            cpa4(Xs + m * PSTRX + k, x + (size_t)(n0 + m) * 257 + 1 + kb + k);
        }
        for (int idx = tid; idx < 128 * 8; idx += 256) {
            int o = idx >> 3, kq = idx & 7;
            cpa16(Ws + o * PSTRX + kq * 4, Wh + (size_t)o * NIN + kb + kq * 4);
        }
    };

    float cacc[2][8][4];
#pragma unroll
    for (int mt = 0; mt < 2; mt++)
#pragma unroll
        for (int nt = 0; nt < 8; nt++)
#pragma unroll
            for (int r = 0; r < 4; r++) cacc[mt][nt][r] = 0.0f;

    load_chunk(0, 0);
    cpa_commit();
    for (int c = 0; c < 8; c++) {
        if (c < 7) { load_chunk((c + 1) * 32, (c + 1) & 1); cpa_commit(); cpa_wait<1>(); }
        else cpa_wait<0>();
        __syncthreads();
        const float* Xc = psm + (c & 1) * (2 * PROJ_TILE);
        const float* Wc = Xc + PROJ_TILE;
#pragma unroll
        for (int ks = 0; ks < 4; ks++) {
            unsigned a[2][4];
            const float* qa = Xc + (mg * 32 + qr) * PSTRX + ks * 8 + qp;
#pragma unroll
            for (int mt = 0; mt < 2; mt++) {
                const float* q2 = qa + mt * 16 * PSTRX;
                a[mt][0] = __float_as_uint(q2[0]);
                a[mt][1] = __float_as_uint(q2[8 * PSTRX]);
                a[mt][2] = __float_as_uint(q2[4]);
                a[mt][3] = __float_as_uint(q2[8 * PSTRX + 4]);
            }
#pragma unroll
            for (int nt = 0; nt < 8; nt++) {
                const float* kb2 = Wc + (ngg * 64 + nt * 8 + qr) * PSTRX + ks * 8 + qp;
                unsigned b0 = __float_as_uint(kb2[0]);
                unsigned b1 = __float_as_uint(kb2[4]);
                mma8(cacc[0][nt], a[0][0], a[0][1], a[0][2], a[0][3], b0, b1);
                mma8(cacc[1][nt], a[1][0], a[1][1], a[1][2], a[1][3], b0, b1);
            }
        }
        __syncthreads();
    }

    float bb[8][2];
#pragma unroll
    for (int nt = 0; nt < 8; nt++) {
        int col = ngg * 64 + nt * 8 + qp * 2;
        bb[nt][0] = B[h * ND + col];
        bb[nt][1] = B[h * ND + col + 1];
    }
    float ssq[2][2] = {{0.f, 0.f}, {0.f, 0.f}};
#pragma unroll
    for (int mt = 0; mt < 2; mt++)
#pragma unroll
        for (int nt = 0; nt < 8; nt++)
#pragma unroll
            for (int rr = 0; rr < 2; rr++) {
                cacc[mt][nt][rr * 2] += bb[nt][0];
                cacc[mt][nt][rr * 2 + 1] += bb[nt][1];
                ssq[mt][rr] = fmaf(cacc[mt][nt][rr * 2], cacc[mt][nt][rr * 2], ssq[mt][rr]);
                ssq[mt][rr] = fmaf(cacc[mt][nt][rr * 2 + 1], cacc[mt][nt][rr * 2 + 1], ssq[mt][rr]);
            }
#pragma unroll
    for (int mt = 0; mt < 2; mt++)
#pragma unroll
        for (int rr = 0; rr < 2; rr++) {
            ssq[mt][rr] += __shfl_xor_sync(0xffffffffu, ssq[mt][rr], 1);
            ssq[mt][rr] += __shfl_xor_sync(0xffffffffu, ssq[mt][rr], 2);
        }
    if (qp == 0) {
#pragma unroll
        for (int mt = 0; mt < 2; mt++)
#pragma unroll
            for (int rr = 0; rr < 2; rr++)
                Sred[mg * 32 + mt * 16 + rr * 8 + qr][ngg] = ssq[mt][rr];
    }
    __syncthreads();

    const float alpha = 2.0f / scale_ptr[0];

    if (sel < 2) {
        const float smul = (sel == 0) ? alpha * LOG2E : 1.0f;
        unsigned* T = ((sel == 0) ? g_Qp : g_Kp) + (size_t)h * 64 * NN;
#pragma unroll
        for (int mt = 0; mt < 2; mt++)
#pragma unroll
            for (int rr = 0; rr < 2; rr++) {
                int n = n0 + mg * 32 + mt * 16 + rr * 8 + qr;
#pragma unroll
                for (int nt = 0; nt < 8; nt++) {
                    int dp = ngg * 32 + nt * 4 + qp;
                    T[(size_t)dp * NN + n] =
                        pkbf2(smul * cacc[mt][nt][rr * 2], smul * cacc[mt][nt][rr * 2 + 1]);
                }
                if (qp == 0 && ngg == 0) {
                    int row = mg * 32 + mt * 16 + rr * 8 + qr;
                    float t = sqrtf(Sred[row][0] + Sred[row][1] + 1.0f);
                    if (sel == 0) g_tq[h * NN + n] = alpha * LOG2E * t;
                    else          g_tk[h * NN + n] = t;
                }
            }
    } else {
#pragma unroll
        for (int mt = 0; mt < 2; mt++)
#pragma unroll
            for (int rr = 0; rr < 2; rr++) {
                int n = n0 + mg * 32 + mt * 16 + rr * 8 + qr;
                int row = mg * 32 + mt * 16 + rr * 8 + qr;
                float t = sqrtf(Sred[row][0] + Sred[row][1] + 1.0f);
                float tp = __shfl_down_sync(0xffffffffu, t, 4);
                unsigned* vdst = g_Vp + ((size_t)h * 2048 + (n >> 1)) * ND;
#pragma unroll
                for (int nt = 0; nt < 8; nt++) {
                    int col = ngg * 64 + nt * 8 + qp * 2;
                    float v0 = cacc[mt][nt][rr * 2];
                    float v1 = cacc[mt][nt][rr * 2 + 1];
                    float v0p = __shfl_down_sync(0xffffffffu, v0, 4);
                    float v1p = __shfl_down_sync(0xffffffffu, v1, 4);
                    if ((qr & 1) == 0) {
                        vdst[col]     = pkbf2(v0, v0p);
                        vdst[col + 1] = pkbf2(v1, v1p);
                    }
                }
                if (qp == 0 && ngg == 0 && (qr & 1) == 0)
                    g_VTp[h * 2048 + (n >> 1)] = pkbf2(t, tp);
            }
    }
}

// =====================================================================
// Kernel 2: flash attention, bf16 mma.sync, 256 threads.
// Warp = 16 rows x ALL 64 keys; P stays in registers (C-frag == A-frag);
// per-head midpoint_norm fused into epilogue.
// =====================================================================
#define KSTR 72
#define VSTR 136

#define OFF_K0   0
#define OFF_K1   4608
#define OFF_VP   9216
#define OFF_TK0  13568
#define OFF_TK1  13632
#define ATTN_SMEM_WORDS 13696
#define ATTN_SMEM_BYTES (ATTN_SMEM_WORDS * 4)

__global__ __launch_bounds__(256, 1) void attn_kernel()
{
    extern __shared__ unsigned smu[];
    unsigned* Vp = smu + OFF_VP;

    const int h = blockIdx.y, m0 = blockIdx.x * 128;
    const int tid = threadIdx.x, lane = tid & 31, wid = tid >> 5;
    const int qp = lane & 3, qr = lane >> 2;
    const int rowb = wid * 16;           // warp owns rows rowb..rowb+15

    const unsigned* ksrc = g_Kp + (size_t)h * 64 * NN;

    const float tqr0 = g_tq[h * NN + m0 + rowb + qr];
    const float tqr1 = g_tq[h * NN + m0 + rowb + qr + 8];

    // Q A-fragments: rows rowb..rowb+15, loaded once (32 regs)
    unsigned qf[8][4];
    {
        const unsigned* qg = g_Qp + (size_t)h * 64 * NN + m0 + rowb;
#pragma unroll
        for (int ks = 0; ks < 8; ks++) {
            qf[ks][0] = qg[(size_t)(ks * 8 + qp) * NN + qr];
            qf[ks][1] = qg[(size_t)(ks * 8 + qp) * NN + qr + 8];
            qf[ks][2] = qg[(size_t)(ks * 8 + 4 + qp) * NN + qr];
            qf[ks][3] = qg[(size_t)(ks * 8 + 4 + qp) * NN + qr + 8];
        }
    }

    // zero V pad cols 129..135
    for (int i = tid; i < 32 * 7; i += 256)
        Vp[(i / 7) * VSTR + 129 + (i % 7)] = 0u;

    // prologue: K(0) + tk(0)
    for (int idx = tid; idx < 64 * 16; idx += 256) {
        int dp = idx >> 4, c = idx & 15;
        cpa16(smu + OFF_K0 + dp * KSTR + c * 4, ksrc + (size_t)dp * NN + c * 4);
    }
    if (tid < 16) cpa16(smu + OFF_TK0 + tid * 4, g_tk + h * NN + tid * 4);
    cpa_commit();

    float oc[16][4], ot[4];
    float lac0 = 0.0f, lac1 = 0.0f;
#pragma unroll
    for (int j = 0; j < 16; j++)
#pragma unroll
        for (int r = 0; r < 4; r++) oc[j][r] = 0.0f;
#pragma unroll
    for (int r = 0; r < 4; r++) ot[r] = 0.0f;

    for (int c64 = 0; c64 < 64; c64++) {
        const int k0 = c64 * 64;
        unsigned* Kc = smu + ((c64 & 1) ? OFF_K1 : OFF_K0);
        unsigned* Kn = smu + ((c64 & 1) ? OFF_K0 : OFF_K1);
        float* tkc = (float*)(smu + ((c64 & 1) ? OFF_TK1 : OFF_TK0));
        float* tkn = (float*)(smu + ((c64 & 1) ? OFF_TK0 : OFF_TK1));

        __syncthreads();   // A: PV(c-1) done; Vp/Kn writable

        // V(c)
        {
            const unsigned* vsrc = g_Vp + ((size_t)h * 2048 + (k0 >> 1)) * ND;
            for (int idx = tid; idx < 1024; idx += 256) {
                int np = idx >> 5, c = idx & 31;
                cpa16(Vp + np * VSTR + c * 4, vsrc + (size_t)np * ND + c * 4);
            }
            if (tid < 32) cpa4(Vp + tid * VSTR + 128, g_VTp + h * 2048 + (k0 >> 1) + tid);
        }
        cpa_commit();

        if (c64 < 63) {
            const unsigned* kn = ksrc + k0 + 64;
            for (int idx = tid; idx < 64 * 16; idx += 256) {
                int dp = idx >> 4, c = idx & 15;
                cpa16(Kn + dp * KSTR + c * 4, kn + (size_t)dp * NN + c * 4);
            }
            if (tid < 16) cpa16(tkn + tid * 4, g_tk + h * NN + k0 + 64 + tid * 4);
            cpa_commit();
            cpa_wait<2>();
        } else {
            cpa_wait<1>();
        }
        __syncthreads();   // B: K(c)/tk(c) visible

        // ---- scores: 16 rows x 64 keys ----
        float sc[8][4];
#pragma unroll
        for (int nt = 0; nt < 8; nt++)
#pragma unroll
            for (int r = 0; r < 4; r++) sc[nt][r] = 0.0f;

#pragma unroll
        for (int ks = 0; ks < 8; ks++) {
            const unsigned* kb = Kc + (ks * 8 + qp) * KSTR + qr;
#pragma unroll
            for (int nt = 0; nt < 8; nt++) {
                unsigned b0 = kb[nt * 8];
                unsigned b1 = kb[4 * KSTR + nt * 8];
                mma16(sc[nt], qf[ks][0], qf[ks][1], qf[ks][2], qf[ks][3], b0, b1);
            }
        }

        // ---- fixup + exp2 + pack into PV A-frags (registers!) ----
        unsigned pa[4][4];
#pragma unroll
        for (int nt = 0; nt < 8; nt++) {
            int col = nt * 8 + qp * 2;
            float t0 = tkc[col], t1 = tkc[col + 1];
            float p0 = exp2f(sc[nt][0] - tqr0 * t0);
            float p1 = exp2f(sc[nt][1] - tqr0 * t1);
            float p2 = exp2f(sc[nt][2] - tqr1 * t0);
            float p3 = exp2f(sc[nt][3] - tqr1 * t1);
            unsigned pkA = pkbf2(p0, p1);
            unsigned pkB = pkbf2(p2, p3);
            lac0 += __uint_as_float(pkA << 16) + __uint_as_float(pkA & 0xffff0000u);
            lac1 += __uint_as_float(pkB << 16) + __uint_as_float(pkB & 0xffff0000u);
            pa[nt >> 1][(nt & 1) * 2]     = pkA;
            pa[nt >> 1][(nt & 1) * 2 + 1] = pkB;
        }

        if (c64 < 63) cpa_wait<1>(); else cpa_wait<0>();   // V(c) done
        __syncthreads();   // C: Vp visible

        // ---- PV: 16 rows x 128 d + time col, P from registers ----
#pragma unroll
        for (int ks = 0; ks < 4; ks++) {
            const unsigned* vb = Vp + (ks * 8 + qp) * VSTR + qr;
#pragma unroll
            for (int j = 0; j < 16; j++) {
                unsigned b0 = vb[j * 8];
                unsigned b1 = vb[4 * VSTR + j * 8];
                mma16(oc[j], pa[ks][0], pa[ks][1], pa[ks][2], pa[ks][3], b0, b1);
            }
            unsigned b0 = vb[128];
            unsigned b1 = vb[4 * VSTR + 128];
            mma16(ot, pa[ks][0], pa[ks][1], pa[ks][2], pa[ks][3], b0, b1);
        }
    }

    // ---- epilogue: l/t quad reductions, ave, fused midpoint_norm ----
    lac0 += __shfl_xor_sync(0xffffffffu, lac0, 1);
    lac0 += __shfl_xor_sync(0xffffffffu, lac0, 2);
    lac1 += __shfl_xor_sync(0xffffffffu, lac1, 1);
    lac1 += __shfl_xor_sync(0xffffffffu, lac1, 2);
    float rl0 = 1.0f / lac0, rl1 = 1.0f / lac1;

    // time averages (valid in C col 0 -> qp==0 lane); broadcast within quad
    float tt0 = __shfl_sync(0xffffffffu, ot[0], lane & ~3) * rl0;
    float tt1 = __shfl_sync(0xffffffffu, ot[2], lane & ~3) * rl1;

    float av0[16][2], av1[16][2];
    float s0 = 0.0f, s1 = 0.0f;
#pragma unroll
    for (int j = 0; j < 16; j++) {
        av0[j][0] = oc[j][0] * rl0; av0[j][1] = oc[j][1] * rl0;
        av1[j][0] = oc[j][2] * rl1; av1[j][1] = oc[j][3] * rl1;
        s0 = fmaf(av0[j][0], av0[j][0], fmaf(av0[j][1], av0[j][1], s0));
        s1 = fmaf(av1[j][0], av1[j][0], fmaf(av1[j][1], av1[j][1], s1));
    }
    s0 += __shfl_xor_sync(0xffffffffu, s0, 1);
    s0 += __shfl_xor_sync(0xffffffffu, s0, 2);
    s1 += __shfl_xor_sync(0xffffffffu, s1, 1);
    s1 += __shfl_xor_sync(0xffffffffu, s1, 2);

    float f0 = rsqrtf(fmaxf(fabsf(s0 - tt0 * tt0), 1e-8f));
    float f1 = rsqrtf(fmaxf(fabsf(s1 - tt1 * tt1), 1e-8f));

    int row0 = m0 + rowb + qr, row1 = row0 + 8;
    float* o0 = g_OS + ((size_t)(h * NN + row0)) * ND;
    float* o1 = g_OS + ((size_t)(h * NN + row1)) * ND;
#pragma unroll
    for (int j = 0; j < 16; j++) {
        int d0 = j * 8 + qp * 2;
        *(float2*)&o0[d0] = make_float2(av0[j][0] * f0, av0[j][1] * f0);
        *(float2*)&o1[d0] = make_float2(av1[j][0] * f1, av1[j][1] * f1);
    }
    if (qp == 0) {
        g_OT[h * NN + row0] = tt0 * f0;
        g_OT[h * NN + row1] = tt1 * f1;
    }
}

// =====================================================================
// Kernel 3: head mean + final midpoint_norm (inputs already normalized)
// =====================================================================
__global__ __launch_bounds__(256) void final_kernel(float* __restrict__ out)
{
    const int warp = threadIdx.x >> 5, lane = threadIdx.x & 31;
    const int n = blockIdx.x * 8 + warp;

    float as0 = 0.f, as1 = 0.f, as2 = 0.f, as3 = 0.f, at = 0.f;
#pragma unroll
    for (int h = 0; h < NH; h++) {
        float4 v = *(const float4*)&g_OS[((size_t)(h * NN + n)) * ND + lane * 4];
        as0 += v.x; as1 += v.y; as2 += v.z; as3 += v.w;
        at += g_OT[h * NN + n];
    }
    const float inv = 1.0f / (float)NH;
    as0 *= inv; as1 *= inv; as2 *= inv; as3 *= inv; at *= inv;

    float q = as0 * as0 + as1 * as1 + as2 * as2 + as3 * as3;
#pragma unroll
    for (int off = 16; off; off >>= 1)
        q += __shfl_xor_sync(0xffffffffu, q, off);

    float inner = q - at * at;
    float f = 1.0f / sqrtf(fmaxf(fabsf(inner), 1e-8f));

    float* o = out + (size_t)n * 129;
    if (lane == 0) o[0] = at * f;
    o[1 + lane * 4 + 0] = as0 * f;
    o[1 + lane * 4 + 1] = as1 * f;
    o[1 + lane * 4 + 2] = as2 * f;
    o[1 + lane * 4 + 3] = as3 * f;
}

// =====================================================================
extern "C" void kernel_launch(void* const* d_in, const int* in_sizes, int n_in,
                              void* d_out, int out_size)
{
    const float* x     = (const float*)d_in[0];
    const float* Wq    = (const float*)d_in[1];
    const float* bq    = (const float*)d_in[2];
    const float* Wk    = (const float*)d_in[3];
    const float* bk    = (const float*)d_in[4];
    const float* Wv    = (const float*)d_in[5];
    const float* bv    = (const float*)d_in[6];
    const float* scale = (const float*)d_in[7];
    float* out = (float*)d_out;

    cudaFuncSetAttribute(proj_kernel,
                         cudaFuncAttributeMaxDynamicSharedMemorySize, PROJ_SMEM_BYTES);
    cudaFuncSetAttribute(attn_kernel,
                         cudaFuncAttributeMaxDynamicSharedMemorySize, ATTN_SMEM_BYTES);

    proj_kernel<<<dim3(NN / 128, NH * 3), 256, PROJ_SMEM_BYTES>>>(
        x, Wq, bq, Wk, bk, Wv, bv, scale);
    attn_kernel<<<dim3(NN / 128, NH), 256, ATTN_SMEM_BYTES>>>();
    final_kernel<<<NN / 8, 256>>>(out);
}

// round 14
// speedup vs baseline: 7.9429x; 1.0138x over previous
#include <cuda_runtime.h>
#include <math.h>

#define NH 12
#define NN 4096
#define ND 128
#define NIN 256

// ---- tf32 (proj) ----
__device__ __forceinline__ void mma8(float* c, unsigned a0, unsigned a1,
    unsigned a2, unsigned a3, unsigned b0, unsigned b1) {
    asm volatile("mma.sync.aligned.m16n8k8.row.col.f32.tf32.tf32.f32 "
        "{%0,%1,%2,%3}, {%4,%5,%6,%7}, {%8,%9}, {%0,%1,%2,%3};"
        : "+f"(c[0]), "+f"(c[1]), "+f"(c[2]), "+f"(c[3])
        : "r"(a0), "r"(a1), "r"(a2), "r"(a3), "r"(b0), "r"(b1));
}
// ---- bf16 (attn) ----
__device__ __forceinline__ void mma16(float* c, unsigned a0, unsigned a1,
    unsigned a2, unsigned a3, unsigned b0, unsigned b1) {
    asm volatile("mma.sync.aligned.m16n8k16.row.col.f32.bf16.bf16.f32 "
        "{%0,%1,%2,%3}, {%4,%5,%6,%7}, {%8,%9}, {%0,%1,%2,%3};"
        : "+f"(c[0]), "+f"(c[1]), "+f"(c[2]), "+f"(c[3])
        : "r"(a0), "r"(a1), "r"(a2), "r"(a3), "r"(b0), "r"(b1));
}
__device__ __forceinline__ unsigned pkbf2(float lo, float hi) {
    unsigned r;
    asm("{.reg .b16 l, h;\n\tcvt.rn.bf16.f32 l, %1;\n\tcvt.rn.bf16.f32 h, %2;\n\t"
        "mov.b32 %0, {l, h};}" : "=r"(r) : "f"(lo), "f"(hi));
    return r;
}
// ---- cp.async ----
__device__ __forceinline__ void cpa16(void* dst, const void* src) {
    unsigned d = (unsigned)__cvta_generic_to_shared(dst);
    asm volatile("cp.async.cg.shared.global [%0], [%1], 16;" :: "r"(d), "l"(src));
}
__device__ __forceinline__ void cpa4(void* dst, const void* src) {
    unsigned d = (unsigned)__cvta_generic_to_shared(dst);
    asm volatile("cp.async.ca.shared.global [%0], [%1], 4;" :: "r"(d), "l"(src));
}
__device__ __forceinline__ void cpa_commit() {
    asm volatile("cp.async.commit_group;" ::: "memory");
}
template<int N> __device__ __forceinline__ void cpa_wait() {
    asm volatile("cp.async.wait_group %0;" :: "n"(N) : "memory");
}

#define LOG2E 1.4426950408889634f

// ---------------- scratch ----------------
__device__ unsigned g_Qp[NH * 64 * NN];     // bf16x2 d-pair-packed, d-major (alpha*log2e*s_q)
__device__ unsigned g_Kp[NH * 64 * NN];     // s_k
__device__ unsigned g_Vp[NH * (NN / 2) * ND];  // key-pair-packed v_s
__device__ unsigned g_VTp[NH * (NN / 2)];      // packed (v_t[2i], v_t[2i+1])
__device__ float g_tq[NH * NN];             // alpha*log2e * t_q
__device__ float g_tk[NH * NN];             // t_k
__device__ float g_OS[NH * NN * ND];        // per-head NORMALIZED midpoint (s)
__device__ float g_OT[NH * NN];             // per-head NORMALIZED midpoint (t)

// =====================================================================
// Kernel 1: projections via tf32 mma (unchanged from R13)
// =====================================================================
#define PSTRX 36
#define PROJ_TILE (128 * PSTRX)
#define PROJ_SMEM_BYTES (4 * PROJ_TILE * 4)

__global__ __launch_bounds__(256, 1) void proj_kernel(
    const float* __restrict__ x,
    const float* __restrict__ Wq, const float* __restrict__ bq,
    const float* __restrict__ Wk, const float* __restrict__ bk,
    const float* __restrict__ Wv, const float* __restrict__ bv,
    const float* __restrict__ scale_ptr)
{
    extern __shared__ float psm[];
    __shared__ float Sred[128][2];

    const int by = blockIdx.y, h = by % NH, sel = by / NH;
    const float* W = (sel == 0) ? Wq : (sel == 1) ? Wk : Wv;
    const float* B = (sel == 0) ? bq : (sel == 1) ? bk : bv;
    const float* Wh = W + (size_t)h * ND * NIN;
    const int n0 = blockIdx.x * 128;
    const int tid = threadIdx.x, lane = tid & 31, wid = tid >> 5;
    const int qp = lane & 3, qr = lane >> 2, mg = wid & 3, ngg = wid >> 2;

    auto load_chunk = [&](int kb, int buf) {
        float* Xs = psm + buf * (2 * PROJ_TILE);
        float* Ws = Xs + PROJ_TILE;
        for (int idx = tid; idx < 128 * 32; idx += 256) {
            int m = idx >> 5, k = idx & 31;
            cpa4(Xs + m * PSTRX + k, x + (size_t)(n0 + m) * 257 + 1 + kb + k);
        }
        for (int idx = tid; idx < 128 * 8; idx += 256) {
            int o = idx >> 3, kq = idx & 7;
            cpa16(Ws + o * PSTRX + kq * 4, Wh + (size_t)o * NIN + kb + kq * 4);
        }
    };

    float cacc[2][8][4];
#pragma unroll
    for (int mt = 0; mt < 2; mt++)
#pragma unroll
        for (int nt = 0; nt < 8; nt++)
#pragma unroll
            for (int r = 0; r < 4; r++) cacc[mt][nt][r] = 0.0f;

    load_chunk(0, 0);
    cpa_commit();
    for (int c = 0; c < 8; c++) {
        if (c < 7) { load_chunk((c + 1) * 32, (c + 1) & 1); cpa_commit(); cpa_wait<1>(); }
        else cpa_wait<0>();
        __syncthreads();
        const float* Xc = psm + (c & 1) * (2 * PROJ_TILE);
        const float* Wc = Xc + PROJ_TILE;
#pragma unroll
        for (int ks = 0; ks < 4; ks++) {
            unsigned a[2][4];
            const float* qa = Xc + (mg * 32 + qr) * PSTRX + ks * 8 + qp;
#pragma unroll
            for (int mt = 0; mt < 2; mt++) {
                const float* q2 = qa + mt * 16 * PSTRX;
                a[mt][0] = __float_as_uint(q2[0]);
                a[mt][1] = __float_as_uint(q2[8 * PSTRX]);
                a[mt][2] = __float_as_uint(q2[4]);
                a[mt][3] = __float_as_uint(q2[8 * PSTRX + 4]);
            }
#pragma unroll
            for (int nt = 0; nt < 8; nt++) {
                const float* kb2 = Wc + (ngg * 64 + nt * 8 + qr) * PSTRX + ks * 8 + qp;
                unsigned b0 = __float_as_uint(kb2[0]);
                unsigned b1 = __float_as_uint(kb2[4]);
                mma8(cacc[0][nt], a[0][0], a[0][1], a[0][2], a[0][3], b0, b1);
                mma8(cacc[1][nt], a[1][0], a[1][1], a[1][2], a[1][3], b0, b1);
            }
        }
        __syncthreads();
    }

    float bb[8][2];
#pragma unroll
    for (int nt = 0; nt < 8; nt++) {
        int col = ngg * 64 + nt * 8 + qp * 2;
        bb[nt][0] = B[h * ND + col];
        bb[nt][1] = B[h * ND + col + 1];
    }
    float ssq[2][2] = {{0.f, 0.f}, {0.f, 0.f}};
#pragma unroll
    for (int mt = 0; mt < 2; mt++)
#pragma unroll
        for (int nt = 0; nt < 8; nt++)
#pragma unroll
            for (int rr = 0; rr < 2; rr++) {
                cacc[mt][nt][rr * 2] += bb[nt][0];
                cacc[mt][nt][rr * 2 + 1] += bb[nt][1];
                ssq[mt][rr] = fmaf(cacc[mt][nt][rr * 2], cacc[mt][nt][rr * 2], ssq[mt][rr]);
                ssq[mt][rr] = fmaf(cacc[mt][nt][rr * 2 + 1], cacc[mt][nt][rr * 2 + 1], ssq[mt][rr]);
            }
#pragma unroll
    for (int mt = 0; mt < 2; mt++)
#pragma unroll
        for (int rr = 0; rr < 2; rr++) {
            ssq[mt][rr] += __shfl_xor_sync(0xffffffffu, ssq[mt][rr], 1);
            ssq[mt][rr] += __shfl_xor_sync(0xffffffffu, ssq[mt][rr], 2);
        }
    if (qp == 0) {
#pragma unroll
        for (int mt = 0; mt < 2; mt++)
#pragma unroll
            for (int rr = 0; rr < 2; rr++)
                Sred[mg * 32 + mt * 16 + rr * 8 + qr][ngg] = ssq[mt][rr];
    }
    __syncthreads();

    const float alpha = 2.0f / scale_ptr[0];

    if (sel < 2) {
        const float smul = (sel == 0) ? alpha * LOG2E : 1.0f;
        unsigned* T = ((sel == 0) ? g_Qp : g_Kp) + (size_t)h * 64 * NN;
#pragma unroll
        for (int mt = 0; mt < 2; mt++)
#pragma unroll
            for (int rr = 0; rr < 2; rr++) {
                int n = n0 + mg * 32 + mt * 16 + rr * 8 + qr;
#pragma unroll
                for (int nt = 0; nt < 8; nt++) {
                    int dp = ngg * 32 + nt * 4 + qp;
                    T[(size_t)dp * NN + n] =
                        pkbf2(smul * cacc[mt][nt][rr * 2], smul * cacc[mt][nt][rr * 2 + 1]);
                }
                if (qp == 0 && ngg == 0) {
                    int row = mg * 32 + mt * 16 + rr * 8 + qr;
                    float t = sqrtf(Sred[row][0] + Sred[row][1] + 1.0f);
                    if (sel == 0) g_tq[h * NN + n] = alpha * LOG2E * t;
                    else          g_tk[h * NN + n] = t;
                }
            }
    } else {
#pragma unroll
        for (int mt = 0; mt < 2; mt++)
#pragma unroll
            for (int rr = 0; rr < 2; rr++) {
                int n = n0 + mg * 32 + mt * 16 + rr * 8 + qr;
                int row = mg * 32 + mt * 16 + rr * 8 + qr;
                float t = sqrtf(Sred[row][0] + Sred[row][1] + 1.0f);
                float tp = __shfl_down_sync(0xffffffffu, t, 4);
                unsigned* vdst = g_Vp + ((size_t)h * 2048 + (n >> 1)) * ND;
#pragma unroll
                for (int nt = 0; nt < 8; nt++) {
                    int col = ngg * 64 + nt * 8 + qp * 2;
                    float v0 = cacc[mt][nt][rr * 2];
                    float v1 = cacc[mt][nt][rr * 2 + 1];
                    float v0p = __shfl_down_sync(0xffffffffu, v0, 4);
                    float v1p = __shfl_down_sync(0xffffffffu, v1, 4);
                    if ((qr & 1) == 0) {
                        vdst[col]     = pkbf2(v0, v0p);
                        vdst[col + 1] = pkbf2(v1, v1p);
                    }
                }
                if (qp == 0 && ngg == 0 && (qr & 1) == 0)
                    g_VTp[h * 2048 + (n >> 1)] = pkbf2(t, tp);
            }
    }
}

// =====================================================================
// Kernel 2: flash attention. One barrier per chunk; merged
// [PV(c) + score(c+1)] tensor block; P in registers; fused midpoint_norm.
// =====================================================================
#define KSTR 72
#define VSTR 136

#define OFF_K0   0
#define OFF_K1   4608
#define OFF_V0   9216
#define OFF_V1   13568
#define OFF_TK0  17920
#define OFF_TK1  17984
#define ATTN_SMEM_WORDS 18048
#define ATTN_SMEM_BYTES (ATTN_SMEM_WORDS * 4)

__global__ __launch_bounds__(256, 1) void attn_kernel()
{
    extern __shared__ unsigned smu[];

    const int h = blockIdx.y, m0 = blockIdx.x * 128;
    const int tid = threadIdx.x, lane = tid & 31, wid = tid >> 5;
    const int qp = lane & 3, qr = lane >> 2;
    const int rowb = wid * 16;

    const unsigned* ksrc = g_Kp + (size_t)h * 64 * NN;
    const unsigned* vsrcb = g_Vp + (size_t)h * 2048 * ND;
    const unsigned* vtb = g_VTp + h * 2048;
    const float* tkg = g_tk + h * NN;

    const float tqr0 = g_tq[h * NN + m0 + rowb + qr];
    const float tqr1 = g_tq[h * NN + m0 + rowb + qr + 8];

    // Q A-fragments: loaded once
    unsigned qf[8][4];
    {
        const unsigned* qg = g_Qp + (size_t)h * 64 * NN + m0 + rowb;
#pragma unroll
        for (int ks = 0; ks < 8; ks++) {
            qf[ks][0] = qg[(size_t)(ks * 8 + qp) * NN + qr];
            qf[ks][1] = qg[(size_t)(ks * 8 + qp) * NN + qr + 8];
            qf[ks][2] = qg[(size_t)(ks * 8 + 4 + qp) * NN + qr];
            qf[ks][3] = qg[(size_t)(ks * 8 + 4 + qp) * NN + qr + 8];
        }
    }

    // zero V pad cols 129..135 for both buffers
    for (int i = tid; i < 2 * 32 * 7; i += 256) {
        int b = i / (32 * 7), r = i % (32 * 7);
        smu[(b ? OFF_V1 : OFF_V0) + (r / 7) * VSTR + 129 + (r % 7)] = 0u;
    }

    // K/V/tk loaders
    auto loadK = [&](int j) {   // K(j) + tk(j) -> buffers by parity j&1
        unsigned* Kd = smu + ((j & 1) ? OFF_K1 : OFF_K0);
        const unsigned* kn = ksrc + j * 64;
        for (int idx = tid; idx < 64 * 16; idx += 256) {
            int dp = idx >> 4, c = idx & 15;
            cpa16(Kd + dp * KSTR + c * 4, kn + (size_t)dp * NN + c * 4);
        }
        if (tid < 16) cpa16(smu + ((j & 1) ? OFF_TK1 : OFF_TK0) + tid * 4,
                            tkg + j * 64 + tid * 4);
    };
    auto loadV = [&](int j) {   // V(j) + vt(j) -> buffer by parity j&1
        unsigned* Vd = smu + ((j & 1) ? OFF_V1 : OFF_V0);
        const unsigned* vsrc = vsrcb + (size_t)(j * 32) * ND;
        for (int idx = tid; idx < 1024; idx += 256) {
            int np = idx >> 5, c = idx & 31;
            cpa16(Vd + np * VSTR + c * 4, vsrc + (size_t)np * ND + c * 4);
        }
        if (tid < 32) cpa4(Vd + tid * VSTR + 128, vtb + j * 32 + tid);
    };

    // prologue: group A = [K(0),tk(0)]; group B = [K(1),tk(1),V(0)]
    loadK(0); cpa_commit();
    loadK(1); loadV(0); cpa_commit();
    cpa_wait<1>();          // A done
    __syncthreads();

    // score(0)
    float sc[8][4];
#pragma unroll
    for (int nt = 0; nt < 8; nt++)
#pragma unroll
        for (int r = 0; r < 4; r++) sc[nt][r] = 0.0f;
    {
        const unsigned* Kc = smu + OFF_K0;
#pragma unroll
        for (int ks = 0; ks < 8; ks++) {
            const unsigned* kb = Kc + (ks * 8 + qp) * KSTR + qr;
#pragma unroll
            for (int nt = 0; nt < 8; nt++)
                mma16(sc[nt], qf[ks][0], qf[ks][1], qf[ks][2], qf[ks][3],
                      kb[nt * 8], kb[4 * KSTR + nt * 8]);
        }
    }

    float oc[16][4], ot[4];
    float lac0 = 0.0f, lac1 = 0.0f;
#pragma unroll
    for (int j = 0; j < 16; j++)
#pragma unroll
        for (int r = 0; r < 4; r++) oc[j][r] = 0.0f;
#pragma unroll
    for (int r = 0; r < 4; r++) ot[r] = 0.0f;

    for (int c = 0; c < 64; c++) {
        const float* tkc = (const float*)(smu + ((c & 1) ? OFF_TK1 : OFF_TK0));

        // ---- exp(c): sc -> pa (registers) ----
        unsigned pa[4][4];
#pragma unroll
        for (int nt = 0; nt < 8; nt++) {
            int col = nt * 8 + qp * 2;
            float t0 = tkc[col], t1 = tkc[col + 1];
            float p0 = exp2f(sc[nt][0] - tqr0 * t0);
            float p1 = exp2f(sc[nt][1] - tqr0 * t1);
            float p2 = exp2f(sc[nt][2] - tqr1 * t0);
            float p3 = exp2f(sc[nt][3] - tqr1 * t1);
            unsigned pkA = pkbf2(p0, p1);
            unsigned pkB = pkbf2(p2, p3);
            lac0 += __uint_as_float(pkA << 16) + __uint_as_float(pkA & 0xffff0000u);
            lac1 += __uint_as_float(pkB << 16) + __uint_as_float(pkB & 0xffff0000u);
            pa[nt >> 1][(nt & 1) * 2]     = pkA;
            pa[nt >> 1][(nt & 1) * 2 + 1] = pkB;
        }

        __syncthreads();   // all warps done reading K(c)/V(c-1)/tk(c) buffers

        // ---- issue group(c) = [K(c+2), tk(c+2), V(c+1)] ----
        if (c + 2 < 64) loadK(c + 2);
        if (c + 1 < 64) loadV(c + 1);
        cpa_commit();
        cpa_wait<1>();     // group(c-1) complete: K(c+1), V(c) resident

        // ---- merged tensor block: PV(c) + score(c+1) ----
        const unsigned* Vc = smu + ((c & 1) ? OFF_V1 : OFF_V0);
#pragma unroll
        for (int ks = 0; ks < 4; ks++) {
            const unsigned* vb = Vc + (ks * 8 + qp) * VSTR + qr;
#pragma unroll
            for (int j = 0; j < 16; j++)
                mma16(oc[j], pa[ks][0], pa[ks][1], pa[ks][2], pa[ks][3],
                      vb[j * 8], vb[4 * VSTR + j * 8]);
            mma16(ot, pa[ks][0], pa[ks][1], pa[ks][2], pa[ks][3],
                  vb[128], vb[4 * VSTR + 128]);
        }
        if (c < 63) {
            const unsigned* Kn = smu + (((c + 1) & 1) ? OFF_K1 : OFF_K0);
#pragma unroll
            for (int nt = 0; nt < 8; nt++)
#pragma unroll
                for (int r = 0; r < 4; r++) sc[nt][r] = 0.0f;
#pragma unroll
            for (int ks = 0; ks < 8; ks++) {
                const unsigned* kb = Kn + (ks * 8 + qp) * KSTR + qr;
#pragma unroll
                for (int nt = 0; nt < 8; nt++)
                    mma16(sc[nt], qf[ks][0], qf[ks][1], qf[ks][2], qf[ks][3],
                          kb[nt * 8], kb[4 * KSTR + nt * 8]);
            }
        }
    }

    // ---- epilogue: l/t reductions, ave, fused per-head midpoint_norm ----
    lac0 += __shfl_xor_sync(0xffffffffu, lac0, 1);
    lac0 += __shfl_xor_sync(0xffffffffu, lac0, 2);
    lac1 += __shfl_xor_sync(0xffffffffu, lac1, 1);
    lac1 += __shfl_xor_sync(0xffffffffu, lac1, 2);
    float rl0 = 1.0f / lac0, rl1 = 1.0f / lac1;

    float tt0 = __shfl_sync(0xffffffffu, ot[0], lane & ~3) * rl0;
    float tt1 = __shfl_sync(0xffffffffu, ot[2], lane & ~3) * rl1;

    float av0[16][2], av1[16][2];
    float s0 = 0.0f, s1 = 0.0f;
#pragma unroll
    for (int j = 0; j < 16; j++) {
        av0[j][0] = oc[j][0] * rl0; av0[j][1] = oc[j][1] * rl0;
        av1[j][0] = oc[j][2] * rl1; av1[j][1] = oc[j][3] * rl1;
        s0 = fmaf(av0[j][0], av0[j][0], fmaf(av0[j][1], av0[j][1], s0));
        s1 = fmaf(av1[j][0], av1[j][0], fmaf(av1[j][1], av1[j][1], s1));
    }
    s0 += __shfl_xor_sync(0xffffffffu, s0, 1);
    s0 += __shfl_xor_sync(0xffffffffu, s0, 2);
    s1 += __shfl_xor_sync(0xffffffffu, s1, 1);
    s1 += __shfl_xor_sync(0xffffffffu, s1, 2);

    float f0 = rsqrtf(fmaxf(fabsf(s0 - tt0 * tt0), 1e-8f));
    float f1 = rsqrtf(fmaxf(fabsf(s1 - tt1 * tt1), 1e-8f));

    int row0 = m0 + rowb + qr, row1 = row0 + 8;
    float* o0 = g_OS + ((size_t)(h * NN + row0)) * ND;
    float* o1 = g_OS + ((size_t)(h * NN + row1)) * ND;
#pragma unroll
    for (int j = 0; j < 16; j++) {
        int d0 = j * 8 + qp * 2;
        *(float2*)&o0[d0] = make_float2(av0[j][0] * f0, av0[j][1] * f0);
        *(float2*)&o1[d0] = make_float2(av1[j][0] * f1, av1[j][1] * f1);
    }
    if (qp == 0) {
        g_OT[h * NN + row0] = tt0 * f0;
        g_OT[h * NN + row1] = tt1 * f1;
    }
}

// =====================================================================
// Kernel 3: head mean + final midpoint_norm (unchanged)
// =====================================================================
__global__ __launch_bounds__(256) void final_kernel(float* __restrict__ out)
{
    const int warp = threadIdx.x >> 5, lane = threadIdx.x & 31;
    const int n = blockIdx.x * 8 + warp;

    float as0 = 0.f, as1 = 0.f, as2 = 0.f, as3 = 0.f, at = 0.f;
#pragma unroll
    for (int h = 0; h < NH; h++) {
        float4 v = *(const float4*)&g_OS[((size_t)(h * NN + n)) * ND + lane * 4];
        as0 += v.x; as1 += v.y; as2 += v.z; as3 += v.w;
        at += g_OT[h * NN + n];
    }
    const float inv = 1.0f / (float)NH;
    as0 *= inv; as1 *= inv; as2 *= inv; as3 *= inv; at *= inv;

    float q = as0 * as0 + as1 * as1 + as2 * as2 + as3 * as3;
#pragma unroll
    for (int off = 16; off; off >>= 1)
        q += __shfl_xor_sync(0xffffffffu, q, off);

    float inner = q - at * at;
    float f = 1.0f / sqrtf(fmaxf(fabsf(inner), 1e-8f));

    float* o = out + (size_t)n * 129;
    if (lane == 0) o[0] = at * f;
    o[1 + lane * 4 + 0] = as0 * f;
    o[1 + lane * 4 + 1] = as1 * f;
    o[1 + lane * 4 + 2] = as2 * f;
    o[1 + lane * 4 + 3] = as3 * f;
}

// =====================================================================
extern "C" void kernel_launch(void* const* d_in, const int* in_sizes, int n_in,
                              void* d_out, int out_size)
{
    const float* x     = (const float*)d_in[0];
    const float* Wq    = (const float*)d_in[1];
    const float* bq    = (const float*)d_in[2];
    const float* Wk    = (const float*)d_in[3];
    const float* bk    = (const float*)d_in[4];
    const float* Wv    = (const float*)d_in[5];
    const float* bv    = (const float*)d_in[6];
    const float* scale = (const float*)d_in[7];
    float* out = (float*)d_out;

    cudaFuncSetAttribute(proj_kernel,
                         cudaFuncAttributeMaxDynamicSharedMemorySize, PROJ_SMEM_BYTES);
    cudaFuncSetAttribute(attn_kernel,
                         cudaFuncAttributeMaxDynamicSharedMemorySize, ATTN_SMEM_BYTES);

    proj_kernel<<<dim3(NN / 128, NH * 3), 256, PROJ_SMEM_BYTES>>>(
        x, Wq, bq, Wk, bk, Wv, bv, scale);
    attn_kernel<<<dim3(NN / 128, NH), 256, ATTN_SMEM_BYTES>>>();
    final_kernel<<<NN / 8, 256>>>(out);
}

// round 15
// speedup vs baseline: 8.1336x; 1.0240x over previous
#include <cuda_runtime.h>
#include <math.h>

#define NH 12
#define NN 4096
#define ND 128
#define NIN 256

// ---- tf32 (proj) ----
__device__ __forceinline__ void mma8(float* c, unsigned a0, unsigned a1,
    unsigned a2, unsigned a3, unsigned b0, unsigned b1) {
    asm volatile("mma.sync.aligned.m16n8k8.row.col.f32.tf32.tf32.f32 "
        "{%0,%1,%2,%3}, {%4,%5,%6,%7}, {%8,%9}, {%0,%1,%2,%3};"
        : "+f"(c[0]), "+f"(c[1]), "+f"(c[2]), "+f"(c[3])
        : "r"(a0), "r"(a1), "r"(a2), "r"(a3), "r"(b0), "r"(b1));
}
// ---- bf16 (attn) ----
__device__ __forceinline__ void mma16(float* c, unsigned a0, unsigned a1,
    unsigned a2, unsigned a3, unsigned b0, unsigned b1) {
    asm volatile("mma.sync.aligned.m16n8k16.row.col.f32.bf16.bf16.f32 "
        "{%0,%1,%2,%3}, {%4,%5,%6,%7}, {%8,%9}, {%0,%1,%2,%3};"
        : "+f"(c[0]), "+f"(c[1]), "+f"(c[2]), "+f"(c[3])
        : "r"(a0), "r"(a1), "r"(a2), "r"(a3), "r"(b0), "r"(b1));
}
__device__ __forceinline__ unsigned pkbf2(float lo, float hi) {
    unsigned r;
    asm("{.reg .b16 l, h;\n\tcvt.rn.bf16.f32 l, %1;\n\tcvt.rn.bf16.f32 h, %2;\n\t"
        "mov.b32 %0, {l, h};}" : "=r"(r) : "f"(lo), "f"(hi));
    return r;
}
// ---- cp.async ----
__device__ __forceinline__ void cpa16(void* dst, const void* src) {
    unsigned d = (unsigned)__cvta_generic_to_shared(dst);
    asm volatile("cp.async.cg.shared.global [%0], [%1], 16;" :: "r"(d), "l"(src));
}
__device__ __forceinline__ void cpa4(void* dst, const void* src) {
    unsigned d = (unsigned)__cvta_generic_to_shared(dst);
    asm volatile("cp.async.ca.shared.global [%0], [%1], 4;" :: "r"(d), "l"(src));
}
__device__ __forceinline__ void cpa_commit() {
    asm volatile("cp.async.commit_group;" ::: "memory");
}
template<int N> __device__ __forceinline__ void cpa_wait() {
    asm volatile("cp.async.wait_group %0;" :: "n"(N) : "memory");
}

#define LOG2E 1.4426950408889634f

// ---------------- scratch ----------------
__device__ unsigned g_Qp[NH * 64 * NN];     // bf16x2 d-pair-packed, d-major (alpha*log2e*s_q)
__device__ unsigned g_Kp[NH * 64 * NN];     // s_k
__device__ unsigned g_Vp[NH * (NN / 2) * ND];  // key-pair-packed v_s
__device__ unsigned g_VTp[NH * (NN / 2)];      // packed (v_t[2i], v_t[2i+1])
__device__ float g_tq[NH * NN];             // alpha*log2e * t_q
__device__ float g_tk[NH * NN];             // t_k
__device__ float g_OS[NH * NN * ND];        // per-head NORMALIZED midpoint (s)
__device__ float g_OT[NH * NN];             // per-head NORMALIZED midpoint (t)

// =====================================================================
// Kernel 1: projections via tf32 mma (unchanged)
// =====================================================================
#define PSTRX 36
#define PROJ_TILE (128 * PSTRX)
#define PROJ_SMEM_BYTES (4 * PROJ_TILE * 4)

__global__ __launch_bounds__(256, 1) void proj_kernel(
    const float* __restrict__ x,
    const float* __restrict__ Wq, const float* __restrict__ bq,
    const float* __restrict__ Wk, const float* __restrict__ bk,
    const float* __restrict__ Wv, const float* __restrict__ bv,
    const float* __restrict__ scale_ptr)
{
    extern __shared__ float psm[];
    __shared__ float Sred[128][2];

    const int by = blockIdx.y, h = by % NH, sel = by / NH;
    const float* W = (sel == 0) ? Wq : (sel == 1) ? Wk : Wv;
    const float* B = (sel == 0) ? bq : (sel == 1) ? bk : bv;
    const float* Wh = W + (size_t)h * ND * NIN;
    const int n0 = blockIdx.x * 128;
    const int tid = threadIdx.x, lane = tid & 31, wid = tid >> 5;
    const int qp = lane & 3, qr = lane >> 2, mg = wid & 3, ngg = wid >> 2;

    auto load_chunk = [&](int kb, int buf) {
        float* Xs = psm + buf * (2 * PROJ_TILE);
        float* Ws = Xs + PROJ_TILE;
        for (int idx = tid; idx < 128 * 32; idx += 256) {
            int m = idx >> 5, k = idx & 31;
            cpa4(Xs + m * PSTRX + k, x + (size_t)(n0 + m) * 257 + 1 + kb + k);
        }
        for (int idx = tid; idx < 128 * 8; idx += 256) {
            int o = idx >> 3, kq = idx & 7;
            cpa16(Ws + o * PSTRX + kq * 4, Wh + (size_t)o * NIN + kb + kq * 4);
        }
    };

    float cacc[2][8][4];
#pragma unroll
    for (int mt = 0; mt < 2; mt++)
#pragma unroll
        for (int nt = 0; nt < 8; nt++)
#pragma unroll
            for (int r = 0; r < 4; r++) cacc[mt][nt][r] = 0.0f;

    load_chunk(0, 0);
    cpa_commit();
    for (int c = 0; c < 8; c++) {
        if (c < 7) { load_chunk((c + 1) * 32, (c + 1) & 1); cpa_commit(); cpa_wait<1>(); }
        else cpa_wait<0>();
        __syncthreads();
        const float* Xc = psm + (c & 1) * (2 * PROJ_TILE);
        const float* Wc = Xc + PROJ_TILE;
#pragma unroll
        for (int ks = 0; ks < 4; ks++) {
            unsigned a[2][4];
            const float* qa = Xc + (mg * 32 + qr) * PSTRX + ks * 8 + qp;
#pragma unroll
            for (int mt = 0; mt < 2; mt++) {
                const float* q2 = qa + mt * 16 * PSTRX;
                a[mt][0] = __float_as_uint(q2[0]);
                a[mt][1] = __float_as_uint(q2[8 * PSTRX]);
                a[mt][2] = __float_as_uint(q2[4]);
                a[mt][3] = __float_as_uint(q2[8 * PSTRX + 4]);
            }
#pragma unroll
            for (int nt = 0; nt < 8; nt++) {
                const float* kb2 = Wc + (ngg * 64 + nt * 8 + qr) * PSTRX + ks * 8 + qp;
                unsigned b0 = __float_as_uint(kb2[0]);
                unsigned b1 = __float_as_uint(kb2[4]);
                mma8(cacc[0][nt], a[0][0], a[0][1], a[0][2], a[0][3], b0, b1);
                mma8(cacc[1][nt], a[1][0], a[1][1], a[1][2], a[1][3], b0, b1);
            }
        }
        __syncthreads();
    }

    float bb[8][2];
#pragma unroll
    for (int nt = 0; nt < 8; nt++) {
        int col = ngg * 64 + nt * 8 + qp * 2;
        bb[nt][0] = B[h * ND + col];
        bb[nt][1] = B[h * ND + col + 1];
    }
    float ssq[2][2] = {{0.f, 0.f}, {0.f, 0.f}};
#pragma unroll
    for (int mt = 0; mt < 2; mt++)
#pragma unroll
        for (int nt = 0; nt < 8; nt++)
#pragma unroll
            for (int rr = 0; rr < 2; rr++) {
                cacc[mt][nt][rr * 2] += bb[nt][0];
                cacc[mt][nt][rr * 2 + 1] += bb[nt][1];
                ssq[mt][rr] = fmaf(cacc[mt][nt][rr * 2], cacc[mt][nt][rr * 2], ssq[mt][rr]);
                ssq[mt][rr] = fmaf(cacc[mt][nt][rr * 2 + 1], cacc[mt][nt][rr * 2 + 1], ssq[mt][rr]);
            }
#pragma unroll
    for (int mt = 0; mt < 2; mt++)
#pragma unroll
        for (int rr = 0; rr < 2; rr++) {
            ssq[mt][rr] += __shfl_xor_sync(0xffffffffu, ssq[mt][rr], 1);
            ssq[mt][rr] += __shfl_xor_sync(0xffffffffu, ssq[mt][rr], 2);
        }
    if (qp == 0) {
#pragma unroll
        for (int mt = 0; mt < 2; mt++)
#pragma unroll
            for (int rr = 0; rr < 2; rr++)
                Sred[mg * 32 + mt * 16 + rr * 8 + qr][ngg] = ssq[mt][rr];
    }
    __syncthreads();

    const float alpha = 2.0f / scale_ptr[0];

    if (sel < 2) {
        const float smul = (sel == 0) ? alpha * LOG2E : 1.0f;
        unsigned* T = ((sel == 0) ? g_Qp : g_Kp) + (size_t)h * 64 * NN;
#pragma unroll
        for (int mt = 0; mt < 2; mt++)
#pragma unroll
            for (int rr = 0; rr < 2; rr++) {
                int n = n0 + mg * 32 + mt * 16 + rr * 8 + qr;
#pragma unroll
                for (int nt = 0; nt < 8; nt++) {
                    int dp = ngg * 32 + nt * 4 + qp;
                    T[(size_t)dp * NN + n] =
                        pkbf2(smul * cacc[mt][nt][rr * 2], smul * cacc[mt][nt][rr * 2 + 1]);
                }
                if (qp == 0 && ngg == 0) {
                    int row = mg * 32 + mt * 16 + rr * 8 + qr;
                    float t = sqrtf(Sred[row][0] + Sred[row][1] + 1.0f);
                    if (sel == 0) g_tq[h * NN + n] = alpha * LOG2E * t;
                    else          g_tk[h * NN + n] = t;
                }
            }
    } else {
#pragma unroll
        for (int mt = 0; mt < 2; mt++)
#pragma unroll
            for (int rr = 0; rr < 2; rr++) {
                int n = n0 + mg * 32 + mt * 16 + rr * 8 + qr;
                int row = mg * 32 + mt * 16 + rr * 8 + qr;
                float t = sqrtf(Sred[row][0] + Sred[row][1] + 1.0f);
                float tp = __shfl_down_sync(0xffffffffu, t, 4);
                unsigned* vdst = g_Vp + ((size_t)h * 2048 + (n >> 1)) * ND;
#pragma unroll
                for (int nt = 0; nt < 8; nt++) {
                    int col = ngg * 64 + nt * 8 + qp * 2;
                    float v0 = cacc[mt][nt][rr * 2];
                    float v1 = cacc[mt][nt][rr * 2 + 1];
                    float v0p = __shfl_down_sync(0xffffffffu, v0, 4);
                    float v1p = __shfl_down_sync(0xffffffffu, v1, 4);
                    if ((qr & 1) == 0) {
                        vdst[col]     = pkbf2(v0, v0p);
                        vdst[col + 1] = pkbf2(v1, v1p);
                    }
                }
                if (qp == 0 && ngg == 0 && (qr & 1) == 0)
                    g_VTp[h * 2048 + (n >> 1)] = pkbf2(t, tp);
            }
    }
}

// =====================================================================
// Kernel 2: flash attention. 128 threads / 64-row CTA -> 2-3 CTAs/SM so
// co-resident CTAs overlap exp/LDS bubbles with tensor work.
// Inner loop identical to R14 (P in registers, 1 barrier/chunk).
// =====================================================================
#define KSTR 72
#define VSTR 136

#define OFF_K0   0
#define OFF_K1   4608
#define OFF_V0   9216
#define OFF_V1   13568
#define OFF_TK0  17920
#define OFF_TK1  17984
#define ATTN_SMEM_WORDS 18048
#define ATTN_SMEM_BYTES (ATTN_SMEM_WORDS * 4)

#define ATHR 128

__global__ __launch_bounds__(ATHR, 1) void attn_kernel()
{
    extern __shared__ unsigned smu[];

    const int h = blockIdx.y, m0 = blockIdx.x * 64;
    const int tid = threadIdx.x, lane = tid & 31, wid = tid >> 5;
    const int qp = lane & 3, qr = lane >> 2;
    const int rowb = wid * 16;

    const unsigned* ksrc = g_Kp + (size_t)h * 64 * NN;
    const unsigned* vsrcb = g_Vp + (size_t)h * 2048 * ND;
    const unsigned* vtb = g_VTp + h * 2048;
    const float* tkg = g_tk + h * NN;

    const float tqr0 = g_tq[h * NN + m0 + rowb + qr];
    const float tqr1 = g_tq[h * NN + m0 + rowb + qr + 8];

    // Q A-fragments: loaded once
    unsigned qf[8][4];
    {
        const unsigned* qg = g_Qp + (size_t)h * 64 * NN + m0 + rowb;
#pragma unroll
        for (int ks = 0; ks < 8; ks++) {
            qf[ks][0] = qg[(size_t)(ks * 8 + qp) * NN + qr];
            qf[ks][1] = qg[(size_t)(ks * 8 + qp) * NN + qr + 8];
            qf[ks][2] = qg[(size_t)(ks * 8 + 4 + qp) * NN + qr];
            qf[ks][3] = qg[(size_t)(ks * 8 + 4 + qp) * NN + qr + 8];
        }
    }

    // zero V pad cols 129..135 for both buffers
    for (int i = tid; i < 2 * 32 * 7; i += ATHR) {
        int b = i / (32 * 7), r = i % (32 * 7);
        smu[(b ? OFF_V1 : OFF_V0) + (r / 7) * VSTR + 129 + (r % 7)] = 0u;
    }

    auto loadK = [&](int j) {
        unsigned* Kd = smu + ((j & 1) ? OFF_K1 : OFF_K0);
        const unsigned* kn = ksrc + j * 64;
        for (int idx = tid; idx < 64 * 16; idx += ATHR) {
            int dp = idx >> 4, c = idx & 15;
            cpa16(Kd + dp * KSTR + c * 4, kn + (size_t)dp * NN + c * 4);
        }
        if (tid < 16) cpa16(smu + ((j & 1) ? OFF_TK1 : OFF_TK0) + tid * 4,
                            tkg + j * 64 + tid * 4);
    };
    auto loadV = [&](int j) {
        unsigned* Vd = smu + ((j & 1) ? OFF_V1 : OFF_V0);
        const unsigned* vsrc = vsrcb + (size_t)(j * 32) * ND;
        for (int idx = tid; idx < 1024; idx += ATHR) {
            int np = idx >> 5, c = idx & 31;
            cpa16(Vd + np * VSTR + c * 4, vsrc + (size_t)np * ND + c * 4);
        }
        if (tid < 32) cpa4(Vd + tid * VSTR + 128, vtb + j * 32 + tid);
    };

    // prologue
    loadK(0); cpa_commit();
    loadK(1); loadV(0); cpa_commit();
    cpa_wait<1>();
    __syncthreads();

    // score(0)
    float sc[8][4];
#pragma unroll
    for (int nt = 0; nt < 8; nt++)
#pragma unroll
        for (int r = 0; r < 4; r++) sc[nt][r] = 0.0f;
    {
        const unsigned* Kc = smu + OFF_K0;
#pragma unroll
        for (int ks = 0; ks < 8; ks++) {
            const unsigned* kb = Kc + (ks * 8 + qp) * KSTR + qr;
#pragma unroll
            for (int nt = 0; nt < 8; nt++)
                mma16(sc[nt], qf[ks][0], qf[ks][1], qf[ks][2], qf[ks][3],
                      kb[nt * 8], kb[4 * KSTR + nt * 8]);
        }
    }

    float oc[16][4], ot[4];
    float lac0 = 0.0f, lac1 = 0.0f;
#pragma unroll
    for (int j = 0; j < 16; j++)
#pragma unroll
        for (int r = 0; r < 4; r++) oc[j][r] = 0.0f;
#pragma unroll
    for (int r = 0; r < 4; r++) ot[r] = 0.0f;

    for (int c = 0; c < 64; c++) {
        const float* tkc = (const float*)(smu + ((c & 1) ? OFF_TK1 : OFF_TK0));

        // ---- exp(c) ----
        unsigned pa[4][4];
#pragma unroll
        for (int nt = 0; nt < 8; nt++) {
            int col = nt * 8 + qp * 2;
            float t0 = tkc[col], t1 = tkc[col + 1];
            float p0 = exp2f(sc[nt][0] - tqr0 * t0);
            float p1 = exp2f(sc[nt][1] - tqr0 * t1);
            float p2 = exp2f(sc[nt][2] - tqr1 * t0);
            float p3 = exp2f(sc[nt][3] - tqr1 * t1);
            unsigned pkA = pkbf2(p0, p1);
            unsigned pkB = pkbf2(p2, p3);
            lac0 += __uint_as_float(pkA << 16) + __uint_as_float(pkA & 0xffff0000u);
            lac1 += __uint_as_float(pkB << 16) + __uint_as_float(pkB & 0xffff0000u);
            pa[nt >> 1][(nt & 1) * 2]     = pkA;
            pa[nt >> 1][(nt & 1) * 2 + 1] = pkB;
        }

        __syncthreads();

        if (c + 2 < 64) loadK(c + 2);
        if (c + 1 < 64) loadV(c + 1);
        cpa_commit();
        cpa_wait<1>();

        // ---- merged tensor block: PV(c) + score(c+1) ----
        const unsigned* Vc = smu + ((c & 1) ? OFF_V1 : OFF_V0);
#pragma unroll
        for (int ks = 0; ks < 4; ks++) {
            const unsigned* vb = Vc + (ks * 8 + qp) * VSTR + qr;
#pragma unroll
            for (int j = 0; j < 16; j++)
                mma16(oc[j], pa[ks][0], pa[ks][1], pa[ks][2], pa[ks][3],
                      vb[j * 8], vb[4 * VSTR + j * 8]);
            mma16(ot, pa[ks][0], pa[ks][1], pa[ks][2], pa[ks][3],
                  vb[128], vb[4 * VSTR + 128]);
        }
        if (c < 63) {
            const unsigned* Kn = smu + (((c + 1) & 1) ? OFF_K1 : OFF_K0);
#pragma unroll
            for (int nt = 0; nt < 8; nt++)
#pragma unroll
                for (int r = 0; r < 4; r++) sc[nt][r] = 0.0f;
#pragma unroll
            for (int ks = 0; ks < 8; ks++) {
                const unsigned* kb = Kn + (ks * 8 + qp) * KSTR + qr;
#pragma unroll
                for (int nt = 0; nt < 8; nt++)
                    mma16(sc[nt], qf[ks][0], qf[ks][1], qf[ks][2], qf[ks][3],
                          kb[nt * 8], kb[4 * KSTR + nt * 8]);
            }
        }
    }

    // ---- epilogue ----
    lac0 += __shfl_xor_sync(0xffffffffu, lac0, 1);
    lac0 += __shfl_xor_sync(0xffffffffu, lac0, 2);
    lac1 += __shfl_xor_sync(0xffffffffu, lac1, 1);
    lac1 += __shfl_xor_sync(0xffffffffu, lac1, 2);
    float rl0 = 1.0f / lac0, rl1 = 1.0f / lac1;

    float tt0 = __shfl_sync(0xffffffffu, ot[0], lane & ~3) * rl0;
    float tt1 = __shfl_sync(0xffffffffu, ot[2], lane & ~3) * rl1;

    float av0[16][2], av1[16][2];
    float s0 = 0.0f, s1 = 0.0f;
#pragma unroll
    for (int j = 0; j < 16; j++) {
        av0[j][0] = oc[j][0] * rl0; av0[j][1] = oc[j][1] * rl0;
        av1[j][0] = oc[j][2] * rl1; av1[j][1] = oc[j][3] * rl1;
        s0 = fmaf(av0[j][0], av0[j][0], fmaf(av0[j][1], av0[j][1], s0));
        s1 = fmaf(av1[j][0], av1[j][0], fmaf(av1[j][1], av1[j][1], s1));
    }
    s0 += __shfl_xor_sync(0xffffffffu, s0, 1);
    s0 += __shfl_xor_sync(0xffffffffu, s0, 2);
    s1 += __shfl_xor_sync(0xffffffffu, s1, 1);
    s1 += __shfl_xor_sync(0xffffffffu, s1, 2);

    float f0 = rsqrtf(fmaxf(fabsf(s0 - tt0 * tt0), 1e-8f));
    float f1 = rsqrtf(fmaxf(fabsf(s1 - tt1 * tt1), 1e-8f));

    int row0 = m0 + rowb + qr, row1 = row0 + 8;
    float* o0 = g_OS + ((size_t)(h * NN + row0)) * ND;
    float* o1 = g_OS + ((size_t)(h * NN + row1)) * ND;
#pragma unroll
    for (int j = 0; j < 16; j++) {
        int d0 = j * 8 + qp * 2;
        *(float2*)&o0[d0] = make_float2(av0[j][0] * f0, av0[j][1] * f0);
        *(float2*)&o1[d0] = make_float2(av1[j][0] * f1, av1[j][1] * f1);
    }
    if (qp == 0) {
        g_OT[h * NN + row0] = tt0 * f0;
        g_OT[h * NN + row1] = tt1 * f1;
    }
}

// =====================================================================
// Kernel 3: head mean + final midpoint_norm (unchanged)
// =====================================================================
__global__ __launch_bounds__(256) void final_kernel(float* __restrict__ out)
{
    const int warp = threadIdx.x >> 5, lane = threadIdx.x & 31;
    const int n = blockIdx.x * 8 + warp;

    float as0 = 0.f, as1 = 0.f, as2 = 0.f, as3 = 0.f, at = 0.f;
#pragma unroll
    for (int h = 0; h < NH; h++) {
        float4 v = *(const float4*)&g_OS[((size_t)(h * NN + n)) * ND + lane * 4];
        as0 += v.x; as1 += v.y; as2 += v.z; as3 += v.w;
        at += g_OT[h * NN + n];
    }
    const float inv = 1.0f / (float)NH;
    as0 *= inv; as1 *= inv; as2 *= inv; as3 *= inv; at *= inv;

    float q = as0 * as0 + as1 * as1 + as2 * as2 + as3 * as3;
#pragma unroll
    for (int off = 16; off; off >>= 1)
        q += __shfl_xor_sync(0xffffffffu, q, off);

    float inner = q - at * at;
    float f = 1.0f / sqrtf(fmaxf(fabsf(inner), 1e-8f));

    float* o = out + (size_t)n * 129;
    if (lane == 0) o[0] = at * f;
    o[1 + lane * 4 + 0] = as0 * f;
    o[1 + lane * 4 + 1] = as1 * f;
    o[1 + lane * 4 + 2] = as2 * f;
    o[1 + lane * 4 + 3] = as3 * f;
}

// =====================================================================
extern "C" void kernel_launch(void* const* d_in, const int* in_sizes, int n_in,
                              void* d_out, int out_size)
{
    const float* x     = (const float*)d_in[0];
    const float* Wq    = (const float*)d_in[1];
    const float* bq    = (const float*)d_in[2];
    const float* Wk    = (const float*)d_in[3];
    const float* bk    = (const float*)d_in[4];
    const float* Wv    = (const float*)d_in[5];
    const float* bv    = (const float*)d_in[6];
    const float* scale = (const float*)d_in[7];
    float* out = (float*)d_out;

    cudaFuncSetAttribute(proj_kernel,
                         cudaFuncAttributeMaxDynamicSharedMemorySize, PROJ_SMEM_BYTES);
    cudaFuncSetAttribute(attn_kernel,
                         cudaFuncAttributeMaxDynamicSharedMemorySize, ATTN_SMEM_BYTES);

    proj_kernel<<<dim3(NN / 128, NH * 3), 256, PROJ_SMEM_BYTES>>>(
        x, Wq, bq, Wk, bk, Wv, bv, scale);
    attn_kernel<<<dim3(NN / 64, NH), ATHR, ATTN_SMEM_BYTES>>>();
    final_kernel<<<NN / 8, 256>>>(out);
}

// round 16
// speedup vs baseline: 8.2272x; 1.0115x over previous
#include <cuda_runtime.h>
#include <math.h>

#define NH 12
#define NN 4096
#define ND 128
#define NIN 256

// ---- tf32 (proj) ----
__device__ __forceinline__ void mma8(float* c, unsigned a0, unsigned a1,
    unsigned a2, unsigned a3, unsigned b0, unsigned b1) {
    asm volatile("mma.sync.aligned.m16n8k8.row.col.f32.tf32.tf32.f32 "
        "{%0,%1,%2,%3}, {%4,%5,%6,%7}, {%8,%9}, {%0,%1,%2,%3};"
        : "+f"(c[0]), "+f"(c[1]), "+f"(c[2]), "+f"(c[3])
        : "r"(a0), "r"(a1), "r"(a2), "r"(a3), "r"(b0), "r"(b1));
}
// ---- bf16 (attn) ----
__device__ __forceinline__ void mma16(float* c, unsigned a0, unsigned a1,
    unsigned a2, unsigned a3, unsigned b0, unsigned b1) {
    asm volatile("mma.sync.aligned.m16n8k16.row.col.f32.bf16.bf16.f32 "
        "{%0,%1,%2,%3}, {%4,%5,%6,%7}, {%8,%9}, {%0,%1,%2,%3};"
        : "+f"(c[0]), "+f"(c[1]), "+f"(c[2]), "+f"(c[3])
        : "r"(a0), "r"(a1), "r"(a2), "r"(a3), "r"(b0), "r"(b1));
}
__device__ __forceinline__ unsigned pkbf2(float lo, float hi) {
    unsigned r;
    asm("{.reg .b16 l, h;\n\tcvt.rn.bf16.f32 l, %1;\n\tcvt.rn.bf16.f32 h, %2;\n\t"
        "mov.b32 %0, {l, h};}" : "=r"(r) : "f"(lo), "f"(hi));
    return r;
}
// ---- cp.async ----
__device__ __forceinline__ void cpa16(void* dst, const void* src) {
    unsigned d = (unsigned)__cvta_generic_to_shared(dst);
    asm volatile("cp.async.cg.shared.global [%0], [%1], 16;" :: "r"(d), "l"(src));
}
__device__ __forceinline__ void cpa4(void* dst, const void* src) {
    unsigned d = (unsigned)__cvta_generic_to_shared(dst);
    asm volatile("cp.async.ca.shared.global [%0], [%1], 4;" :: "r"(d), "l"(src));
}
__device__ __forceinline__ void cpa_commit() {
    asm volatile("cp.async.commit_group;" ::: "memory");
}
template<int N> __device__ __forceinline__ void cpa_wait() {
    asm volatile("cp.async.wait_group %0;" :: "n"(N) : "memory");
}

#define LOG2E 1.4426950408889634f

// ---------------- scratch ----------------
__device__ unsigned g_Qp[NH * 64 * NN];     // bf16x2 d-pair-packed, d-major (alpha*log2e*s_q)
__device__ unsigned g_Kp[NH * 64 * NN];     // s_k
__device__ unsigned g_Vp[NH * (NN / 2) * ND];  // key-pair-packed v_s
__device__ unsigned g_VTp[NH * (NN / 2)];      // packed (v_t[2i], v_t[2i+1])
__device__ float g_tq[NH * NN];             // alpha*log2e * t_q
__device__ float g_tk[NH * NN];             // t_k
__device__ float g_OS[NH * NN * ND];        // per-head NORMALIZED midpoint (s)
__device__ float g_OT[NH * NN];             // per-head NORMALIZED midpoint (t)

// =====================================================================
// Kernel 1: projections via tf32 mma (now 2 CTAs/SM via launch bounds)
// =====================================================================
#define PSTRX 36
#define PROJ_TILE (128 * PSTRX)
#define PROJ_SMEM_BYTES (4 * PROJ_TILE * 4)

__global__ __launch_bounds__(256, 2) void proj_kernel(
    const float* __restrict__ x,
    const float* __restrict__ Wq, const float* __restrict__ bq,
    const float* __restrict__ Wk, const float* __restrict__ bk,
    const float* __restrict__ Wv, const float* __restrict__ bv,
    const float* __restrict__ scale_ptr)
{
    extern __shared__ float psm[];
    __shared__ float Sred[128][2];

    const int by = blockIdx.y, h = by % NH, sel = by / NH;
    const float* W = (sel == 0) ? Wq : (sel == 1) ? Wk : Wv;
    const float* B = (sel == 0) ? bq : (sel == 1) ? bk : bv;
    const float* Wh = W + (size_t)h * ND * NIN;
    const int n0 = blockIdx.x * 128;
    const int tid = threadIdx.x, lane = tid & 31, wid = tid >> 5;
    const int qp = lane & 3, qr = lane >> 2, mg = wid & 3, ngg = wid >> 2;

    auto load_chunk = [&](int kb, int buf) {
        float* Xs = psm + buf * (2 * PROJ_TILE);
        float* Ws = Xs + PROJ_TILE;
        for (int idx = tid; idx < 128 * 32; idx += 256) {
            int m = idx >> 5, k = idx & 31;
            cpa4(Xs + m * PSTRX + k, x + (size_t)(n0 + m) * 257 + 1 + kb + k);
        }
        for (int idx = tid; idx < 128 * 8; idx += 256) {
            int o = idx >> 3, kq = idx & 7;
            cpa16(Ws + o * PSTRX + kq * 4, Wh + (size_t)o * NIN + kb + kq * 4);
        }
    };

    float cacc[2][8][4];
#pragma unroll
    for (int mt = 0; mt < 2; mt++)
#pragma unroll
        for (int nt = 0; nt < 8; nt++)
#pragma unroll
            for (int r = 0; r < 4; r++) cacc[mt][nt][r] = 0.0f;

    load_chunk(0, 0);
    cpa_commit();
    for (int c = 0; c < 8; c++) {
        if (c < 7) { load_chunk((c + 1) * 32, (c + 1) & 1); cpa_commit(); cpa_wait<1>(); }
        else cpa_wait<0>();
        __syncthreads();
        const float* Xc = psm + (c & 1) * (2 * PROJ_TILE);
        const float* Wc = Xc + PROJ_TILE;
#pragma unroll
        for (int ks = 0; ks < 4; ks++) {
            unsigned a[2][4];
            const float* qa = Xc + (mg * 32 + qr) * PSTRX + ks * 8 + qp;
#pragma unroll
            for (int mt = 0; mt < 2; mt++) {
                const float* q2 = qa + mt * 16 * PSTRX;
                a[mt][0] = __float_as_uint(q2[0]);
                a[mt][1] = __float_as_uint(q2[8 * PSTRX]);
                a[mt][2] = __float_as_uint(q2[4]);
                a[mt][3] = __float_as_uint(q2[8 * PSTRX + 4]);
            }
#pragma unroll
            for (int nt = 0; nt < 8; nt++) {
                const float* kb2 = Wc + (ngg * 64 + nt * 8 + qr) * PSTRX + ks * 8 + qp;
                unsigned b0 = __float_as_uint(kb2[0]);
                unsigned b1 = __float_as_uint(kb2[4]);
                mma8(cacc[0][nt], a[0][0], a[0][1], a[0][2], a[0][3], b0, b1);
                mma8(cacc[1][nt], a[1][0], a[1][1], a[1][2], a[1][3], b0, b1);
            }
        }
        __syncthreads();
    }

    float bb[8][2];
#pragma unroll
    for (int nt = 0; nt < 8; nt++) {
        int col = ngg * 64 + nt * 8 + qp * 2;
        bb[nt][0] = B[h * ND + col];
        bb[nt][1] = B[h * ND + col + 1];
    }
    float ssq[2][2] = {{0.f, 0.f}, {0.f, 0.f}};
#pragma unroll
    for (int mt = 0; mt < 2; mt++)
#pragma unroll
        for (int nt = 0; nt < 8; nt++)
#pragma unroll
            for (int rr = 0; rr < 2; rr++) {
                cacc[mt][nt][rr * 2] += bb[nt][0];
                cacc[mt][nt][rr * 2 + 1] += bb[nt][1];
                ssq[mt][rr] = fmaf(cacc[mt][nt][rr * 2], cacc[mt][nt][rr * 2], ssq[mt][rr]);
                ssq[mt][rr] = fmaf(cacc[mt][nt][rr * 2 + 1], cacc[mt][nt][rr * 2 + 1], ssq[mt][rr]);
            }
#pragma unroll
    for (int mt = 0; mt < 2; mt++)
#pragma unroll
        for (int rr = 0; rr < 2; rr++) {
            ssq[mt][rr] += __shfl_xor_sync(0xffffffffu, ssq[mt][rr], 1);
            ssq[mt][rr] += __shfl_xor_sync(0xffffffffu, ssq[mt][rr], 2);
        }
    if (qp == 0) {
#pragma unroll
        for (int mt = 0; mt < 2; mt++)
#pragma unroll
            for (int rr = 0; rr < 2; rr++)
                Sred[mg * 32 + mt * 16 + rr * 8 + qr][ngg] = ssq[mt][rr];
    }
    __syncthreads();

    const float alpha = 2.0f / scale_ptr[0];

    if (sel < 2) {
        const float smul = (sel == 0) ? alpha * LOG2E : 1.0f;
        unsigned* T = ((sel == 0) ? g_Qp : g_Kp) + (size_t)h * 64 * NN;
#pragma unroll
        for (int mt = 0; mt < 2; mt++)
#pragma unroll
            for (int rr = 0; rr < 2; rr++) {
                int n = n0 + mg * 32 + mt * 16 + rr * 8 + qr;
#pragma unroll
                for (int nt = 0; nt < 8; nt++) {
                    int dp = ngg * 32 + nt * 4 + qp;
                    T[(size_t)dp * NN + n] =
                        pkbf2(smul * cacc[mt][nt][rr * 2], smul * cacc[mt][nt][rr * 2 + 1]);
                }
                if (qp == 0 && ngg == 0) {
                    int row = mg * 32 + mt * 16 + rr * 8 + qr;
                    float t = sqrtf(Sred[row][0] + Sred[row][1] + 1.0f);
                    if (sel == 0) g_tq[h * NN + n] = alpha * LOG2E * t;
                    else          g_tk[h * NN + n] = t;
                }
            }
    } else {
#pragma unroll
        for (int mt = 0; mt < 2; mt++)
#pragma unroll
            for (int rr = 0; rr < 2; rr++) {
                int n = n0 + mg * 32 + mt * 16 + rr * 8 + qr;
                int row = mg * 32 + mt * 16 + rr * 8 + qr;
                float t = sqrtf(Sred[row][0] + Sred[row][1] + 1.0f);
                float tp = __shfl_down_sync(0xffffffffu, t, 4);
                unsigned* vdst = g_Vp + ((size_t)h * 2048 + (n >> 1)) * ND;
#pragma unroll
                for (int nt = 0; nt < 8; nt++) {
                    int col = ngg * 64 + nt * 8 + qp * 2;
                    float v0 = cacc[mt][nt][rr * 2];
                    float v1 = cacc[mt][nt][rr * 2 + 1];
                    float v0p = __shfl_down_sync(0xffffffffu, v0, 4);
                    float v1p = __shfl_down_sync(0xffffffffu, v1, 4);
                    if ((qr & 1) == 0) {
                        vdst[col]     = pkbf2(v0, v0p);
                        vdst[col + 1] = pkbf2(v1, v1p);
                    }
                }
                if (qp == 0 && ngg == 0 && (qr & 1) == 0)
                    g_VTp[h * 2048 + (n >> 1)] = pkbf2(t, tp);
            }
    }
}

// =====================================================================
// Kernel 2: flash attention. 128 threads / 64-row CTA; forced 3 CTAs/SM.
// Inner loop identical to R15 (P in registers, 1 barrier/chunk).
// =====================================================================
#define KSTR 72
#define VSTR 136

#define OFF_K0   0
#define OFF_K1   4608
#define OFF_V0   9216
#define OFF_V1   13568
#define OFF_TK0  17920
#define OFF_TK1  17984
#define ATTN_SMEM_WORDS 18048
#define ATTN_SMEM_BYTES (ATTN_SMEM_WORDS * 4)

#define ATHR 128

__global__ __launch_bounds__(ATHR, 3) void attn_kernel()
{
    extern __shared__ unsigned smu[];

    const int h = blockIdx.y, m0 = blockIdx.x * 64;
    const int tid = threadIdx.x, lane = tid & 31, wid = tid >> 5;
    const int qp = lane & 3, qr = lane >> 2;
    const int rowb = wid * 16;

    const unsigned* ksrc = g_Kp + (size_t)h * 64 * NN;
    const unsigned* vsrcb = g_Vp + (size_t)h * 2048 * ND;
    const unsigned* vtb = g_VTp + h * 2048;
    const float* tkg = g_tk + h * NN;

    const float tqr0 = g_tq[h * NN + m0 + rowb + qr];
    const float tqr1 = g_tq[h * NN + m0 + rowb + qr + 8];

    // Q A-fragments: loaded once
    unsigned qf[8][4];
    {
        const unsigned* qg = g_Qp + (size_t)h * 64 * NN + m0 + rowb;
#pragma unroll
        for (int ks = 0; ks < 8; ks++) {
            qf[ks][0] = qg[(size_t)(ks * 8 + qp) * NN + qr];
            qf[ks][1] = qg[(size_t)(ks * 8 + qp) * NN + qr + 8];
            qf[ks][2] = qg[(size_t)(ks * 8 + 4 + qp) * NN + qr];
            qf[ks][3] = qg[(size_t)(ks * 8 + 4 + qp) * NN + qr + 8];
        }
    }

    // zero V pad cols 129..135 for both buffers
    for (int i = tid; i < 2 * 32 * 7; i += ATHR) {
        int b = i / (32 * 7), r = i % (32 * 7);
        smu[(b ? OFF_V1 : OFF_V0) + (r / 7) * VSTR + 129 + (r % 7)] = 0u;
    }

    auto loadK = [&](int j) {
        unsigned* Kd = smu + ((j & 1) ? OFF_K1 : OFF_K0);
        const unsigned* kn = ksrc + j * 64;
        for (int idx = tid; idx < 64 * 16; idx += ATHR) {
            int dp = idx >> 4, c = idx & 15;
            cpa16(Kd + dp * KSTR + c * 4, kn + (size_t)dp * NN + c * 4);
        }
        if (tid < 16) cpa16(smu + ((j & 1) ? OFF_TK1 : OFF_TK0) + tid * 4,
                            tkg + j * 64 + tid * 4);
    };
    auto loadV = [&](int j) {
        unsigned* Vd = smu + ((j & 1) ? OFF_V1 : OFF_V0);
        const unsigned* vsrc = vsrcb + (size_t)(j * 32) * ND;
        for (int idx = tid; idx < 1024; idx += ATHR) {
            int np = idx >> 5, c = idx & 31;
            cpa16(Vd + np * VSTR + c * 4, vsrc + (size_t)np * ND + c * 4);
        }
        if (tid < 32) cpa4(Vd + tid * VSTR + 128, vtb + j * 32 + tid);
    };

    // prologue
    loadK(0); cpa_commit();
    loadK(1); loadV(0); cpa_commit();
    cpa_wait<1>();
    __syncthreads();

    // score(0)
    float sc[8][4];
#pragma unroll
    for (int nt = 0; nt < 8; nt++)
#pragma unroll
        for (int r = 0; r < 4; r++) sc[nt][r] = 0.0f;
    {
        const unsigned* Kc = smu + OFF_K0;
#pragma unroll
        for (int ks = 0; ks < 8; ks++) {
            const unsigned* kb = Kc + (ks * 8 + qp) * KSTR + qr;
#pragma unroll
            for (int nt = 0; nt < 8; nt++)
                mma16(sc[nt], qf[ks][0], qf[ks][1], qf[ks][2], qf[ks][3],
                      kb[nt * 8], kb[4 * KSTR + nt * 8]);
        }
    }

    float oc[16][4], ot[4];
    float lac0 = 0.0f, lac1 = 0.0f;
#pragma unroll
    for (int j = 0; j < 16; j++)
#pragma unroll
        for (int r = 0; r < 4; r++) oc[j][r] = 0.0f;
#pragma unroll
    for (int r = 0; r < 4; r++) ot[r] = 0.0f;

    for (int c = 0; c < 64; c++) {
        const float* tkc = (const float*)(smu + ((c & 1) ? OFF_TK1 : OFF_TK0));

        // ---- exp(c) ----
        unsigned pa[4][4];
#pragma unroll
        for (int nt = 0; nt < 8; nt++) {
            int col = nt * 8 + qp * 2;
            float t0 = tkc[col], t1 = tkc[col + 1];
            float p0 = exp2f(sc[nt][0] - tqr0 * t0);
            float p1 = exp2f(sc[nt][1] - tqr0 * t1);
            float p2 = exp2f(sc[nt][2] - tqr1 * t0);
            float p3 = exp2f(sc[nt][3] - tqr1 * t1);
            unsigned pkA = pkbf2(p0, p1);
            unsigned pkB = pkbf2(p2, p3);
            lac0 += __uint_as_float(pkA << 16) + __uint_as_float(pkA & 0xffff0000u);
            lac1 += __uint_as_float(pkB << 16) + __uint_as_float(pkB & 0xffff0000u);
            pa[nt >> 1][(nt & 1) * 2]     = pkA;
            pa[nt >> 1][(nt & 1) * 2 + 1] = pkB;
        }

        __syncthreads();

        if (c + 2 < 64) loadK(c + 2);
        if (c + 1 < 64) loadV(c + 1);
        cpa_commit();
        cpa_wait<1>();

        // ---- merged tensor block: PV(c) + score(c+1) ----
        const unsigned* Vc = smu + ((c & 1) ? OFF_V1 : OFF_V0);
#pragma unroll
        for (int ks = 0; ks < 4; ks++) {
            const unsigned* vb = Vc + (ks * 8 + qp) * VSTR + qr;
#pragma unroll
            for (int j = 0; j < 16; j++)
                mma16(oc[j], pa[ks][0], pa[ks][1], pa[ks][2], pa[ks][3],
                      vb[j * 8], vb[4 * VSTR + j * 8]);
            mma16(ot, pa[ks][0], pa[ks][1], pa[ks][2], pa[ks][3],
                  vb[128], vb[4 * VSTR + 128]);
        }
        if (c < 63) {
            const unsigned* Kn = smu + (((c + 1) & 1) ? OFF_K1 : OFF_K0);
#pragma unroll
            for (int nt = 0; nt < 8; nt++)
#pragma unroll
                for (int r = 0; r < 4; r++) sc[nt][r] = 0.0f;
#pragma unroll
            for (int ks = 0; ks < 8; ks++) {
                const unsigned* kb = Kn + (ks * 8 + qp) * KSTR + qr;
#pragma unroll
                for (int nt = 0; nt < 8; nt++)
                    mma16(sc[nt], qf[ks][0], qf[ks][1], qf[ks][2], qf[ks][3],
                          kb[nt * 8], kb[4 * KSTR + nt * 8]);
            }
        }
    }

    // ---- epilogue ----
    lac0 += __shfl_xor_sync(0xffffffffu, lac0, 1);
    lac0 += __shfl_xor_sync(0xffffffffu, lac0, 2);
    lac1 += __shfl_xor_sync(0xffffffffu, lac1, 1);
    lac1 += __shfl_xor_sync(0xffffffffu, lac1, 2);
    float rl0 = 1.0f / lac0, rl1 = 1.0f / lac1;

    float tt0 = __shfl_sync(0xffffffffu, ot[0], lane & ~3) * rl0;
    float tt1 = __shfl_sync(0xffffffffu, ot[2], lane & ~3) * rl1;

    float av0[16][2], av1[16][2];
    float s0 = 0.0f, s1 = 0.0f;
#pragma unroll
    for (int j = 0; j < 16; j++) {
        av0[j][0] = oc[j][0] * rl0; av0[j][1] = oc[j][1] * rl0;
        av1[j][0] = oc[j][2] * rl1; av1[j][1] = oc[j][3] * rl1;
        s0 = fmaf(av0[j][0], av0[j][0], fmaf(av0[j][1], av0[j][1], s0));
        s1 = fmaf(av1[j][0], av1[j][0], fmaf(av1[j][1], av1[j][1], s1));
    }
    s0 += __shfl_xor_sync(0xffffffffu, s0, 1);
    s0 += __shfl_xor_sync(0xffffffffu, s0, 2);
    s1 += __shfl_xor_sync(0xffffffffu, s1, 1);
    s1 += __shfl_xor_sync(0xffffffffu, s1, 2);

    float f0 = rsqrtf(fmaxf(fabsf(s0 - tt0 * tt0), 1e-8f));
    float f1 = rsqrtf(fmaxf(fabsf(s1 - tt1 * tt1), 1e-8f));

    int row0 = m0 + rowb + qr, row1 = row0 + 8;
    float* o0 = g_OS + ((size_t)(h * NN + row0)) * ND;
    float* o1 = g_OS + ((size_t)(h * NN + row1)) * ND;
#pragma unroll
    for (int j = 0; j < 16; j++) {
        int d0 = j * 8 + qp * 2;
        *(float2*)&o0[d0] = make_float2(av0[j][0] * f0, av0[j][1] * f0);
        *(float2*)&o1[d0] = make_float2(av1[j][0] * f1, av1[j][1] * f1);
    }
    if (qp == 0) {
        g_OT[h * NN + row0] = tt0 * f0;
        g_OT[h * NN + row1] = tt1 * f1;
    }
}

// =====================================================================
// Kernel 3: head mean + final midpoint_norm (unchanged)
// =====================================================================
__global__ __launch_bounds__(256) void final_kernel(float* __restrict__ out)
{
    const int warp = threadIdx.x >> 5, lane = threadIdx.x & 31;
    const int n = blockIdx.x * 8 + warp;

    float as0 = 0.f, as1 = 0.f, as2 = 0.f, as3 = 0.f, at = 0.f;
#pragma unroll
    for (int h = 0; h < NH; h++) {
        float4 v = *(const float4*)&g_OS[((size_t)(h * NN + n)) * ND + lane * 4];
        as0 += v.x; as1 += v.y; as2 += v.z; as3 += v.w;
        at += g_OT[h * NN + n];
    }
    const float inv = 1.0f / (float)NH;
    as0 *= inv; as1 *= inv; as2 *= inv; as3 *= inv; at *= inv;

    float q = as0 * as0 + as1 * as1 + as2 * as2 + as3 * as3;
#pragma unroll
    for (int off = 16; off; off >>= 1)
        q += __shfl_xor_sync(0xffffffffu, q, off);

    float inner = q - at * at;
    float f = 1.0f / sqrtf(fmaxf(fabsf(inner), 1e-8f));

    float* o = out + (size_t)n * 129;
    if (lane == 0) o[0] = at * f;
    o[1 + lane * 4 + 0] = as0 * f;
    o[1 + lane * 4 + 1] = as1 * f;
    o[1 + lane * 4 + 2] = as2 * f;
    o[1 + lane * 4 + 3] = as3 * f;
}

// =====================================================================
extern "C" void kernel_launch(void* const* d_in, const int* in_sizes, int n_in,
                              void* d_out, int out_size)
{
    const float* x     = (const float*)d_in[0];
    const float* Wq    = (const float*)d_in[1];
    const float* bq    = (const float*)d_in[2];
    const float* Wk    = (const float*)d_in[3];
    const float* bk    = (const float*)d_in[4];
    const float* Wv    = (const float*)d_in[5];
    const float* bv    = (const float*)d_in[6];
    const float* scale = (const float*)d_in[7];
    float* out = (float*)d_out;

    cudaFuncSetAttribute(proj_kernel,
                         cudaFuncAttributeMaxDynamicSharedMemorySize, PROJ_SMEM_BYTES);
    cudaFuncSetAttribute(attn_kernel,
                         cudaFuncAttributeMaxDynamicSharedMemorySize, ATTN_SMEM_BYTES);

    proj_kernel<<<dim3(NN / 128, NH * 3), 256, PROJ_SMEM_BYTES>>>(
        x, Wq, bq, Wk, bk, Wv, bv, scale);
    attn_kernel<<<dim3(NN / 64, NH), ATHR, ATTN_SMEM_BYTES>>>();
    final_kernel<<<NN / 8, 256>>>(out);
}